// round 6
// baseline (speedup 1.0000x reference)
#include <cuda_runtime.h>
#include <cuda_bf16.h>
#include <stdint.h>

#define CE     768
#define NHEAD  8
#define HD     96
#define BATCH  8
#define SEQ    1024
#define MROWS  (BATCH*SEQ)
#define KDIM   768
#define NQKV   (3*CE)
#define NC     (KDIM/32)          // 24 chunks of K=32

// ------------------------------- scratch (allocation-free rule) -------------
__device__ __align__(16) __nv_bfloat16 g_xh[MROWS*KDIM];
__device__ __align__(16) __nv_bfloat16 g_xl[MROWS*KDIM];
__device__ __align__(16) __nv_bfloat16 g_wah[NQKV*KDIM];
__device__ __align__(16) __nv_bfloat16 g_wal[NQKV*KDIM];
__device__ __align__(16) __nv_bfloat16 g_wph[CE*KDIM];
__device__ __align__(16) __nv_bfloat16 g_wpl[CE*KDIM];
__device__ __align__(16) __nv_bfloat16 g_ah[MROWS*KDIM];
__device__ __align__(16) __nv_bfloat16 g_al[MROWS*KDIM];
__device__ __align__(16) __nv_bfloat16 g_qh[BATCH*NHEAD*SEQ*HD];
__device__ __align__(16) __nv_bfloat16 g_ql[BATCH*NHEAD*SEQ*HD];
__device__ __align__(16) __nv_bfloat16 g_kh[BATCH*NHEAD*SEQ*HD];
__device__ __align__(16) __nv_bfloat16 g_kl[BATCH*NHEAD*SEQ*HD];
__device__ __align__(16) __nv_bfloat16 g_vh[BATCH*NHEAD*SEQ*HD];
__device__ __align__(16) __nv_bfloat16 g_vl[BATCH*NHEAD*SEQ*HD];

// ------------------------------- helpers ------------------------------------
__device__ __forceinline__ uint32_t smem_u32(const void* p) {
    uint32_t a;
    asm("{ .reg .u64 t; cvta.to.shared.u64 t, %1; cvt.u32.u64 %0, t; }" : "=r"(a) : "l"(p));
    return a;
}
__device__ __forceinline__ void ldmx4(uint32_t* r, uint32_t addr) {
    asm volatile("ldmatrix.sync.aligned.m8n8.x4.shared.b16 {%0,%1,%2,%3}, [%4];"
                 : "=r"(r[0]), "=r"(r[1]), "=r"(r[2]), "=r"(r[3]) : "r"(addr));
}
__device__ __forceinline__ void ldmx4t(uint32_t* r, uint32_t addr) {
    asm volatile("ldmatrix.sync.aligned.m8n8.x4.trans.shared.b16 {%0,%1,%2,%3}, [%4];"
                 : "=r"(r[0]), "=r"(r[1]), "=r"(r[2]), "=r"(r[3]) : "r"(addr));
}
__device__ __forceinline__ void mma16816(float* c, const uint32_t* a, const uint32_t* b) {
    asm volatile(
        "mma.sync.aligned.m16n8k16.row.col.f32.bf16.bf16.f32 "
        "{%0,%1,%2,%3}, {%4,%5,%6,%7}, {%8,%9}, {%0,%1,%2,%3};"
        : "+f"(c[0]), "+f"(c[1]), "+f"(c[2]), "+f"(c[3])
        : "r"(a[0]), "r"(a[1]), "r"(a[2]), "r"(a[3]), "r"(b[0]), "r"(b[1]));
}
__device__ __forceinline__ void cp16(uint32_t saddr, const void* gptr) {
    asm volatile("cp.async.ca.shared.global [%0], [%1], 16;"
                 :: "r"(saddr), "l"(__cvta_generic_to_global(gptr)) : "memory");
}
#define CP_COMMIT() asm volatile("cp.async.commit_group;" ::: "memory")
#define CP_WAIT1()  asm volatile("cp.async.wait_group 1;" ::: "memory")

__device__ __forceinline__ void split2(float x, float y, uint32_t& hi, uint32_t& lo) {
    __nv_bfloat162 h, l;
    h.x = __float2bfloat16(x);  h.y = __float2bfloat16(y);
    l.x = __float2bfloat16(x - __bfloat162float(h.x));
    l.y = __float2bfloat16(y - __bfloat162float(h.y));
    hi = *(uint32_t*)&h;  lo = *(uint32_t*)&l;
}

// ------------------------------- conversion kernels -------------------------
__global__ void split_kernel(const float* __restrict__ in,
                             __nv_bfloat16* __restrict__ hi,
                             __nv_bfloat16* __restrict__ lo, int n)
{
    int i = (blockIdx.x * 256 + threadIdx.x) * 4;
    if (i >= n) return;
    float4 v = *(const float4*)(in + i);
    uint32_t h0, l0, h1, l1;
    split2(v.x, v.y, h0, l0);
    split2(v.z, v.w, h1, l1);
    *(uint32_t*)(hi + i)     = h0;  *(uint32_t*)(hi + i + 2) = h1;
    *(uint32_t*)(lo + i)     = l0;  *(uint32_t*)(lo + i + 2) = l1;
}

// in: [K,N] row-major -> out hi/lo: [N,K] row-major (transposed) + split
__global__ void tsplit_kernel(const float* __restrict__ in,
                              __nv_bfloat16* __restrict__ hi,
                              __nv_bfloat16* __restrict__ lo, int K, int N)
{
    __shared__ float t[32][33];
    const int n0 = blockIdx.x * 32, k0 = blockIdx.y * 32;
#pragma unroll
    for (int i = 0; i < 4; i++) {
        int k = k0 + threadIdx.y + i * 8;
        t[threadIdx.y + i * 8][threadIdx.x] = in[(size_t)k * N + n0 + threadIdx.x];
    }
    __syncthreads();
#pragma unroll
    for (int i = 0; i < 4; i++) {
        int n = n0 + threadIdx.y + i * 8;
        float v = t[threadIdx.x][threadIdx.y + i * 8];
        __nv_bfloat16 h = __float2bfloat16(v);
        size_t o = (size_t)n * K + k0 + threadIdx.x;
        hi[o] = h;
        lo[o] = __float2bfloat16(v - __bfloat162float(h));
    }
}

// ------------------------------- HMMA GEMM ----------------------------------
// C[M,N] = (Ah+Al)[M,768]*(Bh+Bl)[N,768]^T, 3-pass split-bf16, fp32 accum.
// Block 64x128, 128 threads (4 warps, 2Mx2N), K-chunk 32, double-buffered
// cp.async. Small CTA => 2 CTAs/SM, syncs of one CTA overlap the other's MMAs.
// Stage layout (24576B): Ah@0(4KB) Al@4096 Bh@8192(8KB) Bl@16384
// addr(r,ch16) = (r>>3)*512 + (r&7)*16 + ch*128
#define STG 24576

__global__ __launch_bounds__(128) void gemm_mma(
    const __nv_bfloat16* __restrict__ Ah, const __nv_bfloat16* __restrict__ Al,
    const __nv_bfloat16* __restrict__ Bh, const __nv_bfloat16* __restrict__ Bl,
    float* __restrict__ outp, int scatter)
{
    __shared__ __align__(128) uint8_t sm[2][STG];
    const int tid = threadIdx.x, lid = tid & 31, wid = tid >> 5;
    const int wm = wid & 1, wn = wid >> 1;
    const int mbase = blockIdx.y * 64, nbase = blockIdx.x * 128;
    const uint32_t sbase = smem_u32(sm);

    // loader: r = idx>>2 (row), ch = idx&3 (16B chunk within 64B row)
    const int lr = tid >> 2, lch = tid & 3;
    const uint32_t lso = ((lr >> 3) << 9) | ((lr & 7) << 4) | (lch << 7);

    const uint32_t aoff = ((lid & 7) << 4) | (((lid >> 3) & 1) << 9) | ((lid >> 4) << 7);
    const uint32_t boff = ((lid & 7) << 4) | (((lid >> 3) & 1) << 7) | ((lid >> 4) << 9);

    auto load_chunk = [&](int c, int stg) {
        const uint32_t sb = sbase + stg * STG;
        const int kt = c * 32;
#pragma unroll
        for (int i = 0; i < 2; i++) {           // A: 64 rows
            int idx = tid + i * 128;
            int r = idx >> 2, ch = idx & 3;
            uint32_t d = sb + ((r >> 3) << 9) + ((r & 7) << 4) + (ch << 7);
            size_t g = (size_t)(mbase + r) * KDIM + kt + ch * 8;
            cp16(d,        Ah + g);
            cp16(d + 4096, Al + g);
        }
#pragma unroll
        for (int i = 0; i < 4; i++) {           // B: 128 rows
            int idx = tid + i * 128;
            int r = idx >> 2, ch = idx & 3;
            uint32_t d = sb + 8192 + ((r >> 3) << 9) + ((r & 7) << 4) + (ch << 7);
            size_t g = (size_t)(nbase + r) * KDIM + kt + ch * 8;
            cp16(d,        Bh + g);
            cp16(d + 8192, Bl + g);
        }
        (void)lso;
    };

    float acc[2][8][4];
#pragma unroll
    for (int mt = 0; mt < 2; mt++)
#pragma unroll
        for (int nt = 0; nt < 8; nt++)
#pragma unroll
            for (int u = 0; u < 4; u++) acc[mt][nt][u] = 0.f;

    load_chunk(0, 0); CP_COMMIT();
    load_chunk(1, 1); CP_COMMIT();

    for (int c = 0; c < NC; c++) {
        CP_WAIT1();                 // chunk c resident in stage c&1
        __syncthreads();

        const uint32_t stg = sbase + (c & 1) * STG;
        const uint32_t aAh = stg + wm * 2048 + aoff;
        const uint32_t bBh = stg + 8192 + wn * 4096 + boff;

        // load ALL fragments for both k16 substeps, then free the stage
        uint32_t ah[2][2][4], al[2][2][4], bh[2][4][4], bl[2][4][4];
#pragma unroll
        for (int s = 0; s < 2; s++) {
#pragma unroll
            for (int mt = 0; mt < 2; mt++) {
                ldmx4(ah[s][mt], aAh + s * 256 + mt * 1024);
                ldmx4(al[s][mt], aAh + 4096 + s * 256 + mt * 1024);
            }
#pragma unroll
            for (int g = 0; g < 4; g++) {
                ldmx4(bh[s][g], bBh + s * 256 + g * 1024);
                ldmx4(bl[s][g], bBh + 8192 + s * 256 + g * 1024);
            }
        }
        __syncthreads();            // stage c&1 free for reuse

        if (c + 2 < NC) load_chunk(c + 2, c & 1);
        CP_COMMIT();                // always commit (stable group count)

#pragma unroll
        for (int s = 0; s < 2; s++)
#pragma unroll
            for (int mt = 0; mt < 2; mt++)
#pragma unroll
                for (int g = 0; g < 4; g++) {
                    mma16816(acc[mt][2*g],   ah[s][mt], &bh[s][g][0]);
                    mma16816(acc[mt][2*g+1], ah[s][mt], &bh[s][g][2]);
                    mma16816(acc[mt][2*g],   ah[s][mt], &bl[s][g][0]);
                    mma16816(acc[mt][2*g+1], ah[s][mt], &bl[s][g][2]);
                    mma16816(acc[mt][2*g],   al[s][mt], &bh[s][g][0]);
                    mma16816(acc[mt][2*g+1], al[s][mt], &bh[s][g][2]);
                }
    }

    const int rowb = mbase + wm * 32 + (lid >> 2);
    const int colb = nbase + wn * 64 + 2 * (lid & 3);
#pragma unroll
    for (int mt = 0; mt < 2; mt++)
#pragma unroll
        for (int nt = 0; nt < 8; nt++) {
            int col = colb + nt * 8;
#pragma unroll
            for (int h2 = 0; h2 < 2; h2++) {
                int row = rowb + mt * 16 + h2 * 8;
                float vx = acc[mt][nt][2*h2], vy = acc[mt][nt][2*h2+1];
                if (scatter) {
                    int which = col / CE, cc = col - which * CE;
                    int h = cc / HD, d = cc - h * HD;
                    int bb = row >> 10, tt = row & 1023;
                    size_t idx = (size_t)(((bb * NHEAD + h) * SEQ) + tt) * HD + d;
                    uint32_t hi, lo;
                    split2(vx, vy, hi, lo);
                    __nv_bfloat16 *dh, *dl;
                    if (which == 0)      { dh = g_qh; dl = g_ql; }
                    else if (which == 1) { dh = g_kh; dl = g_kl; }
                    else                 { dh = g_vh; dl = g_vl; }
                    *(uint32_t*)(dh + idx) = hi;
                    *(uint32_t*)(dl + idx) = lo;
                } else {
                    *(float2*)(outp + (size_t)row * CE + col) = make_float2(vx, vy);
                }
            }
        }
}

// ------------------------------- flash attention (HMMA) ---------------------
#define FBM    128
#define FBN    64
#define PITCHB 208
#define KVSTG  (4*FBN*PITCHB)
#define FSMEM  (2*FBM*PITCHB + 2*KVSTG)

__global__ __launch_bounds__(256, 1) void flash_mma()
{
    extern __shared__ uint8_t fs[];
    const int tid = threadIdx.x, lid = tid & 31, wid = tid >> 5;
    const int bh = blockIdx.y;
    const int qt = (int)gridDim.x - 1 - (int)blockIdx.x;
    const int q0 = qt * FBM;
    const uint32_t sQh = smem_u32(fs);
    const uint32_t sKV = sQh + 2 * FBM * PITCHB;
    const size_t gb = (size_t)bh * SEQ * HD;
    const float scale = 0.10206207261596575f;

    const int rkv = tid >> 2, qq = tid & 3;

    {
        uint32_t sb = sKV + rkv * PITCHB + qq * 48;
        size_t go = gb + (size_t)rkv * HD + qq * 24;
#pragma unroll
        for (int k = 0; k < 3; k++) {
            cp16(sb + k*16,                 g_kh + go + k*8);
            cp16(sb + FBN*PITCHB + k*16,    g_kl + go + k*8);
            cp16(sb + 2*FBN*PITCHB + k*16,  g_vh + go + k*8);
            cp16(sb + 3*FBN*PITCHB + k*16,  g_vl + go + k*8);
        }
    }
    CP_COMMIT();
    {
        int r = tid >> 1, hf = tid & 1;
        uint32_t sq = sQh + r * PITCHB + hf * 96;
        size_t gq = gb + (size_t)(q0 + r) * HD + hf * 48;
#pragma unroll
        for (int k = 0; k < 6; k++) {
            cp16(sq + k*16,              g_qh + gq + k*8);
            cp16(sq + FBM*PITCHB + k*16, g_ql + gq + k*8);
        }
    }
    CP_COMMIT();

    const uint32_t aoff = (lid & 7) * PITCHB + ((lid >> 3) & 1) * (8 * PITCHB) + (lid >> 4) * 16;
    const uint32_t boff = (lid & 7) * PITCHB + ((lid >> 3) & 1) * 16 + (lid >> 4) * (8 * PITCHB);

    uint32_t qfh[6][4], qfl[6][4];
    float oacc[12][4];
#pragma unroll
    for (int n = 0; n < 12; n++)
#pragma unroll
        for (int u = 0; u < 4; u++) oacc[n][u] = 0.f;
    float m0 = -1e30f, m1 = -1e30f, lsum0 = 0.f, lsum1 = 0.f;
    const int row0 = q0 + wid * 16 + (lid >> 2);

    const int nkt = 2 * qt + 2;
    for (int kt = 0; kt < nkt; kt++) {
        if (kt + 1 < nkt) {
            uint32_t sb = sKV + ((kt + 1) & 1) * KVSTG + rkv * PITCHB + qq * 48;
            size_t go = gb + (size_t)((kt + 1) * FBN + rkv) * HD + qq * 24;
#pragma unroll
            for (int k = 0; k < 3; k++) {
                cp16(sb + k*16,                g_kh + go + k*8);
                cp16(sb + FBN*PITCHB + k*16,   g_kl + go + k*8);
                cp16(sb + 2*FBN*PITCHB + k*16, g_vh + go + k*8);
                cp16(sb + 3*FBN*PITCHB + k*16, g_vl + go + k*8);
            }
        }
        CP_COMMIT();
        CP_WAIT1();
        __syncthreads();

        if (kt == 0) {
            uint32_t aQ = sQh + wid * 16 * PITCHB + aoff;
#pragma unroll
            for (int kc = 0; kc < 6; kc++) {
                ldmx4(qfh[kc], aQ + kc * 32);
                ldmx4(qfl[kc], aQ + FBM * PITCHB + kc * 32);
            }
        }

        const uint32_t stg = sKV + (kt & 1) * KVSTG;

        float sacc[8][4];
#pragma unroll
        for (int n = 0; n < 8; n++)
#pragma unroll
            for (int u = 0; u < 4; u++) sacc[n][u] = 0.f;
#pragma unroll
        for (int kc = 0; kc < 6; kc++) {
#pragma unroll
            for (int g = 0; g < 4; g++) {
                uint32_t kh4[4], kl4[4];
                ldmx4(kh4, stg + boff + g * (16 * PITCHB) + kc * 32);
                ldmx4(kl4, stg + FBN*PITCHB + boff + g * (16 * PITCHB) + kc * 32);
                mma16816(sacc[2*g],   qfh[kc], &kh4[0]);
                mma16816(sacc[2*g+1], qfh[kc], &kh4[2]);
                mma16816(sacc[2*g],   qfh[kc], &kl4[0]);
                mma16816(sacc[2*g+1], qfh[kc], &kl4[2]);
                mma16816(sacc[2*g],   qfl[kc], &kh4[0]);
                mma16816(sacc[2*g+1], qfl[kc], &kh4[2]);
            }
        }

        const int colb = kt * FBN + 2 * (lid & 3);
        float ml0 = -1e30f, ml1 = -1e30f;
#pragma unroll
        for (int n = 0; n < 8; n++)
#pragma unroll
            for (int e = 0; e < 2; e++) {
                int col = colb + 8 * n + e;
                float v0 = sacc[n][e] * scale;     if (col > row0)     v0 = -1e30f;
                float v1 = sacc[n][2 + e] * scale; if (col > row0 + 8) v1 = -1e30f;
                sacc[n][e] = v0; sacc[n][2 + e] = v1;
                ml0 = fmaxf(ml0, v0); ml1 = fmaxf(ml1, v1);
            }
        ml0 = fmaxf(ml0, __shfl_xor_sync(0xffffffffu, ml0, 1));
        ml0 = fmaxf(ml0, __shfl_xor_sync(0xffffffffu, ml0, 2));
        ml1 = fmaxf(ml1, __shfl_xor_sync(0xffffffffu, ml1, 1));
        ml1 = fmaxf(ml1, __shfl_xor_sync(0xffffffffu, ml1, 2));
        float mn0 = fmaxf(m0, ml0), mn1 = fmaxf(m1, ml1);
        float al0 = __expf(m0 - mn0), al1 = __expf(m1 - mn1);
        float ps0 = 0.f, ps1 = 0.f;
#pragma unroll
        for (int n = 0; n < 8; n++) {
            sacc[n][0] = __expf(sacc[n][0] - mn0); ps0 += sacc[n][0];
            sacc[n][1] = __expf(sacc[n][1] - mn0); ps0 += sacc[n][1];
            sacc[n][2] = __expf(sacc[n][2] - mn1); ps1 += sacc[n][2];
            sacc[n][3] = __expf(sacc[n][3] - mn1); ps1 += sacc[n][3];
        }
        ps0 += __shfl_xor_sync(0xffffffffu, ps0, 1);
        ps0 += __shfl_xor_sync(0xffffffffu, ps0, 2);
        ps1 += __shfl_xor_sync(0xffffffffu, ps1, 1);
        ps1 += __shfl_xor_sync(0xffffffffu, ps1, 2);
        lsum0 = lsum0 * al0 + ps0; m0 = mn0;
        lsum1 = lsum1 * al1 + ps1; m1 = mn1;
#pragma unroll
        for (int n = 0; n < 12; n++) {
            oacc[n][0] *= al0; oacc[n][1] *= al0;
            oacc[n][2] *= al1; oacc[n][3] *= al1;
        }

        const uint32_t vBh = stg + 2 * FBN * PITCHB + aoff;
#pragma unroll
        for (int kc2 = 0; kc2 < 4; kc2++) {
            uint32_t pah[4], pal[4];
            split2(sacc[2*kc2][0],   sacc[2*kc2][1],   pah[0], pal[0]);
            split2(sacc[2*kc2][2],   sacc[2*kc2][3],   pah[1], pal[1]);
            split2(sacc[2*kc2+1][0], sacc[2*kc2+1][1], pah[2], pal[2]);
            split2(sacc[2*kc2+1][2], sacc[2*kc2+1][3], pah[3], pal[3]);
            uint32_t vb = vBh + kc2 * (16 * PITCHB);
#pragma unroll
            for (int dn = 0; dn < 6; dn++) {
                uint32_t vh4[4], vl4[4];
                ldmx4t(vh4, vb + dn * 32);
                ldmx4t(vl4, vb + FBN*PITCHB + dn * 32);
                mma16816(oacc[2*dn],   pah, &vh4[0]);
                mma16816(oacc[2*dn+1], pah, &vh4[2]);
                mma16816(oacc[2*dn],   pal, &vh4[0]);
                mma16816(oacc[2*dn+1], pal, &vh4[2]);
                mma16816(oacc[2*dn],   pah, &vl4[0]);
                mma16816(oacc[2*dn+1], pah, &vl4[2]);
            }
        }
        __syncthreads();
    }

    const int b_ = bh >> 3, h_ = bh & 7;
    const float il0 = 1.f / lsum0, il1 = 1.f / lsum1;
    const size_t base0 = (size_t)(b_ * SEQ + row0) * CE + h_ * HD + 2 * (lid & 3);
    const size_t base1 = base0 + (size_t)8 * CE;
#pragma unroll
    for (int n = 0; n < 12; n++) {
        uint32_t hi, lo;
        split2(oacc[n][0] * il0, oacc[n][1] * il0, hi, lo);
        *(uint32_t*)(g_ah + base0 + 8 * n) = hi;
        *(uint32_t*)(g_al + base0 + 8 * n) = lo;
        split2(oacc[n][2] * il1, oacc[n][3] * il1, hi, lo);
        *(uint32_t*)(g_ah + base1 + 8 * n) = hi;
        *(uint32_t*)(g_al + base1 + 8 * n) = lo;
    }
}

// ---------------------------------------------------------------------------
extern "C" void kernel_launch(void* const* d_in, const int* in_sizes, int n_in,
                              void* d_out, int out_size)
{
    const float* x  = (const float*)d_in[0];   // [8,1024,768]
    const float* Wa = (const float*)d_in[1];   // [768,2304]
    const float* Wp = (const float*)d_in[2];   // [768,768]
    float* out = (float*)d_out;

    void *xh, *xl, *wah, *wal, *wph, *wpl, *ah, *al;
    cudaGetSymbolAddress(&xh,  g_xh);  cudaGetSymbolAddress(&xl,  g_xl);
    cudaGetSymbolAddress(&wah, g_wah); cudaGetSymbolAddress(&wal, g_wal);
    cudaGetSymbolAddress(&wph, g_wph); cudaGetSymbolAddress(&wpl, g_wpl);
    cudaGetSymbolAddress(&ah,  g_ah);  cudaGetSymbolAddress(&al,  g_al);

    cudaFuncSetAttribute(flash_mma, cudaFuncAttributeMaxDynamicSharedMemorySize, FSMEM);

    // conversions
    split_kernel<<<(MROWS * KDIM) / 1024, 256>>>(x, (__nv_bfloat16*)xh, (__nv_bfloat16*)xl, MROWS * KDIM);
    dim3 bt(32, 8);
    tsplit_kernel<<<dim3(NQKV / 32, KDIM / 32), bt>>>(Wa, (__nv_bfloat16*)wah, (__nv_bfloat16*)wal, KDIM, NQKV);
    tsplit_kernel<<<dim3(CE / 32, KDIM / 32), bt>>>(Wp, (__nv_bfloat16*)wph, (__nv_bfloat16*)wpl, KDIM, CE);

    // 1) QKV GEMM (HMMA) -> split-bf16 q/k/v [B,H,T,D]
    gemm_mma<<<dim3(NQKV / 128, MROWS / 64), 128>>>(
        (__nv_bfloat16*)xh, (__nv_bfloat16*)xl,
        (__nv_bfloat16*)wah, (__nv_bfloat16*)wal, nullptr, 1);

    // 2) flash attention (HMMA) -> g_ah/g_al (split bf16, [B,T,C])
    flash_mma<<<dim3(SEQ / FBM, BATCH * NHEAD), 256, FSMEM>>>();

    // 3) output projection (HMMA) -> d_out
    gemm_mma<<<dim3(CE / 128, MROWS / 64), 128>>>(
        (__nv_bfloat16*)ah, (__nv_bfloat16*)al,
        (__nv_bfloat16*)wph, (__nv_bfloat16*)wpl, out, 0);
}

// round 7
// speedup vs baseline: 1.0722x; 1.0722x over previous
#include <cuda_runtime.h>
#include <cuda_bf16.h>
#include <stdint.h>

#define CE     768
#define NHEAD  8
#define HD     96
#define BATCH  8
#define SEQ    1024
#define MROWS  (BATCH*SEQ)
#define KDIM   768
#define NQKV   (3*CE)
#define NK     (KDIM/16)          // 48 chunks of K=16

// ------------------------------- scratch (allocation-free rule) -------------
__device__ __align__(16) __nv_bfloat16 g_xh[MROWS*KDIM];
__device__ __align__(16) __nv_bfloat16 g_xl[MROWS*KDIM];
__device__ __align__(16) __nv_bfloat16 g_wah[NQKV*KDIM];
__device__ __align__(16) __nv_bfloat16 g_wal[NQKV*KDIM];
__device__ __align__(16) __nv_bfloat16 g_wph[CE*KDIM];
__device__ __align__(16) __nv_bfloat16 g_wpl[CE*KDIM];
__device__ __align__(16) __nv_bfloat16 g_ah[MROWS*KDIM];
__device__ __align__(16) __nv_bfloat16 g_al[MROWS*KDIM];
__device__ __align__(16) __nv_bfloat16 g_qh[BATCH*NHEAD*SEQ*HD];
__device__ __align__(16) __nv_bfloat16 g_ql[BATCH*NHEAD*SEQ*HD];
__device__ __align__(16) __nv_bfloat16 g_kh[BATCH*NHEAD*SEQ*HD];
__device__ __align__(16) __nv_bfloat16 g_kl[BATCH*NHEAD*SEQ*HD];
__device__ __align__(16) __nv_bfloat16 g_vh[BATCH*NHEAD*SEQ*HD];
__device__ __align__(16) __nv_bfloat16 g_vl[BATCH*NHEAD*SEQ*HD];

// ------------------------------- helpers ------------------------------------
__device__ __forceinline__ uint32_t smem_u32(const void* p) {
    uint32_t a;
    asm("{ .reg .u64 t; cvta.to.shared.u64 t, %1; cvt.u32.u64 %0, t; }" : "=r"(a) : "l"(p));
    return a;
}
__device__ __forceinline__ void ldmx4(uint32_t* r, uint32_t addr) {
    asm volatile("ldmatrix.sync.aligned.m8n8.x4.shared.b16 {%0,%1,%2,%3}, [%4];"
                 : "=r"(r[0]), "=r"(r[1]), "=r"(r[2]), "=r"(r[3]) : "r"(addr));
}
__device__ __forceinline__ void ldmx4t(uint32_t* r, uint32_t addr) {
    asm volatile("ldmatrix.sync.aligned.m8n8.x4.trans.shared.b16 {%0,%1,%2,%3}, [%4];"
                 : "=r"(r[0]), "=r"(r[1]), "=r"(r[2]), "=r"(r[3]) : "r"(addr));
}
__device__ __forceinline__ void mma16816(float* c, const uint32_t* a, const uint32_t* b) {
    asm volatile(
        "mma.sync.aligned.m16n8k16.row.col.f32.bf16.bf16.f32 "
        "{%0,%1,%2,%3}, {%4,%5,%6,%7}, {%8,%9}, {%0,%1,%2,%3};"
        : "+f"(c[0]), "+f"(c[1]), "+f"(c[2]), "+f"(c[3])
        : "r"(a[0]), "r"(a[1]), "r"(a[2]), "r"(a[3]), "r"(b[0]), "r"(b[1]));
}
__device__ __forceinline__ void cp16(uint32_t saddr, const void* gptr) {
    asm volatile("cp.async.ca.shared.global [%0], [%1], 16;"
                 :: "r"(saddr), "l"(__cvta_generic_to_global(gptr)) : "memory");
}
#define CP_COMMIT() asm volatile("cp.async.commit_group;" ::: "memory")
#define CP_WAIT1()  asm volatile("cp.async.wait_group 1;" ::: "memory")

__device__ __forceinline__ void split2(float x, float y, uint32_t& hi, uint32_t& lo) {
    __nv_bfloat162 h, l;
    h.x = __float2bfloat16(x);  h.y = __float2bfloat16(y);
    l.x = __float2bfloat16(x - __bfloat162float(h.x));
    l.y = __float2bfloat16(y - __bfloat162float(h.y));
    hi = *(uint32_t*)&h;  lo = *(uint32_t*)&l;
}

// ------------------------------- conversion kernels -------------------------
__global__ void split_kernel(const float* __restrict__ in,
                             __nv_bfloat16* __restrict__ hi,
                             __nv_bfloat16* __restrict__ lo, int n)
{
    int i = (blockIdx.x * 256 + threadIdx.x) * 4;
    if (i >= n) return;
    float4 v = *(const float4*)(in + i);
    uint32_t h0, l0, h1, l1;
    split2(v.x, v.y, h0, l0);
    split2(v.z, v.w, h1, l1);
    *(uint32_t*)(hi + i)     = h0;  *(uint32_t*)(hi + i + 2) = h1;
    *(uint32_t*)(lo + i)     = l0;  *(uint32_t*)(lo + i + 2) = l1;
}

// in: [K,N] row-major -> out hi/lo: [N,K] row-major (transposed) + split
__global__ void tsplit_kernel(const float* __restrict__ in,
                              __nv_bfloat16* __restrict__ hi,
                              __nv_bfloat16* __restrict__ lo, int K, int N)
{
    __shared__ float t[32][33];
    const int n0 = blockIdx.x * 32, k0 = blockIdx.y * 32;
#pragma unroll
    for (int i = 0; i < 4; i++) {
        int k = k0 + threadIdx.y + i * 8;
        t[threadIdx.y + i * 8][threadIdx.x] = in[(size_t)k * N + n0 + threadIdx.x];
    }
    __syncthreads();
#pragma unroll
    for (int i = 0; i < 4; i++) {
        int n = n0 + threadIdx.y + i * 8;
        float v = t[threadIdx.x][threadIdx.y + i * 8];
        __nv_bfloat16 h = __float2bfloat16(v);
        size_t o = (size_t)n * K + k0 + threadIdx.x;
        hi[o] = h;
        lo[o] = __float2bfloat16(v - __bfloat162float(h));
    }
}

// ------------------------------- HMMA GEMM ----------------------------------
// C[M,N] = (Ah+Al)[M,768]*(Bh+Bl)[N,768]^T, 3-pass split-bf16, fp32 accum.
// Block 128x128, 8 warps (4Mx2N), K-chunk 16, THREE-stage cp.async pipeline,
// ONE __syncthreads per chunk, pass-major MMA ordering (16 independent MMAs
// per pass -> no accumulator RAW chains).
__global__ __launch_bounds__(256) void gemm_mma(
    const __nv_bfloat16* __restrict__ Ah, const __nv_bfloat16* __restrict__ Al,
    const __nv_bfloat16* __restrict__ Bh, const __nv_bfloat16* __restrict__ Bl,
    float* __restrict__ outp, int scatter)
{
    extern __shared__ uint8_t sm[];               // 3 stages x 16384
    const int tid = threadIdx.x, lid = tid & 31, wid = tid >> 5;
    const int wm = wid & 3, wn = wid >> 2;
    const int mbase = blockIdx.y * 128, nbase = blockIdx.x * 128;
    const uint32_t sbase = smem_u32(sm);

    const int r = tid >> 1, ch = tid & 1;
    const uint32_t so = ((r >> 3) << 8) | ((r & 7) << 4) | (ch << 7);
    const __nv_bfloat16* pAh = Ah + (size_t)(mbase + r) * KDIM + ch * 8;
    const __nv_bfloat16* pAl = Al + (size_t)(mbase + r) * KDIM + ch * 8;
    const __nv_bfloat16* pBh = Bh + (size_t)(nbase + r) * KDIM + ch * 8;
    const __nv_bfloat16* pBl = Bl + (size_t)(nbase + r) * KDIM + ch * 8;

    const uint32_t aoff = ((lid & 7) << 4) | (((lid >> 3) & 1) << 8) | ((lid >> 4) << 7);
    const uint32_t boff = ((lid & 7) << 4) | (((lid >> 3) & 1) << 7) | ((lid >> 4) << 8);

    float acc[2][8][4];
#pragma unroll
    for (int mt = 0; mt < 2; mt++)
#pragma unroll
        for (int nt = 0; nt < 8; nt++)
#pragma unroll
            for (int u = 0; u < 4; u++) acc[mt][nt][u] = 0.f;

    auto load_chunk = [&](int c, int stg) {
        uint32_t sb = sbase + stg * 16384 + so;
        int ko = c * 16;
        cp16(sb,         pAh + ko);
        cp16(sb + 4096,  pAl + ko);
        cp16(sb + 8192,  pBh + ko);
        cp16(sb + 12288, pBl + ko);
    };

    load_chunk(0, 0); CP_COMMIT();
    load_chunk(1, 1); CP_COMMIT();

    for (int c = 0; c < NK; c++) {
        CP_WAIT1();                       // chunk c resident (oldest completes first)
        __syncthreads();                  // all warps done with chunk c-1 compute

        if (c + 2 < NK) load_chunk(c + 2, (c + 2) % 3);
        CP_COMMIT();                      // always commit: stable group accounting

        const uint32_t base = sbase + (c % 3) * 16384;
        const uint32_t aAh = base + wm * 1024 + aoff;
        const uint32_t aAl = base + 4096 + wm * 1024 + aoff;
        const uint32_t aBh = base + 8192 + wn * 2048 + boff;
        const uint32_t aBl = base + 12288 + wn * 2048 + boff;

        uint32_t ah[2][4], al[2][4], bh[4][4], bl[4][4];
#pragma unroll
        for (int mt = 0; mt < 2; mt++) { ldmx4(ah[mt], aAh + mt * 512); ldmx4(al[mt], aAl + mt * 512); }
#pragma unroll
        for (int g = 0; g < 4; g++) { ldmx4(bh[g], aBh + g * 512); ldmx4(bl[g], aBl + g * 512); }

        // pass-major: 16 independent MMAs per pass (acc RAW distance = 16)
#pragma unroll
        for (int mt = 0; mt < 2; mt++)
#pragma unroll
            for (int g = 0; g < 4; g++) {
                mma16816(acc[mt][2*g],   ah[mt], &bh[g][0]);
                mma16816(acc[mt][2*g+1], ah[mt], &bh[g][2]);
            }
#pragma unroll
        for (int mt = 0; mt < 2; mt++)
#pragma unroll
            for (int g = 0; g < 4; g++) {
                mma16816(acc[mt][2*g],   ah[mt], &bl[g][0]);
                mma16816(acc[mt][2*g+1], ah[mt], &bl[g][2]);
            }
#pragma unroll
        for (int mt = 0; mt < 2; mt++)
#pragma unroll
            for (int g = 0; g < 4; g++) {
                mma16816(acc[mt][2*g],   al[mt], &bh[g][0]);
                mma16816(acc[mt][2*g+1], al[mt], &bh[g][2]);
            }
    }

    const int rowb = mbase + wm * 32 + (lid >> 2);
    const int colb = nbase + wn * 64 + 2 * (lid & 3);
#pragma unroll
    for (int mt = 0; mt < 2; mt++)
#pragma unroll
        for (int nt = 0; nt < 8; nt++) {
            int col = colb + nt * 8;
#pragma unroll
            for (int h2 = 0; h2 < 2; h2++) {
                int row = rowb + mt * 16 + h2 * 8;
                float vx = acc[mt][nt][2*h2], vy = acc[mt][nt][2*h2+1];
                if (scatter) {
                    int which = col / CE, cc = col - which * CE;
                    int h = cc / HD, d = cc - h * HD;
                    int bb = row >> 10, tt = row & 1023;
                    size_t idx = (size_t)(((bb * NHEAD + h) * SEQ) + tt) * HD + d;
                    uint32_t hi, lo;
                    split2(vx, vy, hi, lo);
                    __nv_bfloat16 *dh, *dl;
                    if (which == 0)      { dh = g_qh; dl = g_ql; }
                    else if (which == 1) { dh = g_kh; dl = g_kl; }
                    else                 { dh = g_vh; dl = g_vl; }
                    *(uint32_t*)(dh + idx) = hi;
                    *(uint32_t*)(dl + idx) = lo;
                } else {
                    *(float2*)(outp + (size_t)row * CE + col) = make_float2(vx, vy);
                }
            }
        }
}

// ------------------------------- flash attention (HMMA) ---------------------
#define FBM    128
#define FBN    64
#define PITCHB 208
#define KVSTG  (4*FBN*PITCHB)
#define FSMEM  (2*FBM*PITCHB + 2*KVSTG)

__global__ __launch_bounds__(256, 1) void flash_mma()
{
    extern __shared__ uint8_t fs[];
    const int tid = threadIdx.x, lid = tid & 31, wid = tid >> 5;
    const int bh = blockIdx.y;
    const int qt = (int)gridDim.x - 1 - (int)blockIdx.x;
    const int q0 = qt * FBM;
    const uint32_t sQh = smem_u32(fs);
    const uint32_t sKV = sQh + 2 * FBM * PITCHB;
    const size_t gb = (size_t)bh * SEQ * HD;
    const float scale = 0.10206207261596575f;

    const int rkv = tid >> 2, qq = tid & 3;

    {
        uint32_t sb = sKV + rkv * PITCHB + qq * 48;
        size_t go = gb + (size_t)rkv * HD + qq * 24;
#pragma unroll
        for (int k = 0; k < 3; k++) {
            cp16(sb + k*16,                 g_kh + go + k*8);
            cp16(sb + FBN*PITCHB + k*16,    g_kl + go + k*8);
            cp16(sb + 2*FBN*PITCHB + k*16,  g_vh + go + k*8);
            cp16(sb + 3*FBN*PITCHB + k*16,  g_vl + go + k*8);
        }
    }
    CP_COMMIT();
    {
        int r = tid >> 1, hf = tid & 1;
        uint32_t sq = sQh + r * PITCHB + hf * 96;
        size_t gq = gb + (size_t)(q0 + r) * HD + hf * 48;
#pragma unroll
        for (int k = 0; k < 6; k++) {
            cp16(sq + k*16,              g_qh + gq + k*8);
            cp16(sq + FBM*PITCHB + k*16, g_ql + gq + k*8);
        }
    }
    CP_COMMIT();

    const uint32_t aoff = (lid & 7) * PITCHB + ((lid >> 3) & 1) * (8 * PITCHB) + (lid >> 4) * 16;
    const uint32_t boff = (lid & 7) * PITCHB + ((lid >> 3) & 1) * 16 + (lid >> 4) * (8 * PITCHB);

    uint32_t qfh[6][4], qfl[6][4];
    float oacc[12][4];
#pragma unroll
    for (int n = 0; n < 12; n++)
#pragma unroll
        for (int u = 0; u < 4; u++) oacc[n][u] = 0.f;
    float m0 = -1e30f, m1 = -1e30f, lsum0 = 0.f, lsum1 = 0.f;
    const int row0 = q0 + wid * 16 + (lid >> 2);

    const int nkt = 2 * qt + 2;
    for (int kt = 0; kt < nkt; kt++) {
        if (kt + 1 < nkt) {
            uint32_t sb = sKV + ((kt + 1) & 1) * KVSTG + rkv * PITCHB + qq * 48;
            size_t go = gb + (size_t)((kt + 1) * FBN + rkv) * HD + qq * 24;
#pragma unroll
            for (int k = 0; k < 3; k++) {
                cp16(sb + k*16,                g_kh + go + k*8);
                cp16(sb + FBN*PITCHB + k*16,   g_kl + go + k*8);
                cp16(sb + 2*FBN*PITCHB + k*16, g_vh + go + k*8);
                cp16(sb + 3*FBN*PITCHB + k*16, g_vl + go + k*8);
            }
        }
        CP_COMMIT();
        CP_WAIT1();
        __syncthreads();

        if (kt == 0) {
            uint32_t aQ = sQh + wid * 16 * PITCHB + aoff;
#pragma unroll
            for (int kc = 0; kc < 6; kc++) {
                ldmx4(qfh[kc], aQ + kc * 32);
                ldmx4(qfl[kc], aQ + FBM * PITCHB + kc * 32);
            }
        }

        const uint32_t stg = sKV + (kt & 1) * KVSTG;

        float sacc[8][4];
#pragma unroll
        for (int n = 0; n < 8; n++)
#pragma unroll
            for (int u = 0; u < 4; u++) sacc[n][u] = 0.f;
#pragma unroll
        for (int kc = 0; kc < 6; kc++) {
#pragma unroll
            for (int g = 0; g < 4; g++) {
                uint32_t kh4[4], kl4[4];
                ldmx4(kh4, stg + boff + g * (16 * PITCHB) + kc * 32);
                ldmx4(kl4, stg + FBN*PITCHB + boff + g * (16 * PITCHB) + kc * 32);
                mma16816(sacc[2*g],   qfh[kc], &kh4[0]);
                mma16816(sacc[2*g+1], qfh[kc], &kh4[2]);
                mma16816(sacc[2*g],   qfh[kc], &kl4[0]);
                mma16816(sacc[2*g+1], qfh[kc], &kl4[2]);
                mma16816(sacc[2*g],   qfl[kc], &kh4[0]);
                mma16816(sacc[2*g+1], qfl[kc], &kh4[2]);
            }
        }

        const int colb = kt * FBN + 2 * (lid & 3);
        float ml0 = -1e30f, ml1 = -1e30f;
#pragma unroll
        for (int n = 0; n < 8; n++)
#pragma unroll
            for (int e = 0; e < 2; e++) {
                int col = colb + 8 * n + e;
                float v0 = sacc[n][e] * scale;     if (col > row0)     v0 = -1e30f;
                float v1 = sacc[n][2 + e] * scale; if (col > row0 + 8) v1 = -1e30f;
                sacc[n][e] = v0; sacc[n][2 + e] = v1;
                ml0 = fmaxf(ml0, v0); ml1 = fmaxf(ml1, v1);
            }
        ml0 = fmaxf(ml0, __shfl_xor_sync(0xffffffffu, ml0, 1));
        ml0 = fmaxf(ml0, __shfl_xor_sync(0xffffffffu, ml0, 2));
        ml1 = fmaxf(ml1, __shfl_xor_sync(0xffffffffu, ml1, 1));
        ml1 = fmaxf(ml1, __shfl_xor_sync(0xffffffffu, ml1, 2));
        float mn0 = fmaxf(m0, ml0), mn1 = fmaxf(m1, ml1);
        float al0 = __expf(m0 - mn0), al1 = __expf(m1 - mn1);
        float ps0 = 0.f, ps1 = 0.f;
#pragma unroll
        for (int n = 0; n < 8; n++) {
            sacc[n][0] = __expf(sacc[n][0] - mn0); ps0 += sacc[n][0];
            sacc[n][1] = __expf(sacc[n][1] - mn0); ps0 += sacc[n][1];
            sacc[n][2] = __expf(sacc[n][2] - mn1); ps1 += sacc[n][2];
            sacc[n][3] = __expf(sacc[n][3] - mn1); ps1 += sacc[n][3];
        }
        ps0 += __shfl_xor_sync(0xffffffffu, ps0, 1);
        ps0 += __shfl_xor_sync(0xffffffffu, ps0, 2);
        ps1 += __shfl_xor_sync(0xffffffffu, ps1, 1);
        ps1 += __shfl_xor_sync(0xffffffffu, ps1, 2);
        lsum0 = lsum0 * al0 + ps0; m0 = mn0;
        lsum1 = lsum1 * al1 + ps1; m1 = mn1;
#pragma unroll
        for (int n = 0; n < 12; n++) {
            oacc[n][0] *= al0; oacc[n][1] *= al0;
            oacc[n][2] *= al1; oacc[n][3] *= al1;
        }

        const uint32_t vBh = stg + 2 * FBN * PITCHB + aoff;
#pragma unroll
        for (int kc2 = 0; kc2 < 4; kc2++) {
            uint32_t pah[4], pal[4];
            split2(sacc[2*kc2][0],   sacc[2*kc2][1],   pah[0], pal[0]);
            split2(sacc[2*kc2][2],   sacc[2*kc2][3],   pah[1], pal[1]);
            split2(sacc[2*kc2+1][0], sacc[2*kc2+1][1], pah[2], pal[2]);
            split2(sacc[2*kc2+1][2], sacc[2*kc2+1][3], pah[3], pal[3]);
            uint32_t vb = vBh + kc2 * (16 * PITCHB);
#pragma unroll
            for (int dn = 0; dn < 6; dn++) {
                uint32_t vh4[4], vl4[4];
                ldmx4t(vh4, vb + dn * 32);
                ldmx4t(vl4, vb + FBN*PITCHB + dn * 32);
                mma16816(oacc[2*dn],   pah, &vh4[0]);
                mma16816(oacc[2*dn+1], pah, &vh4[2]);
                mma16816(oacc[2*dn],   pal, &vh4[0]);
                mma16816(oacc[2*dn+1], pal, &vh4[2]);
                mma16816(oacc[2*dn],   pah, &vl4[0]);
                mma16816(oacc[2*dn+1], pah, &vl4[2]);
            }
        }
        __syncthreads();
    }

    const int b_ = bh >> 3, h_ = bh & 7;
    const float il0 = 1.f / lsum0, il1 = 1.f / lsum1;
    const size_t base0 = (size_t)(b_ * SEQ + row0) * CE + h_ * HD + 2 * (lid & 3);
    const size_t base1 = base0 + (size_t)8 * CE;
#pragma unroll
    for (int n = 0; n < 12; n++) {
        uint32_t hi, lo;
        split2(oacc[n][0] * il0, oacc[n][1] * il0, hi, lo);
        *(uint32_t*)(g_ah + base0 + 8 * n) = hi;
        *(uint32_t*)(g_al + base0 + 8 * n) = lo;
        split2(oacc[n][2] * il1, oacc[n][3] * il1, hi, lo);
        *(uint32_t*)(g_ah + base1 + 8 * n) = hi;
        *(uint32_t*)(g_al + base1 + 8 * n) = lo;
    }
}

// ---------------------------------------------------------------------------
extern "C" void kernel_launch(void* const* d_in, const int* in_sizes, int n_in,
                              void* d_out, int out_size)
{
    const float* x  = (const float*)d_in[0];   // [8,1024,768]
    const float* Wa = (const float*)d_in[1];   // [768,2304]
    const float* Wp = (const float*)d_in[2];   // [768,768]
    float* out = (float*)d_out;

    void *xh, *xl, *wah, *wal, *wph, *wpl, *ah, *al;
    cudaGetSymbolAddress(&xh,  g_xh);  cudaGetSymbolAddress(&xl,  g_xl);
    cudaGetSymbolAddress(&wah, g_wah); cudaGetSymbolAddress(&wal, g_wal);
    cudaGetSymbolAddress(&wph, g_wph); cudaGetSymbolAddress(&wpl, g_wpl);
    cudaGetSymbolAddress(&ah,  g_ah);  cudaGetSymbolAddress(&al,  g_al);

    cudaFuncSetAttribute(flash_mma, cudaFuncAttributeMaxDynamicSharedMemorySize, FSMEM);
    cudaFuncSetAttribute(gemm_mma,  cudaFuncAttributeMaxDynamicSharedMemorySize, 49152);

    // conversions
    split_kernel<<<(MROWS * KDIM) / 1024, 256>>>(x, (__nv_bfloat16*)xh, (__nv_bfloat16*)xl, MROWS * KDIM);
    dim3 bt(32, 8);
    tsplit_kernel<<<dim3(NQKV / 32, KDIM / 32), bt>>>(Wa, (__nv_bfloat16*)wah, (__nv_bfloat16*)wal, KDIM, NQKV);
    tsplit_kernel<<<dim3(CE / 32, KDIM / 32), bt>>>(Wp, (__nv_bfloat16*)wph, (__nv_bfloat16*)wpl, KDIM, CE);

    // 1) QKV GEMM (HMMA) -> split-bf16 q/k/v [B,H,T,D]
    gemm_mma<<<dim3(NQKV / 128, MROWS / 128), 256, 49152>>>(
        (__nv_bfloat16*)xh, (__nv_bfloat16*)xl,
        (__nv_bfloat16*)wah, (__nv_bfloat16*)wal, nullptr, 1);

    // 2) flash attention (HMMA) -> g_ah/g_al (split bf16, [B,T,C])
    flash_mma<<<dim3(SEQ / FBM, BATCH * NHEAD), 256, FSMEM>>>();

    // 3) output projection (HMMA) -> d_out
    gemm_mma<<<dim3(CE / 128, MROWS / 128), 256, 49152>>>(
        (__nv_bfloat16*)ah, (__nv_bfloat16*)al,
        (__nv_bfloat16*)wph, (__nv_bfloat16*)wpl, out, 0);
}

// round 8
// speedup vs baseline: 1.4700x; 1.3710x over previous
#include <cuda_runtime.h>
#include <cuda_bf16.h>
#include <cuda_fp16.h>
#include <stdint.h>

#define CE     768
#define NHEAD  8
#define HD     96
#define BATCH  8
#define SEQ    1024
#define MROWS  (BATCH*SEQ)
#define KDIM   768
#define NQKV   (3*CE)
#define NK     (KDIM/16)          // 48 chunks of K=16

// ------------------------------- scratch (allocation-free rule) -------------
__device__ __align__(16) __half g_xh[MROWS*KDIM];
__device__ __align__(16) __half g_xl[MROWS*KDIM];
__device__ __align__(16) __half g_wah[NQKV*KDIM];
__device__ __align__(16) __half g_wph[CE*KDIM];
__device__ __align__(16) __half g_ah[MROWS*KDIM];
__device__ __align__(16) __half g_al[MROWS*KDIM];
__device__ __align__(16) __nv_bfloat16 g_qh[BATCH*NHEAD*SEQ*HD];
__device__ __align__(16) __nv_bfloat16 g_ql[BATCH*NHEAD*SEQ*HD];
__device__ __align__(16) __nv_bfloat16 g_kh[BATCH*NHEAD*SEQ*HD];
__device__ __align__(16) __nv_bfloat16 g_kl[BATCH*NHEAD*SEQ*HD];
__device__ __align__(16) __nv_bfloat16 g_vh[BATCH*NHEAD*SEQ*HD];
__device__ __align__(16) __nv_bfloat16 g_vl[BATCH*NHEAD*SEQ*HD];

// ------------------------------- helpers ------------------------------------
__device__ __forceinline__ uint32_t smem_u32(const void* p) {
    uint32_t a;
    asm("{ .reg .u64 t; cvta.to.shared.u64 t, %1; cvt.u32.u64 %0, t; }" : "=r"(a) : "l"(p));
    return a;
}
__device__ __forceinline__ void ldmx4(uint32_t* r, uint32_t addr) {
    asm volatile("ldmatrix.sync.aligned.m8n8.x4.shared.b16 {%0,%1,%2,%3}, [%4];"
                 : "=r"(r[0]), "=r"(r[1]), "=r"(r[2]), "=r"(r[3]) : "r"(addr));
}
__device__ __forceinline__ void ldmx4t(uint32_t* r, uint32_t addr) {
    asm volatile("ldmatrix.sync.aligned.m8n8.x4.trans.shared.b16 {%0,%1,%2,%3}, [%4];"
                 : "=r"(r[0]), "=r"(r[1]), "=r"(r[2]), "=r"(r[3]) : "r"(addr));
}
// bf16 mma (flash)
__device__ __forceinline__ void mma16816(float* c, const uint32_t* a, const uint32_t* b) {
    asm volatile(
        "mma.sync.aligned.m16n8k16.row.col.f32.bf16.bf16.f32 "
        "{%0,%1,%2,%3}, {%4,%5,%6,%7}, {%8,%9}, {%0,%1,%2,%3};"
        : "+f"(c[0]), "+f"(c[1]), "+f"(c[2]), "+f"(c[3])
        : "r"(a[0]), "r"(a[1]), "r"(a[2]), "r"(a[3]), "r"(b[0]), "r"(b[1]));
}
// fp16 mma (GEMMs)
__device__ __forceinline__ void mma16816h(float* c, const uint32_t* a, const uint32_t* b) {
    asm volatile(
        "mma.sync.aligned.m16n8k16.row.col.f32.f16.f16.f32 "
        "{%0,%1,%2,%3}, {%4,%5,%6,%7}, {%8,%9}, {%0,%1,%2,%3};"
        : "+f"(c[0]), "+f"(c[1]), "+f"(c[2]), "+f"(c[3])
        : "r"(a[0]), "r"(a[1]), "r"(a[2]), "r"(a[3]), "r"(b[0]), "r"(b[1]));
}
__device__ __forceinline__ void cp16(uint32_t saddr, const void* gptr) {
    asm volatile("cp.async.ca.shared.global [%0], [%1], 16;"
                 :: "r"(saddr), "l"(__cvta_generic_to_global(gptr)) : "memory");
}
#define CP_COMMIT() asm volatile("cp.async.commit_group;" ::: "memory")
#define CP_WAIT1()  asm volatile("cp.async.wait_group 1;" ::: "memory")

__device__ __forceinline__ void split2(float x, float y, uint32_t& hi, uint32_t& lo) {
    __nv_bfloat162 h, l;
    h.x = __float2bfloat16(x);  h.y = __float2bfloat16(y);
    l.x = __float2bfloat16(x - __bfloat162float(h.x));
    l.y = __float2bfloat16(y - __bfloat162float(h.y));
    hi = *(uint32_t*)&h;  lo = *(uint32_t*)&l;
}
__device__ __forceinline__ void split2h(float x, float y, uint32_t& hi, uint32_t& lo) {
    __half2 h, l;
    h.x = __float2half(x);  h.y = __float2half(y);
    l.x = __float2half(x - __half2float(h.x));
    l.y = __float2half(y - __half2float(h.y));
    hi = *(uint32_t*)&h;  lo = *(uint32_t*)&l;
}

// ------------------------------- conversion kernels -------------------------
__global__ void split_kernel_h(const float* __restrict__ in,
                               __half* __restrict__ hi,
                               __half* __restrict__ lo, int n)
{
    int i = (blockIdx.x * 256 + threadIdx.x) * 4;
    if (i >= n) return;
    float4 v = *(const float4*)(in + i);
    uint32_t h0, l0, h1, l1;
    split2h(v.x, v.y, h0, l0);
    split2h(v.z, v.w, h1, l1);
    *(uint32_t*)(hi + i)     = h0;  *(uint32_t*)(hi + i + 2) = h1;
    *(uint32_t*)(lo + i)     = l0;  *(uint32_t*)(lo + i + 2) = l1;
}

// in: [K,N] fp32 row-major -> out: [N,K] fp16 (transposed)
__global__ void tconv_kernel(const float* __restrict__ in,
                             __half* __restrict__ outw, int K, int N)
{
    __shared__ float t[32][33];
    const int n0 = blockIdx.x * 32, k0 = blockIdx.y * 32;
#pragma unroll
    for (int i = 0; i < 4; i++) {
        int k = k0 + threadIdx.y + i * 8;
        t[threadIdx.y + i * 8][threadIdx.x] = in[(size_t)k * N + n0 + threadIdx.x];
    }
    __syncthreads();
#pragma unroll
    for (int i = 0; i < 4; i++) {
        int n = n0 + threadIdx.y + i * 8;
        float v = t[threadIdx.x][threadIdx.y + i * 8];
        outw[(size_t)n * K + k0 + threadIdx.x] = __float2half(v);
    }
}

// ------------------------------- HMMA GEMM (fp16, 2-pass) -------------------
// C[M,N] = (Ah+Al)[M,768] * B[N,768]^T, fp16 operands, fp32 accum.
// A split (exact); only B carries fp16 rounding (2.8e-4 RMS).
// Block 128x128, 8 warps (4Mx2N), K-chunk 16, double-buffered cp.async.
// Stage 12KB: Ah@0 Al@4096 B@8192. 2 CTAs/SM via launch_bounds(256,2).
__global__ __launch_bounds__(256, 2) void gemm_mma(
    const __half* __restrict__ Ah, const __half* __restrict__ Al,
    const __half* __restrict__ Bm,
    float* __restrict__ outp, int scatter)
{
    __shared__ __align__(128) uint8_t sm[2][12288];
    const int tid = threadIdx.x, lid = tid & 31, wid = tid >> 5;
    const int wm = wid & 3, wn = wid >> 2;
    const int mbase = blockIdx.y * 128, nbase = blockIdx.x * 128;
    const uint32_t sbase = smem_u32(sm);

    const int r = tid >> 1, ch = tid & 1;
    const uint32_t so = ((r >> 3) << 8) | ((r & 7) << 4) | (ch << 7);
    const __half* pAh = Ah + (size_t)(mbase + r) * KDIM + ch * 8;
    const __half* pAl = Al + (size_t)(mbase + r) * KDIM + ch * 8;
    const __half* pB  = Bm + (size_t)(nbase + r) * KDIM + ch * 8;

    const uint32_t aoff = ((lid & 7) << 4) | (((lid >> 3) & 1) << 8) | ((lid >> 4) << 7);
    const uint32_t boff = ((lid & 7) << 4) | (((lid >> 3) & 1) << 7) | ((lid >> 4) << 8);

    float acc[2][8][4];
#pragma unroll
    for (int mt = 0; mt < 2; mt++)
#pragma unroll
        for (int nt = 0; nt < 8; nt++)
#pragma unroll
            for (int u = 0; u < 4; u++) acc[mt][nt][u] = 0.f;

    {
        uint32_t sb = sbase + so;
        cp16(sb, pAh); cp16(sb + 4096, pAl); cp16(sb + 8192, pB);
        CP_COMMIT();
    }

    for (int c = 0; c < NK; c++) {
        if (c + 1 < NK) {
            uint32_t sb = sbase + ((c + 1) & 1) * 12288 + so;
            int ko = (c + 1) * 16;
            cp16(sb, pAh + ko); cp16(sb + 4096, pAl + ko); cp16(sb + 8192, pB + ko);
        }
        CP_COMMIT();
        CP_WAIT1();
        __syncthreads();

        const uint32_t base = sbase + (c & 1) * 12288;
        const uint32_t aAh = base + wm * 1024 + aoff;
        const uint32_t aAl = base + 4096 + wm * 1024 + aoff;
        const uint32_t bB  = base + 8192 + wn * 2048 + boff;

        uint32_t ah[2][4], al[2][4], bf[4][4];
#pragma unroll
        for (int mt = 0; mt < 2; mt++) { ldmx4(ah[mt], aAh + mt * 512); ldmx4(al[mt], aAl + mt * 512); }
#pragma unroll
        for (int g = 0; g < 4; g++) ldmx4(bf[g], bB + g * 512);

#pragma unroll
        for (int mt = 0; mt < 2; mt++)
#pragma unroll
            for (int g = 0; g < 4; g++) {
                mma16816h(acc[mt][2*g],   ah[mt], &bf[g][0]);
                mma16816h(acc[mt][2*g+1], ah[mt], &bf[g][2]);
                mma16816h(acc[mt][2*g],   al[mt], &bf[g][0]);
                mma16816h(acc[mt][2*g+1], al[mt], &bf[g][2]);
            }
        __syncthreads();
    }

    const int rowb = mbase + wm * 32 + (lid >> 2);
    const int colb = nbase + wn * 64 + 2 * (lid & 3);
#pragma unroll
    for (int mt = 0; mt < 2; mt++)
#pragma unroll
        for (int nt = 0; nt < 8; nt++) {
            int col = colb + nt * 8;
#pragma unroll
            for (int h2 = 0; h2 < 2; h2++) {
                int row = rowb + mt * 16 + h2 * 8;
                float vx = acc[mt][nt][2*h2], vy = acc[mt][nt][2*h2+1];
                if (scatter) {
                    int which = col / CE, cc = col - which * CE;
                    int h = cc / HD, d = cc - h * HD;
                    int bb = row >> 10, tt = row & 1023;
                    size_t idx = (size_t)(((bb * NHEAD + h) * SEQ) + tt) * HD + d;
                    uint32_t hi, lo;
                    split2(vx, vy, hi, lo);            // flash consumes bf16 splits
                    __nv_bfloat16 *dh, *dl;
                    if (which == 0)      { dh = g_qh; dl = g_ql; }
                    else if (which == 1) { dh = g_kh; dl = g_kl; }
                    else                 { dh = g_vh; dl = g_vl; }
                    *(uint32_t*)(dh + idx) = hi;
                    *(uint32_t*)(dl + idx) = lo;
                } else {
                    *(float2*)(outp + (size_t)row * CE + col) = make_float2(vx, vy);
                }
            }
        }
}

// ------------------------------- flash attention (HMMA bf16 3-pass) ---------
#define FBM    128
#define FBN    64
#define PITCHB 208
#define KVSTG  (4*FBN*PITCHB)
#define FSMEM  (2*FBM*PITCHB + 2*KVSTG)

__global__ __launch_bounds__(256, 1) void flash_mma()
{
    extern __shared__ uint8_t fs[];
    const int tid = threadIdx.x, lid = tid & 31, wid = tid >> 5;
    const int bh = blockIdx.y;
    const int qt = (int)gridDim.x - 1 - (int)blockIdx.x;
    const int q0 = qt * FBM;
    const uint32_t sQh = smem_u32(fs);
    const uint32_t sKV = sQh + 2 * FBM * PITCHB;
    const size_t gb = (size_t)bh * SEQ * HD;
    const float scale = 0.10206207261596575f;

    const int rkv = tid >> 2, qq = tid & 3;

    {
        uint32_t sb = sKV + rkv * PITCHB + qq * 48;
        size_t go = gb + (size_t)rkv * HD + qq * 24;
#pragma unroll
        for (int k = 0; k < 3; k++) {
            cp16(sb + k*16,                 g_kh + go + k*8);
            cp16(sb + FBN*PITCHB + k*16,    g_kl + go + k*8);
            cp16(sb + 2*FBN*PITCHB + k*16,  g_vh + go + k*8);
            cp16(sb + 3*FBN*PITCHB + k*16,  g_vl + go + k*8);
        }
    }
    CP_COMMIT();
    {
        int r = tid >> 1, hf = tid & 1;
        uint32_t sq = sQh + r * PITCHB + hf * 96;
        size_t gq = gb + (size_t)(q0 + r) * HD + hf * 48;
#pragma unroll
        for (int k = 0; k < 6; k++) {
            cp16(sq + k*16,              g_qh + gq + k*8);
            cp16(sq + FBM*PITCHB + k*16, g_ql + gq + k*8);
        }
    }
    CP_COMMIT();

    const uint32_t aoff = (lid & 7) * PITCHB + ((lid >> 3) & 1) * (8 * PITCHB) + (lid >> 4) * 16;
    const uint32_t boff = (lid & 7) * PITCHB + ((lid >> 3) & 1) * 16 + (lid >> 4) * (8 * PITCHB);

    uint32_t qfh[6][4], qfl[6][4];
    float oacc[12][4];
#pragma unroll
    for (int n = 0; n < 12; n++)
#pragma unroll
        for (int u = 0; u < 4; u++) oacc[n][u] = 0.f;
    float m0 = -1e30f, m1 = -1e30f, lsum0 = 0.f, lsum1 = 0.f;
    const int row0 = q0 + wid * 16 + (lid >> 2);

    const int nkt = 2 * qt + 2;
    for (int kt = 0; kt < nkt; kt++) {
        if (kt + 1 < nkt) {
            uint32_t sb = sKV + ((kt + 1) & 1) * KVSTG + rkv * PITCHB + qq * 48;
            size_t go = gb + (size_t)((kt + 1) * FBN + rkv) * HD + qq * 24;
#pragma unroll
            for (int k = 0; k < 3; k++) {
                cp16(sb + k*16,                g_kh + go + k*8);
                cp16(sb + FBN*PITCHB + k*16,   g_kl + go + k*8);
                cp16(sb + 2*FBN*PITCHB + k*16, g_vh + go + k*8);
                cp16(sb + 3*FBN*PITCHB + k*16, g_vl + go + k*8);
            }
        }
        CP_COMMIT();
        CP_WAIT1();
        __syncthreads();

        if (kt == 0) {
            uint32_t aQ = sQh + wid * 16 * PITCHB + aoff;
#pragma unroll
            for (int kc = 0; kc < 6; kc++) {
                ldmx4(qfh[kc], aQ + kc * 32);
                ldmx4(qfl[kc], aQ + FBM * PITCHB + kc * 32);
            }
        }

        const uint32_t stg = sKV + (kt & 1) * KVSTG;

        float sacc[8][4];
#pragma unroll
        for (int n = 0; n < 8; n++)
#pragma unroll
            for (int u = 0; u < 4; u++) sacc[n][u] = 0.f;
#pragma unroll
        for (int kc = 0; kc < 6; kc++) {
#pragma unroll
            for (int g = 0; g < 4; g++) {
                uint32_t kh4[4], kl4[4];
                ldmx4(kh4, stg + boff + g * (16 * PITCHB) + kc * 32);
                ldmx4(kl4, stg + FBN*PITCHB + boff + g * (16 * PITCHB) + kc * 32);
                mma16816(sacc[2*g],   qfh[kc], &kh4[0]);
                mma16816(sacc[2*g+1], qfh[kc], &kh4[2]);
                mma16816(sacc[2*g],   qfh[kc], &kl4[0]);
                mma16816(sacc[2*g+1], qfh[kc], &kl4[2]);
                mma16816(sacc[2*g],   qfl[kc], &kh4[0]);
                mma16816(sacc[2*g+1], qfl[kc], &kh4[2]);
            }
        }

        const int colb = kt * FBN + 2 * (lid & 3);
        float ml0 = -1e30f, ml1 = -1e30f;
#pragma unroll
        for (int n = 0; n < 8; n++)
#pragma unroll
            for (int e = 0; e < 2; e++) {
                int col = colb + 8 * n + e;
                float v0 = sacc[n][e] * scale;     if (col > row0)     v0 = -1e30f;
                float v1 = sacc[n][2 + e] * scale; if (col > row0 + 8) v1 = -1e30f;
                sacc[n][e] = v0; sacc[n][2 + e] = v1;
                ml0 = fmaxf(ml0, v0); ml1 = fmaxf(ml1, v1);
            }
        ml0 = fmaxf(ml0, __shfl_xor_sync(0xffffffffu, ml0, 1));
        ml0 = fmaxf(ml0, __shfl_xor_sync(0xffffffffu, ml0, 2));
        ml1 = fmaxf(ml1, __shfl_xor_sync(0xffffffffu, ml1, 1));
        ml1 = fmaxf(ml1, __shfl_xor_sync(0xffffffffu, ml1, 2));
        float mn0 = fmaxf(m0, ml0), mn1 = fmaxf(m1, ml1);
        float al0 = __expf(m0 - mn0), al1 = __expf(m1 - mn1);
        float ps0 = 0.f, ps1 = 0.f;
#pragma unroll
        for (int n = 0; n < 8; n++) {
            sacc[n][0] = __expf(sacc[n][0] - mn0); ps0 += sacc[n][0];
            sacc[n][1] = __expf(sacc[n][1] - mn0); ps0 += sacc[n][1];
            sacc[n][2] = __expf(sacc[n][2] - mn1); ps1 += sacc[n][2];
            sacc[n][3] = __expf(sacc[n][3] - mn1); ps1 += sacc[n][3];
        }
        ps0 += __shfl_xor_sync(0xffffffffu, ps0, 1);
        ps0 += __shfl_xor_sync(0xffffffffu, ps0, 2);
        ps1 += __shfl_xor_sync(0xffffffffu, ps1, 1);
        ps1 += __shfl_xor_sync(0xffffffffu, ps1, 2);
        lsum0 = lsum0 * al0 + ps0; m0 = mn0;
        lsum1 = lsum1 * al1 + ps1; m1 = mn1;
#pragma unroll
        for (int n = 0; n < 12; n++) {
            oacc[n][0] *= al0; oacc[n][1] *= al0;
            oacc[n][2] *= al1; oacc[n][3] *= al1;
        }

        const uint32_t vBh = stg + 2 * FBN * PITCHB + aoff;
#pragma unroll
        for (int kc2 = 0; kc2 < 4; kc2++) {
            uint32_t pah[4], pal[4];
            split2(sacc[2*kc2][0],   sacc[2*kc2][1],   pah[0], pal[0]);
            split2(sacc[2*kc2][2],   sacc[2*kc2][3],   pah[1], pal[1]);
            split2(sacc[2*kc2+1][0], sacc[2*kc2+1][1], pah[2], pal[2]);
            split2(sacc[2*kc2+1][2], sacc[2*kc2+1][3], pah[3], pal[3]);
            uint32_t vb = vBh + kc2 * (16 * PITCHB);
#pragma unroll
            for (int dn = 0; dn < 6; dn++) {
                uint32_t vh4[4], vl4[4];
                ldmx4t(vh4, vb + dn * 32);
                ldmx4t(vl4, vb + FBN*PITCHB + dn * 32);
                mma16816(oacc[2*dn],   pah, &vh4[0]);
                mma16816(oacc[2*dn+1], pah, &vh4[2]);
                mma16816(oacc[2*dn],   pal, &vh4[0]);
                mma16816(oacc[2*dn+1], pal, &vh4[2]);
                mma16816(oacc[2*dn],   pah, &vl4[0]);
                mma16816(oacc[2*dn+1], pah, &vl4[2]);
            }
        }
        __syncthreads();
    }

    // epilogue: O/l -> split-fp16 [B,T,C] for the projection GEMM
    const int b_ = bh >> 3, h_ = bh & 7;
    const float il0 = 1.f / lsum0, il1 = 1.f / lsum1;
    const size_t base0 = (size_t)(b_ * SEQ + row0) * CE + h_ * HD + 2 * (lid & 3);
    const size_t base1 = base0 + (size_t)8 * CE;
#pragma unroll
    for (int n = 0; n < 12; n++) {
        uint32_t hi, lo;
        split2h(oacc[n][0] * il0, oacc[n][1] * il0, hi, lo);
        *(uint32_t*)(g_ah + base0 + 8 * n) = hi;
        *(uint32_t*)(g_al + base0 + 8 * n) = lo;
        split2h(oacc[n][2] * il1, oacc[n][3] * il1, hi, lo);
        *(uint32_t*)(g_ah + base1 + 8 * n) = hi;
        *(uint32_t*)(g_al + base1 + 8 * n) = lo;
    }
}

// ---------------------------------------------------------------------------
extern "C" void kernel_launch(void* const* d_in, const int* in_sizes, int n_in,
                              void* d_out, int out_size)
{
    const float* x  = (const float*)d_in[0];   // [8,1024,768]
    const float* Wa = (const float*)d_in[1];   // [768,2304]
    const float* Wp = (const float*)d_in[2];   // [768,768]
    float* out = (float*)d_out;

    void *xh, *xl, *wah, *wph, *ah, *al;
    cudaGetSymbolAddress(&xh,  g_xh);  cudaGetSymbolAddress(&xl,  g_xl);
    cudaGetSymbolAddress(&wah, g_wah); cudaGetSymbolAddress(&wph, g_wph);
    cudaGetSymbolAddress(&ah,  g_ah);  cudaGetSymbolAddress(&al,  g_al);

    cudaFuncSetAttribute(flash_mma, cudaFuncAttributeMaxDynamicSharedMemorySize, FSMEM);

    // conversions: x -> fp16 hi/lo split; W -> transposed single fp16
    split_kernel_h<<<(MROWS * KDIM) / 1024, 256>>>(x, (__half*)xh, (__half*)xl, MROWS * KDIM);
    dim3 bt(32, 8);
    tconv_kernel<<<dim3(NQKV / 32, KDIM / 32), bt>>>(Wa, (__half*)wah, KDIM, NQKV);
    tconv_kernel<<<dim3(CE / 32, KDIM / 32), bt>>>(Wp, (__half*)wph, KDIM, CE);

    // 1) QKV GEMM (fp16 2-pass) -> split-bf16 q/k/v [B,H,T,D]
    gemm_mma<<<dim3(NQKV / 128, MROWS / 128), 256>>>(
        (__half*)xh, (__half*)xl, (__half*)wah, nullptr, 1);

    // 2) flash attention (bf16 3-pass) -> g_ah/g_al (split fp16, [B,T,C])
    flash_mma<<<dim3(SEQ / FBM, BATCH * NHEAD), 256, FSMEM>>>();

    // 3) output projection (fp16 2-pass) -> d_out
    gemm_mma<<<dim3(CE / 128, MROWS / 128), 256>>>(
        (__half*)ah, (__half*)al, (__half*)wph, out, 0);
}

// round 9
// speedup vs baseline: 1.6954x; 1.1533x over previous
#include <cuda_runtime.h>
#include <cuda_fp16.h>
#include <stdint.h>

#define CE     768
#define NHEAD  8
#define HD     96
#define BATCH  8
#define SEQ    1024
#define MROWS  (BATCH*SEQ)
#define KDIM   768
#define NQKV   (3*CE)
#define NC2    (KDIM/32)          // 24 chunks of K=32

// ------------------------------- scratch (allocation-free rule) -------------
__device__ __align__(16) __half g_xh[MROWS*KDIM];
__device__ __align__(16) __half g_xl[MROWS*KDIM];
__device__ __align__(16) __half g_wah[NQKV*KDIM];
__device__ __align__(16) __half g_wph[CE*KDIM];
__device__ __align__(16) __half g_ah[MROWS*KDIM];
__device__ __align__(16) __half g_al[MROWS*KDIM];
__device__ __align__(16) __half g_qh[BATCH*NHEAD*SEQ*HD];
__device__ __align__(16) __half g_ql[BATCH*NHEAD*SEQ*HD];
__device__ __align__(16) __half g_kv[2*BATCH*NHEAD*SEQ*HD];   // k then v

// ------------------------------- helpers ------------------------------------
__device__ __forceinline__ uint32_t smem_u32(const void* p) {
    uint32_t a;
    asm("{ .reg .u64 t; cvta.to.shared.u64 t, %1; cvt.u32.u64 %0, t; }" : "=r"(a) : "l"(p));
    return a;
}
__device__ __forceinline__ void ldmx4(uint32_t* r, uint32_t addr) {
    asm volatile("ldmatrix.sync.aligned.m8n8.x4.shared.b16 {%0,%1,%2,%3}, [%4];"
                 : "=r"(r[0]), "=r"(r[1]), "=r"(r[2]), "=r"(r[3]) : "r"(addr));
}
__device__ __forceinline__ void ldmx4t(uint32_t* r, uint32_t addr) {
    asm volatile("ldmatrix.sync.aligned.m8n8.x4.trans.shared.b16 {%0,%1,%2,%3}, [%4];"
                 : "=r"(r[0]), "=r"(r[1]), "=r"(r[2]), "=r"(r[3]) : "r"(addr));
}
__device__ __forceinline__ void mma16816h(float* c, const uint32_t* a, const uint32_t* b) {
    asm volatile(
        "mma.sync.aligned.m16n8k16.row.col.f32.f16.f16.f32 "
        "{%0,%1,%2,%3}, {%4,%5,%6,%7}, {%8,%9}, {%0,%1,%2,%3};"
        : "+f"(c[0]), "+f"(c[1]), "+f"(c[2]), "+f"(c[3])
        : "r"(a[0]), "r"(a[1]), "r"(a[2]), "r"(a[3]), "r"(b[0]), "r"(b[1]));
}
__device__ __forceinline__ void cp16(uint32_t saddr, const void* gptr) {
    asm volatile("cp.async.ca.shared.global [%0], [%1], 16;"
                 :: "r"(saddr), "l"(__cvta_generic_to_global(gptr)) : "memory");
}
#define CP_COMMIT() asm volatile("cp.async.commit_group;" ::: "memory")
#define CP_WAIT1()  asm volatile("cp.async.wait_group 1;" ::: "memory")

__device__ __forceinline__ void split2h(float x, float y, uint32_t& hi, uint32_t& lo) {
    __half2 h, l;
    h.x = __float2half(x);  h.y = __float2half(y);
    l.x = __float2half(x - __half2float(h.x));
    l.y = __float2half(y - __half2float(h.y));
    hi = *(uint32_t*)&h;  lo = *(uint32_t*)&l;
}
__device__ __forceinline__ uint32_t pack2h(float x, float y) {
    __half2 h; h.x = __float2half(x); h.y = __float2half(y);
    return *(uint32_t*)&h;
}

// ------------------------------- conversion kernels -------------------------
__global__ void split_kernel_h(const float* __restrict__ in,
                               __half* __restrict__ hi,
                               __half* __restrict__ lo, int n)
{
    int i = (blockIdx.x * 256 + threadIdx.x) * 4;
    if (i >= n) return;
    float4 v = *(const float4*)(in + i);
    uint32_t h0, l0, h1, l1;
    split2h(v.x, v.y, h0, l0);
    split2h(v.z, v.w, h1, l1);
    *(uint32_t*)(hi + i)     = h0;  *(uint32_t*)(hi + i + 2) = h1;
    *(uint32_t*)(lo + i)     = l0;  *(uint32_t*)(lo + i + 2) = l1;
}

// in: [K,N] fp32 row-major -> out: [N,K] fp16 (transposed)
__global__ void tconv_kernel(const float* __restrict__ in,
                             __half* __restrict__ outw, int K, int N)
{
    __shared__ float t[32][33];
    const int n0 = blockIdx.x * 32, k0 = blockIdx.y * 32;
#pragma unroll
    for (int i = 0; i < 4; i++) {
        int k = k0 + threadIdx.y + i * 8;
        t[threadIdx.y + i * 8][threadIdx.x] = in[(size_t)k * N + n0 + threadIdx.x];
    }
    __syncthreads();
#pragma unroll
    for (int i = 0; i < 4; i++) {
        int n = n0 + threadIdx.y + i * 8;
        float v = t[threadIdx.x][threadIdx.y + i * 8];
        outw[(size_t)n * K + k0 + threadIdx.x] = __float2half(v);
    }
}

// ------------------------------- HMMA GEMM (fp16, 2-pass, K-chunk 32) -------
// C[M,N] = (Ah+Al)[M,768] * B[N,768]^T, fp16 operands, fp32 accum.
// Block 128x128, 8 warps (4Mx2N), K-chunk 32 (2 sequential k16 substeps),
// double-buffered cp.async, 2 syncs per chunk (24 chunks).
// Stage 24KB: Ah@0(8K) Al@8192 B@16384(8K).
// addr(r, ch16) = (r>>3)<<9 | (r&7)<<4 | ch<<7, ch in 0..3.
__global__ __launch_bounds__(256, 2) void gemm_mma(
    const __half* __restrict__ Ah, const __half* __restrict__ Al,
    const __half* __restrict__ Bm,
    float* __restrict__ outp, int scatter)
{
    __shared__ __align__(128) uint8_t sm[2][24576];
    const int tid = threadIdx.x, lid = tid & 31, wid = tid >> 5;
    const int wm = wid & 3, wn = wid >> 2;
    const int mbase = blockIdx.y * 128, nbase = blockIdx.x * 128;
    const uint32_t sbase = smem_u32(sm);

    // loader: r = tid>>1, two 16B chunks chbase..chbase+1
    const int lr = tid >> 1, lcb = (tid & 1) * 2;

    const uint32_t aoff = ((lid & 7) << 4) | (((lid >> 3) & 1) << 9) | ((lid >> 4) << 7);
    const uint32_t boff = ((lid & 7) << 4) | (((lid >> 3) & 1) << 7) | ((lid >> 4) << 9);

    float acc[2][8][4];
#pragma unroll
    for (int mt = 0; mt < 2; mt++)
#pragma unroll
        for (int nt = 0; nt < 8; nt++)
#pragma unroll
            for (int u = 0; u < 4; u++) acc[mt][nt][u] = 0.f;

    auto load_chunk = [&](int c, int stg) {
        const uint32_t sb = sbase + stg * 24576;
        const int kt = c * 32;
#pragma unroll
        for (int i = 0; i < 2; i++) {
            int ch = lcb + i;
            uint32_t d = sb + ((lr >> 3) << 9) + ((lr & 7) << 4) + (ch << 7);
            size_t ga = (size_t)(mbase + lr) * KDIM + kt + ch * 8;
            size_t gbp = (size_t)(nbase + lr) * KDIM + kt + ch * 8;
            cp16(d,         Ah + ga);
            cp16(d + 8192,  Al + ga);
            cp16(d + 16384, Bm + gbp);
        }
    };

    load_chunk(0, 0); CP_COMMIT();

    for (int c = 0; c < NC2; c++) {
        if (c + 1 < NC2) load_chunk(c + 1, (c + 1) & 1);
        CP_COMMIT();
        CP_WAIT1();
        __syncthreads();

        const uint32_t base = sbase + (c & 1) * 24576;
        const uint32_t aAh = base + wm * 2048 + aoff;
        const uint32_t aAl = base + 8192 + wm * 2048 + aoff;
        const uint32_t bB  = base + 16384 + wn * 4096 + boff;

#pragma unroll
        for (int s = 0; s < 2; s++) {
            uint32_t ah[2][4], al[2][4], bf[4][4];
#pragma unroll
            for (int mt = 0; mt < 2; mt++) {
                ldmx4(ah[mt], aAh + s * 256 + mt * 1024);
                ldmx4(al[mt], aAl + s * 256 + mt * 1024);
            }
#pragma unroll
            for (int g = 0; g < 4; g++) ldmx4(bf[g], bB + s * 256 + g * 1024);

#pragma unroll
            for (int mt = 0; mt < 2; mt++)
#pragma unroll
                for (int g = 0; g < 4; g++) {
                    mma16816h(acc[mt][2*g],   ah[mt], &bf[g][0]);
                    mma16816h(acc[mt][2*g+1], ah[mt], &bf[g][2]);
                    mma16816h(acc[mt][2*g],   al[mt], &bf[g][0]);
                    mma16816h(acc[mt][2*g+1], al[mt], &bf[g][2]);
                }
        }
        __syncthreads();
    }

    const int rowb = mbase + wm * 32 + (lid >> 2);
    const int colb = nbase + wn * 64 + 2 * (lid & 3);
#pragma unroll
    for (int mt = 0; mt < 2; mt++)
#pragma unroll
        for (int nt = 0; nt < 8; nt++) {
            int col = colb + nt * 8;
#pragma unroll
            for (int h2 = 0; h2 < 2; h2++) {
                int row = rowb + mt * 16 + h2 * 8;
                float vx = acc[mt][nt][2*h2], vy = acc[mt][nt][2*h2+1];
                if (scatter) {
                    int which = col / CE, cc = col - which * CE;
                    int h = cc / HD, d = cc - h * HD;
                    int bb = row >> 10, tt = row & 1023;
                    size_t idx = (size_t)(((bb * NHEAD + h) * SEQ) + tt) * HD + d;
                    if (which == 0) {                 // q: split fp16
                        uint32_t hi, lo;
                        split2h(vx, vy, hi, lo);
                        *(uint32_t*)(g_qh + idx) = hi;
                        *(uint32_t*)(g_ql + idx) = lo;
                    } else {                          // k/v: single fp16
                        size_t off = (which == 1) ? 0 : (size_t)BATCH*NHEAD*SEQ*HD;
                        *(uint32_t*)(g_kv + off + idx) = pack2h(vx, vy);
                    }
                } else {
                    *(float2*)(outp + (size_t)row * CE + col) = make_float2(vx, vy);
                }
            }
        }
}

// ------------------------------- flash attention (fp16 2+2-pass) ------------
// Q split (Qh+Ql) x K single; P split (Ph+Pl) x V single. fp32 accum.
#define FBM    128
#define FBN    64
#define PITCHB 208
#define KVSTG  (2*FBN*PITCHB)               // K + V per stage
#define FSMEM  (2*FBM*PITCHB + 2*KVSTG)     // 53248 + 53248

__global__ __launch_bounds__(256, 1) void flash_mma()
{
    extern __shared__ uint8_t fs[];
    const int tid = threadIdx.x, lid = tid & 31, wid = tid >> 5;
    const int bh = blockIdx.y;
    const int qt = (int)gridDim.x - 1 - (int)blockIdx.x;   // heavy tiles first
    const int q0 = qt * FBM;
    const uint32_t sQh = smem_u32(fs);
    const uint32_t sKV = sQh + 2 * FBM * PITCHB;
    const size_t gb = (size_t)bh * SEQ * HD;
    const __half* Kg = g_kv;
    const __half* Vg = g_kv + (size_t)BATCH*NHEAD*SEQ*HD;
    const float scale = 0.10206207261596575f;

    const int rkv = tid >> 2, qq = tid & 3;

    // stage-0 KV
    {
        uint32_t sb = sKV + rkv * PITCHB + qq * 48;
        size_t go = gb + (size_t)rkv * HD + qq * 24;
#pragma unroll
        for (int k = 0; k < 3; k++) {
            cp16(sb + k*16,              Kg + go + k*8);
            cp16(sb + FBN*PITCHB + k*16, Vg + go + k*8);
        }
    }
    CP_COMMIT();
    // Q (resident)
    {
        int r = tid >> 1, hf = tid & 1;
        uint32_t sq = sQh + r * PITCHB + hf * 96;
        size_t gq = gb + (size_t)(q0 + r) * HD + hf * 48;
#pragma unroll
        for (int k = 0; k < 6; k++) {
            cp16(sq + k*16,              g_qh + gq + k*8);
            cp16(sq + FBM*PITCHB + k*16, g_ql + gq + k*8);
        }
    }
    CP_COMMIT();

    const uint32_t aoff = (lid & 7) * PITCHB + ((lid >> 3) & 1) * (8 * PITCHB) + (lid >> 4) * 16;
    const uint32_t boff = (lid & 7) * PITCHB + ((lid >> 3) & 1) * 16 + (lid >> 4) * (8 * PITCHB);

    uint32_t qfh[6][4], qfl[6][4];
    float oacc[12][4];
#pragma unroll
    for (int n = 0; n < 12; n++)
#pragma unroll
        for (int u = 0; u < 4; u++) oacc[n][u] = 0.f;
    float m0 = -1e30f, m1 = -1e30f, lsum0 = 0.f, lsum1 = 0.f;
    const int row0 = q0 + wid * 16 + (lid >> 2);

    const int nkt = 2 * qt + 2;
    for (int kt = 0; kt < nkt; kt++) {
        if (kt + 1 < nkt) {
            uint32_t sb = sKV + ((kt + 1) & 1) * KVSTG + rkv * PITCHB + qq * 48;
            size_t go = gb + (size_t)((kt + 1) * FBN + rkv) * HD + qq * 24;
#pragma unroll
            for (int k = 0; k < 3; k++) {
                cp16(sb + k*16,              Kg + go + k*8);
                cp16(sb + FBN*PITCHB + k*16, Vg + go + k*8);
            }
        }
        CP_COMMIT();
        CP_WAIT1();
        __syncthreads();

        if (kt == 0) {   // Q fragments once
            uint32_t aQ = sQh + wid * 16 * PITCHB + aoff;
#pragma unroll
            for (int kc = 0; kc < 6; kc++) {
                ldmx4(qfh[kc], aQ + kc * 32);
                ldmx4(qfl[kc], aQ + FBM * PITCHB + kc * 32);
            }
        }

        const uint32_t stg = sKV + (kt & 1) * KVSTG;

        // ---- S = (Qh+Ql) K^T
        float sacc[8][4];
#pragma unroll
        for (int n = 0; n < 8; n++)
#pragma unroll
            for (int u = 0; u < 4; u++) sacc[n][u] = 0.f;
#pragma unroll
        for (int kc = 0; kc < 6; kc++) {
#pragma unroll
            for (int g = 0; g < 4; g++) {
                uint32_t k4[4];
                ldmx4(k4, stg + boff + g * (16 * PITCHB) + kc * 32);
                mma16816h(sacc[2*g],   qfh[kc], &k4[0]);
                mma16816h(sacc[2*g+1], qfh[kc], &k4[2]);
                mma16816h(sacc[2*g],   qfl[kc], &k4[0]);
                mma16816h(sacc[2*g+1], qfl[kc], &k4[2]);
            }
        }

        // ---- online softmax
        const int colb = kt * FBN + 2 * (lid & 3);
        float ml0 = -1e30f, ml1 = -1e30f;
#pragma unroll
        for (int n = 0; n < 8; n++)
#pragma unroll
            for (int e = 0; e < 2; e++) {
                int col = colb + 8 * n + e;
                float v0 = sacc[n][e] * scale;     if (col > row0)     v0 = -1e30f;
                float v1 = sacc[n][2 + e] * scale; if (col > row0 + 8) v1 = -1e30f;
                sacc[n][e] = v0; sacc[n][2 + e] = v1;
                ml0 = fmaxf(ml0, v0); ml1 = fmaxf(ml1, v1);
            }
        ml0 = fmaxf(ml0, __shfl_xor_sync(0xffffffffu, ml0, 1));
        ml0 = fmaxf(ml0, __shfl_xor_sync(0xffffffffu, ml0, 2));
        ml1 = fmaxf(ml1, __shfl_xor_sync(0xffffffffu, ml1, 1));
        ml1 = fmaxf(ml1, __shfl_xor_sync(0xffffffffu, ml1, 2));
        float mn0 = fmaxf(m0, ml0), mn1 = fmaxf(m1, ml1);
        float al0 = __expf(m0 - mn0), al1 = __expf(m1 - mn1);
        float ps0 = 0.f, ps1 = 0.f;
#pragma unroll
        for (int n = 0; n < 8; n++) {
            sacc[n][0] = __expf(sacc[n][0] - mn0); ps0 += sacc[n][0];
            sacc[n][1] = __expf(sacc[n][1] - mn0); ps0 += sacc[n][1];
            sacc[n][2] = __expf(sacc[n][2] - mn1); ps1 += sacc[n][2];
            sacc[n][3] = __expf(sacc[n][3] - mn1); ps1 += sacc[n][3];
        }
        ps0 += __shfl_xor_sync(0xffffffffu, ps0, 1);
        ps0 += __shfl_xor_sync(0xffffffffu, ps0, 2);
        ps1 += __shfl_xor_sync(0xffffffffu, ps1, 1);
        ps1 += __shfl_xor_sync(0xffffffffu, ps1, 2);
        lsum0 = lsum0 * al0 + ps0; m0 = mn0;
        lsum1 = lsum1 * al1 + ps1; m1 = mn1;
#pragma unroll
        for (int n = 0; n < 12; n++) {
            oacc[n][0] *= al0; oacc[n][1] *= al0;
            oacc[n][2] *= al1; oacc[n][3] *= al1;
        }

        // ---- O += (Ph+Pl) V
        const uint32_t vB = stg + FBN * PITCHB + aoff;
#pragma unroll
        for (int kc2 = 0; kc2 < 4; kc2++) {
            uint32_t pah[4], pal[4];
            split2h(sacc[2*kc2][0],   sacc[2*kc2][1],   pah[0], pal[0]);
            split2h(sacc[2*kc2][2],   sacc[2*kc2][3],   pah[1], pal[1]);
            split2h(sacc[2*kc2+1][0], sacc[2*kc2+1][1], pah[2], pal[2]);
            split2h(sacc[2*kc2+1][2], sacc[2*kc2+1][3], pah[3], pal[3]);
            uint32_t vb = vB + kc2 * (16 * PITCHB);
#pragma unroll
            for (int dn = 0; dn < 6; dn++) {
                uint32_t v4[4];
                ldmx4t(v4, vb + dn * 32);
                mma16816h(oacc[2*dn],   pah, &v4[0]);
                mma16816h(oacc[2*dn+1], pah, &v4[2]);
                mma16816h(oacc[2*dn],   pal, &v4[0]);
                mma16816h(oacc[2*dn+1], pal, &v4[2]);
            }
        }
        __syncthreads();
    }

    // epilogue: O/l -> split-fp16 [B,T,C] for the projection GEMM
    const int b_ = bh >> 3, h_ = bh & 7;
    const float il0 = 1.f / lsum0, il1 = 1.f / lsum1;
    const size_t base0 = (size_t)(b_ * SEQ + row0) * CE + h_ * HD + 2 * (lid & 3);
    const size_t base1 = base0 + (size_t)8 * CE;
#pragma unroll
    for (int n = 0; n < 12; n++) {
        uint32_t hi, lo;
        split2h(oacc[n][0] * il0, oacc[n][1] * il0, hi, lo);
        *(uint32_t*)(g_ah + base0 + 8 * n) = hi;
        *(uint32_t*)(g_al + base0 + 8 * n) = lo;
        split2h(oacc[n][2] * il1, oacc[n][3] * il1, hi, lo);
        *(uint32_t*)(g_ah + base1 + 8 * n) = hi;
        *(uint32_t*)(g_al + base1 + 8 * n) = lo;
    }
}

// ---------------------------------------------------------------------------
extern "C" void kernel_launch(void* const* d_in, const int* in_sizes, int n_in,
                              void* d_out, int out_size)
{
    const float* x  = (const float*)d_in[0];   // [8,1024,768]
    const float* Wa = (const float*)d_in[1];   // [768,2304]
    const float* Wp = (const float*)d_in[2];   // [768,768]
    float* out = (float*)d_out;

    void *xh, *xl, *wah, *wph, *ah, *al;
    cudaGetSymbolAddress(&xh,  g_xh);  cudaGetSymbolAddress(&xl,  g_xl);
    cudaGetSymbolAddress(&wah, g_wah); cudaGetSymbolAddress(&wph, g_wph);
    cudaGetSymbolAddress(&ah,  g_ah);  cudaGetSymbolAddress(&al,  g_al);

    cudaFuncSetAttribute(flash_mma, cudaFuncAttributeMaxDynamicSharedMemorySize, FSMEM);

    // conversions
    split_kernel_h<<<(MROWS * KDIM) / 1024, 256>>>(x, (__half*)xh, (__half*)xl, MROWS * KDIM);
    dim3 bt(32, 8);
    tconv_kernel<<<dim3(NQKV / 32, KDIM / 32), bt>>>(Wa, (__half*)wah, KDIM, NQKV);
    tconv_kernel<<<dim3(CE / 32, KDIM / 32), bt>>>(Wp, (__half*)wph, KDIM, CE);

    // 1) QKV GEMM -> q split fp16, k/v single fp16, [B,H,T,D]
    gemm_mma<<<dim3(NQKV / 128, MROWS / 128), 256>>>(
        (__half*)xh, (__half*)xl, (__half*)wah, nullptr, 1);

    // 2) flash attention (fp16 2+2-pass) -> g_ah/g_al (split fp16, [B,T,C])
    flash_mma<<<dim3(SEQ / FBM, BATCH * NHEAD), 256, FSMEM>>>();

    // 3) output projection -> d_out
    gemm_mma<<<dim3(CE / 128, MROWS / 128), 256>>>(
        (__half*)ah, (__half*)al, (__half*)wph, out, 0);
}

// round 12
// speedup vs baseline: 1.8590x; 1.0965x over previous
#include <cuda_runtime.h>
#include <cuda_fp16.h>
#include <stdint.h>

#define CE     768
#define NHEAD  8
#define HD     96
#define BATCH  8
#define SEQ    1024
#define MROWS  (BATCH*SEQ)
#define KDIM   768
#define NQKV   (3*CE)
#define NC2    (KDIM/32)          // 24 chunks of K=32

// ------------------------------- scratch (allocation-free rule) -------------
__device__ __align__(16) __half g_xh[MROWS*KDIM];
__device__ __align__(16) __half g_xl[MROWS*KDIM];
__device__ __align__(16) __half g_wah[NQKV*KDIM];
__device__ __align__(16) __half g_wph[CE*KDIM];
__device__ __align__(16) __half g_ah[MROWS*KDIM];
__device__ __align__(16) __half g_al[MROWS*KDIM];
__device__ __align__(16) __half g_qh[BATCH*NHEAD*SEQ*HD];
__device__ __align__(16) __half g_ql[BATCH*NHEAD*SEQ*HD];
__device__ __align__(16) __half g_kv[2*BATCH*NHEAD*SEQ*HD];   // k then v

// ------------------------------- helpers ------------------------------------
__device__ __forceinline__ uint32_t smem_u32(const void* p) {
    uint32_t a;
    asm("{ .reg .u64 t; cvta.to.shared.u64 t, %1; cvt.u32.u64 %0, t; }" : "=r"(a) : "l"(p));
    return a;
}
__device__ __forceinline__ void ldmx4(uint32_t* r, uint32_t addr) {
    asm volatile("ldmatrix.sync.aligned.m8n8.x4.shared.b16 {%0,%1,%2,%3}, [%4];"
                 : "=r"(r[0]), "=r"(r[1]), "=r"(r[2]), "=r"(r[3]) : "r"(addr));
}
__device__ __forceinline__ void ldmx4t(uint32_t* r, uint32_t addr) {
    asm volatile("ldmatrix.sync.aligned.m8n8.x4.trans.shared.b16 {%0,%1,%2,%3}, [%4];"
                 : "=r"(r[0]), "=r"(r[1]), "=r"(r[2]), "=r"(r[3]) : "r"(addr));
}
__device__ __forceinline__ void mma16816h(float* c, const uint32_t* a, const uint32_t* b) {
    asm volatile(
        "mma.sync.aligned.m16n8k16.row.col.f32.f16.f16.f32 "
        "{%0,%1,%2,%3}, {%4,%5,%6,%7}, {%8,%9}, {%0,%1,%2,%3};"
        : "+f"(c[0]), "+f"(c[1]), "+f"(c[2]), "+f"(c[3])
        : "r"(a[0]), "r"(a[1]), "r"(a[2]), "r"(a[3]), "r"(b[0]), "r"(b[1]));
}
__device__ __forceinline__ void cp16(uint32_t saddr, const void* gptr) {
    asm volatile("cp.async.ca.shared.global [%0], [%1], 16;"
                 :: "r"(saddr), "l"(__cvta_generic_to_global(gptr)) : "memory");
}
#define CP_COMMIT() asm volatile("cp.async.commit_group;" ::: "memory")
#define CP_WAIT1()  asm volatile("cp.async.wait_group 1;" ::: "memory")

__device__ __forceinline__ void split2h(float x, float y, uint32_t& hi, uint32_t& lo) {
    __half2 h, l;
    h.x = __float2half(x);  h.y = __float2half(y);
    l.x = __float2half(x - __half2float(h.x));
    l.y = __float2half(y - __half2float(h.y));
    hi = *(uint32_t*)&h;  lo = *(uint32_t*)&l;
}
__device__ __forceinline__ uint32_t pack2h(float x, float y) {
    __half2 h; h.x = __float2half(x); h.y = __float2half(y);
    return *(uint32_t*)&h;
}

// ------------------------------- conversion kernels -------------------------
__global__ void split_kernel_h(const float* __restrict__ in,
                               __half* __restrict__ hi,
                               __half* __restrict__ lo, int n)
{
    int i = (blockIdx.x * 256 + threadIdx.x) * 4;
    if (i >= n) return;
    float4 v = *(const float4*)(in + i);
    uint32_t h0, l0, h1, l1;
    split2h(v.x, v.y, h0, l0);
    split2h(v.z, v.w, h1, l1);
    *(uint32_t*)(hi + i)     = h0;  *(uint32_t*)(hi + i + 2) = h1;
    *(uint32_t*)(lo + i)     = l0;  *(uint32_t*)(lo + i + 2) = l1;
}

// in: [K,N] fp32 row-major -> out: [N,K] fp16 (transposed)
__global__ void tconv_kernel(const float* __restrict__ in,
                             __half* __restrict__ outw, int K, int N)
{
    __shared__ float t[32][33];
    const int n0 = blockIdx.x * 32, k0 = blockIdx.y * 32;
#pragma unroll
    for (int i = 0; i < 4; i++) {
        int k = k0 + threadIdx.y + i * 8;
        t[threadIdx.y + i * 8][threadIdx.x] = in[(size_t)k * N + n0 + threadIdx.x];
    }
    __syncthreads();
#pragma unroll
    for (int i = 0; i < 4; i++) {
        int n = n0 + threadIdx.y + i * 8;
        float v = t[threadIdx.x][threadIdx.y + i * 8];
        outw[(size_t)n * K + k0 + threadIdx.x] = __float2half(v);
    }
}

// ------------------------------- HMMA GEMM (fp16, mixed-pass) ---------------
// C[M,N] = (Ah[+Al])[M,768] * B[N,768]^T, fp16 operands, fp32 accum.
// N-tiles with blockIdx.x < q2tiles run 2-pass (A split exact); the rest run
// 1-pass (Ah only) — used for K/V outputs whose store rounds to fp16 anyway.
// Block 128x128, 8 warps (4Mx2N), K-chunk 32, double-buffered cp.async.
__global__ __launch_bounds__(256, 2) void gemm_mma(
    const __half* __restrict__ Ah, const __half* __restrict__ Al,
    const __half* __restrict__ Bm,
    float* __restrict__ outp, int scatter, int q2tiles)
{
    __shared__ __align__(128) uint8_t sm[2][24576];
    const int tid = threadIdx.x, lid = tid & 31, wid = tid >> 5;
    const int wm = wid & 3, wn = wid >> 2;
    const int mbase = blockIdx.y * 128, nbase = blockIdx.x * 128;
    const int npass = ((int)blockIdx.x < q2tiles) ? 2 : 1;
    const uint32_t sbase = smem_u32(sm);

    const int lr = tid >> 1, lcb = (tid & 1) * 2;

    const uint32_t aoff = ((lid & 7) << 4) | (((lid >> 3) & 1) << 9) | ((lid >> 4) << 7);
    const uint32_t boff = ((lid & 7) << 4) | (((lid >> 3) & 1) << 7) | ((lid >> 4) << 9);

    float acc[2][8][4];
#pragma unroll
    for (int mt = 0; mt < 2; mt++)
#pragma unroll
        for (int nt = 0; nt < 8; nt++)
#pragma unroll
            for (int u = 0; u < 4; u++) acc[mt][nt][u] = 0.f;

    auto load_chunk = [&](int c, int stg) {
        const uint32_t sb = sbase + stg * 24576;
        const int kt = c * 32;
#pragma unroll
        for (int i = 0; i < 2; i++) {
            int ch = lcb + i;
            uint32_t d = sb + ((lr >> 3) << 9) + ((lr & 7) << 4) + (ch << 7);
            size_t ga = (size_t)(mbase + lr) * KDIM + kt + ch * 8;
            size_t gbp = (size_t)(nbase + lr) * KDIM + kt + ch * 8;
            cp16(d,         Ah + ga);
            if (npass == 2) cp16(d + 8192, Al + ga);
            cp16(d + 16384, Bm + gbp);
        }
    };

    load_chunk(0, 0); CP_COMMIT();

    for (int c = 0; c < NC2; c++) {
        if (c + 1 < NC2) load_chunk(c + 1, (c + 1) & 1);
        CP_COMMIT();
        CP_WAIT1();
        __syncthreads();

        const uint32_t base = sbase + (c & 1) * 24576;
        const uint32_t aAh = base + wm * 2048 + aoff;
        const uint32_t aAl = base + 8192 + wm * 2048 + aoff;
        const uint32_t bB  = base + 16384 + wn * 4096 + boff;

#pragma unroll
        for (int s = 0; s < 2; s++) {
            uint32_t ah[2][4], bf[4][4];
#pragma unroll
            for (int mt = 0; mt < 2; mt++) ldmx4(ah[mt], aAh + s * 256 + mt * 1024);
#pragma unroll
            for (int g = 0; g < 4; g++) ldmx4(bf[g], bB + s * 256 + g * 1024);

#pragma unroll
            for (int mt = 0; mt < 2; mt++)
#pragma unroll
                for (int g = 0; g < 4; g++) {
                    mma16816h(acc[mt][2*g],   ah[mt], &bf[g][0]);
                    mma16816h(acc[mt][2*g+1], ah[mt], &bf[g][2]);
                }
            if (npass == 2) {
                uint32_t al[2][4];
#pragma unroll
                for (int mt = 0; mt < 2; mt++) ldmx4(al[mt], aAl + s * 256 + mt * 1024);
#pragma unroll
                for (int mt = 0; mt < 2; mt++)
#pragma unroll
                    for (int g = 0; g < 4; g++) {
                        mma16816h(acc[mt][2*g],   al[mt], &bf[g][0]);
                        mma16816h(acc[mt][2*g+1], al[mt], &bf[g][2]);
                    }
            }
        }
        __syncthreads();
    }

    const int rowb = mbase + wm * 32 + (lid >> 2);
    const int colb = nbase + wn * 64 + 2 * (lid & 3);
#pragma unroll
    for (int mt = 0; mt < 2; mt++)
#pragma unroll
        for (int nt = 0; nt < 8; nt++) {
            int col = colb + nt * 8;
#pragma unroll
            for (int h2 = 0; h2 < 2; h2++) {
                int row = rowb + mt * 16 + h2 * 8;
                float vx = acc[mt][nt][2*h2], vy = acc[mt][nt][2*h2+1];
                if (scatter) {
                    int which = col / CE, cc = col - which * CE;
                    int h = cc / HD, d = cc - h * HD;
                    int bb = row >> 10, tt = row & 1023;
                    size_t idx = (size_t)(((bb * NHEAD + h) * SEQ) + tt) * HD + d;
                    if (which == 0) {                 // q: split fp16
                        uint32_t hi, lo;
                        split2h(vx, vy, hi, lo);
                        *(uint32_t*)(g_qh + idx) = hi;
                        *(uint32_t*)(g_ql + idx) = lo;
                    } else {                          // k/v: single fp16
                        size_t off = (which == 1) ? 0 : (size_t)BATCH*NHEAD*SEQ*HD;
                        *(uint32_t*)(g_kv + off + idx) = pack2h(vx, vy);
                    }
                } else {
                    *(float2*)(outp + (size_t)row * CE + col) = make_float2(vx, vy);
                }
            }
        }
}

// ------------------------------- flash attention (fp16) ---------------------
// QK: (Qh+Ql) x K (2-pass).  PV: Ph x V (1-pass; P in [0,1], fp16 exact-ish).
#define FBM    128
#define FBN    64
#define PITCHB 208
#define KVSTG  (2*FBN*PITCHB)               // K + V per stage
#define FSMEM  (2*FBM*PITCHB + 2*KVSTG)

__global__ __launch_bounds__(256, 1) void flash_mma()
{
    extern __shared__ uint8_t fs[];
    const int tid = threadIdx.x, lid = tid & 31, wid = tid >> 5;
    const int bh = blockIdx.y;
    const int qt = (int)gridDim.x - 1 - (int)blockIdx.x;   // heavy tiles first
    const int q0 = qt * FBM;
    const uint32_t sQh = smem_u32(fs);
    const uint32_t sKV = sQh + 2 * FBM * PITCHB;
    const size_t gb = (size_t)bh * SEQ * HD;
    const __half* Kg = g_kv;
    const __half* Vg = g_kv + (size_t)BATCH*NHEAD*SEQ*HD;
    const float scale = 0.10206207261596575f;

    const int rkv = tid >> 2, qq = tid & 3;

    {
        uint32_t sb = sKV + rkv * PITCHB + qq * 48;
        size_t go = gb + (size_t)rkv * HD + qq * 24;
#pragma unroll
        for (int k = 0; k < 3; k++) {
            cp16(sb + k*16,              Kg + go + k*8);
            cp16(sb + FBN*PITCHB + k*16, Vg + go + k*8);
        }
    }
    CP_COMMIT();
    {
        int r = tid >> 1, hf = tid & 1;
        uint32_t sq = sQh + r * PITCHB + hf * 96;
        size_t gq = gb + (size_t)(q0 + r) * HD + hf * 48;
#pragma unroll
        for (int k = 0; k < 6; k++) {
            cp16(sq + k*16,              g_qh + gq + k*8);
            cp16(sq + FBM*PITCHB + k*16, g_ql + gq + k*8);
        }
    }
    CP_COMMIT();

    const uint32_t aoff = (lid & 7) * PITCHB + ((lid >> 3) & 1) * (8 * PITCHB) + (lid >> 4) * 16;
    const uint32_t boff = (lid & 7) * PITCHB + ((lid >> 3) & 1) * 16 + (lid >> 4) * (8 * PITCHB);

    uint32_t qfh[6][4], qfl[6][4];
    float oacc[12][4];
#pragma unroll
    for (int n = 0; n < 12; n++)
#pragma unroll
        for (int u = 0; u < 4; u++) oacc[n][u] = 0.f;
    float m0 = -1e30f, m1 = -1e30f, lsum0 = 0.f, lsum1 = 0.f;
    const int row0 = q0 + wid * 16 + (lid >> 2);

    const int nkt = 2 * qt + 2;
    for (int kt = 0; kt < nkt; kt++) {
        if (kt + 1 < nkt) {
            uint32_t sb = sKV + ((kt + 1) & 1) * KVSTG + rkv * PITCHB + qq * 48;
            size_t go = gb + (size_t)((kt + 1) * FBN + rkv) * HD + qq * 24;
#pragma unroll
            for (int k = 0; k < 3; k++) {
                cp16(sb + k*16,              Kg + go + k*8);
                cp16(sb + FBN*PITCHB + k*16, Vg + go + k*8);
            }
        }
        CP_COMMIT();
        CP_WAIT1();
        __syncthreads();

        if (kt == 0) {
            uint32_t aQ = sQh + wid * 16 * PITCHB + aoff;
#pragma unroll
            for (int kc = 0; kc < 6; kc++) {
                ldmx4(qfh[kc], aQ + kc * 32);
                ldmx4(qfl[kc], aQ + FBM * PITCHB + kc * 32);
            }
        }

        const uint32_t stg = sKV + (kt & 1) * KVSTG;

        // ---- S = (Qh+Ql) K^T
        float sacc[8][4];
#pragma unroll
        for (int n = 0; n < 8; n++)
#pragma unroll
            for (int u = 0; u < 4; u++) sacc[n][u] = 0.f;
#pragma unroll
        for (int kc = 0; kc < 6; kc++) {
#pragma unroll
            for (int g = 0; g < 4; g++) {
                uint32_t k4[4];
                ldmx4(k4, stg + boff + g * (16 * PITCHB) + kc * 32);
                mma16816h(sacc[2*g],   qfh[kc], &k4[0]);
                mma16816h(sacc[2*g+1], qfh[kc], &k4[2]);
                mma16816h(sacc[2*g],   qfl[kc], &k4[0]);
                mma16816h(sacc[2*g+1], qfl[kc], &k4[2]);
            }
        }

        // ---- online softmax
        const int colb = kt * FBN + 2 * (lid & 3);
        float ml0 = -1e30f, ml1 = -1e30f;
#pragma unroll
        for (int n = 0; n < 8; n++)
#pragma unroll
            for (int e = 0; e < 2; e++) {
                int col = colb + 8 * n + e;
                float v0 = sacc[n][e] * scale;     if (col > row0)     v0 = -1e30f;
                float v1 = sacc[n][2 + e] * scale; if (col > row0 + 8) v1 = -1e30f;
                sacc[n][e] = v0; sacc[n][2 + e] = v1;
                ml0 = fmaxf(ml0, v0); ml1 = fmaxf(ml1, v1);
            }
        ml0 = fmaxf(ml0, __shfl_xor_sync(0xffffffffu, ml0, 1));
        ml0 = fmaxf(ml0, __shfl_xor_sync(0xffffffffu, ml0, 2));
        ml1 = fmaxf(ml1, __shfl_xor_sync(0xffffffffu, ml1, 1));
        ml1 = fmaxf(ml1, __shfl_xor_sync(0xffffffffu, ml1, 2));
        float mn0 = fmaxf(m0, ml0), mn1 = fmaxf(m1, ml1);
        float al0 = __expf(m0 - mn0), al1 = __expf(m1 - mn1);
        float ps0 = 0.f, ps1 = 0.f;
#pragma unroll
        for (int n = 0; n < 8; n++) {
            sacc[n][0] = __expf(sacc[n][0] - mn0); ps0 += sacc[n][0];
            sacc[n][1] = __expf(sacc[n][1] - mn0); ps0 += sacc[n][1];
            sacc[n][2] = __expf(sacc[n][2] - mn1); ps1 += sacc[n][2];
            sacc[n][3] = __expf(sacc[n][3] - mn1); ps1 += sacc[n][3];
        }
        ps0 += __shfl_xor_sync(0xffffffffu, ps0, 1);
        ps0 += __shfl_xor_sync(0xffffffffu, ps0, 2);
        ps1 += __shfl_xor_sync(0xffffffffu, ps1, 1);
        ps1 += __shfl_xor_sync(0xffffffffu, ps1, 2);
        lsum0 = lsum0 * al0 + ps0; m0 = mn0;
        lsum1 = lsum1 * al1 + ps1; m1 = mn1;
#pragma unroll
        for (int n = 0; n < 12; n++) {
            oacc[n][0] *= al0; oacc[n][1] *= al0;
            oacc[n][2] *= al1; oacc[n][3] *= al1;
        }

        // ---- O += Ph V  (single pass)
        const uint32_t vB = stg + FBN * PITCHB + aoff;
#pragma unroll
        for (int kc2 = 0; kc2 < 4; kc2++) {
            uint32_t pah[4];
            pah[0] = pack2h(sacc[2*kc2][0],   sacc[2*kc2][1]);
            pah[1] = pack2h(sacc[2*kc2][2],   sacc[2*kc2][3]);
            pah[2] = pack2h(sacc[2*kc2+1][0], sacc[2*kc2+1][1]);
            pah[3] = pack2h(sacc[2*kc2+1][2], sacc[2*kc2+1][3]);
            uint32_t vb = vB + kc2 * (16 * PITCHB);
#pragma unroll
            for (int dn = 0; dn < 6; dn++) {
                uint32_t v4[4];
                ldmx4t(v4, vb + dn * 32);
                mma16816h(oacc[2*dn],   pah, &v4[0]);
                mma16816h(oacc[2*dn+1], pah, &v4[2]);
            }
        }
        __syncthreads();
    }

    // epilogue: O/l -> split-fp16 [B,T,C] for the projection GEMM
    const int b_ = bh >> 3, h_ = bh & 7;
    const float il0 = 1.f / lsum0, il1 = 1.f / lsum1;
    const size_t base0 = (size_t)(b_ * SEQ + row0) * CE + h_ * HD + 2 * (lid & 3);
    const size_t base1 = base0 + (size_t)8 * CE;
#pragma unroll
    for (int n = 0; n < 12; n++) {
        uint32_t hi, lo;
        split2h(oacc[n][0] * il0, oacc[n][1] * il0, hi, lo);
        *(uint32_t*)(g_ah + base0 + 8 * n) = hi;
        *(uint32_t*)(g_al + base0 + 8 * n) = lo;
        split2h(oacc[n][2] * il1, oacc[n][3] * il1, hi, lo);
        *(uint32_t*)(g_ah + base1 + 8 * n) = hi;
        *(uint32_t*)(g_al + base1 + 8 * n) = lo;
    }
}

// ---------------------------------------------------------------------------
extern "C" void kernel_launch(void* const* d_in, const int* in_sizes, int n_in,
                              void* d_out, int out_size)
{
    const float* x  = (const float*)d_in[0];   // [8,1024,768]
    const float* Wa = (const float*)d_in[1];   // [768,2304]
    const float* Wp = (const float*)d_in[2];   // [768,768]
    float* out = (float*)d_out;

    void *xh, *xl, *wah, *wph, *ah, *al;
    cudaGetSymbolAddress(&xh,  g_xh);  cudaGetSymbolAddress(&xl,  g_xl);
    cudaGetSymbolAddress(&wah, g_wah); cudaGetSymbolAddress(&wph, g_wph);
    cudaGetSymbolAddress(&ah,  g_ah);  cudaGetSymbolAddress(&al,  g_al);

    cudaFuncSetAttribute(flash_mma, cudaFuncAttributeMaxDynamicSharedMemorySize, FSMEM);

    // conversions
    split_kernel_h<<<(MROWS * KDIM) / 1024, 256>>>(x, (__half*)xh, (__half*)xl, MROWS * KDIM);
    dim3 bt(32, 8);
    tconv_kernel<<<dim3(NQKV / 32, KDIM / 32), bt>>>(Wa, (__half*)wah, KDIM, NQKV);
    tconv_kernel<<<dim3(CE / 32, KDIM / 32), bt>>>(Wp, (__half*)wph, KDIM, CE);

    // 1) QKV GEMM: Q tiles (x<6) 2-pass, K/V tiles 1-pass -> [B,H,T,D]
    gemm_mma<<<dim3(NQKV / 128, MROWS / 128), 256>>>(
        (__half*)xh, (__half*)xl, (__half*)wah, nullptr, 1, 6);

    // 2) flash attention (QK 2-pass, PV 1-pass) -> g_ah/g_al (split fp16)
    flash_mma<<<dim3(SEQ / FBM, BATCH * NHEAD), 256, FSMEM>>>();

    // 3) output projection (2-pass, A = attention out split) -> d_out
    gemm_mma<<<dim3(CE / 128, MROWS / 128), 256>>>(
        (__half*)ah, (__half*)al, (__half*)wph, out, 0, 6);
}

// round 13
// speedup vs baseline: 2.2573x; 1.2143x over previous
#include <cuda_runtime.h>
#include <cuda_fp16.h>
#include <stdint.h>

#define CE     768
#define NHEAD  8
#define HD     96
#define BATCH  8
#define SEQ    1024
#define MROWS  (BATCH*SEQ)
#define KDIM   768
#define NQKV   (3*CE)
#define NC2    (KDIM/32)          // 24 chunks of K=32

// ------------------------------- scratch (allocation-free rule) -------------
__device__ __align__(16) __half g_xh[MROWS*KDIM];
__device__ __align__(16) __half g_wah[NQKV*KDIM];
__device__ __align__(16) __half g_wph[CE*KDIM];
__device__ __align__(16) __half g_ah[MROWS*KDIM];
__device__ __align__(16) __half g_qh[BATCH*NHEAD*SEQ*HD];
__device__ __align__(16) __half g_ql[BATCH*NHEAD*SEQ*HD];
__device__ __align__(16) __half g_kv[2*BATCH*NHEAD*SEQ*HD];   // k then v

// ------------------------------- helpers ------------------------------------
__device__ __forceinline__ uint32_t smem_u32(const void* p) {
    uint32_t a;
    asm("{ .reg .u64 t; cvta.to.shared.u64 t, %1; cvt.u32.u64 %0, t; }" : "=r"(a) : "l"(p));
    return a;
}
__device__ __forceinline__ void ldmx4(uint32_t* r, uint32_t addr) {
    asm volatile("ldmatrix.sync.aligned.m8n8.x4.shared.b16 {%0,%1,%2,%3}, [%4];"
                 : "=r"(r[0]), "=r"(r[1]), "=r"(r[2]), "=r"(r[3]) : "r"(addr));
}
__device__ __forceinline__ void ldmx4t(uint32_t* r, uint32_t addr) {
    asm volatile("ldmatrix.sync.aligned.m8n8.x4.trans.shared.b16 {%0,%1,%2,%3}, [%4];"
                 : "=r"(r[0]), "=r"(r[1]), "=r"(r[2]), "=r"(r[3]) : "r"(addr));
}
__device__ __forceinline__ void mma16816h(float* c, const uint32_t* a, const uint32_t* b) {
    asm volatile(
        "mma.sync.aligned.m16n8k16.row.col.f32.f16.f16.f32 "
        "{%0,%1,%2,%3}, {%4,%5,%6,%7}, {%8,%9}, {%0,%1,%2,%3};"
        : "+f"(c[0]), "+f"(c[1]), "+f"(c[2]), "+f"(c[3])
        : "r"(a[0]), "r"(a[1]), "r"(a[2]), "r"(a[3]), "r"(b[0]), "r"(b[1]));
}
__device__ __forceinline__ void cp16(uint32_t saddr, const void* gptr) {
    asm volatile("cp.async.ca.shared.global [%0], [%1], 16;"
                 :: "r"(saddr), "l"(__cvta_generic_to_global(gptr)) : "memory");
}
#define CP_COMMIT() asm volatile("cp.async.commit_group;" ::: "memory")
#define CP_WAIT1()  asm volatile("cp.async.wait_group 1;" ::: "memory")

__device__ __forceinline__ void split2h(float x, float y, uint32_t& hi, uint32_t& lo) {
    __half2 h, l;
    h.x = __float2half(x);  h.y = __float2half(y);
    l.x = __float2half(x - __half2float(h.x));
    l.y = __float2half(y - __half2float(h.y));
    hi = *(uint32_t*)&h;  lo = *(uint32_t*)&l;
}
__device__ __forceinline__ uint32_t pack2h(float x, float y) {
    __half2 h; h.x = __float2half(x); h.y = __float2half(y);
    return *(uint32_t*)&h;
}

// ------------------------------- conversion kernels -------------------------
__global__ void conv_kernel_h(const float* __restrict__ in,
                              __half* __restrict__ outh, int n)
{
    int i = (blockIdx.x * 256 + threadIdx.x) * 4;
    if (i >= n) return;
    float4 v = *(const float4*)(in + i);
    uint2 o;
    o.x = pack2h(v.x, v.y);
    o.y = pack2h(v.z, v.w);
    *(uint2*)(outh + i) = o;
}

// in: [K,N] fp32 row-major -> out: [N,K] fp16 (transposed)
__global__ void tconv_kernel(const float* __restrict__ in,
                             __half* __restrict__ outw, int K, int N)
{
    __shared__ float t[32][33];
    const int n0 = blockIdx.x * 32, k0 = blockIdx.y * 32;
#pragma unroll
    for (int i = 0; i < 4; i++) {
        int k = k0 + threadIdx.y + i * 8;
        t[threadIdx.y + i * 8][threadIdx.x] = in[(size_t)k * N + n0 + threadIdx.x];
    }
    __syncthreads();
#pragma unroll
    for (int i = 0; i < 4; i++) {
        int n = n0 + threadIdx.y + i * 8;
        float v = t[threadIdx.x][threadIdx.y + i * 8];
        outw[(size_t)n * K + k0 + threadIdx.x] = __float2half(v);
    }
}

// ------------------------------- HMMA GEMM (fp16, 1-pass) -------------------
// C[M,N] = A[M,768] * B[N,768]^T, fp16 operands, fp32 accum.
// Block 128x128, 8 warps (4Mx2N), K-chunk 32, double-buffered cp.async.
// Stage 16KB: A@0(8K) B@8192(8K). addr(r,ch16) = (r>>3)<<9 | (r&7)<<4 | ch<<7.
__global__ __launch_bounds__(256, 2) void gemm_mma(
    const __half* __restrict__ Ah, const __half* __restrict__ Bm,
    float* __restrict__ outp, int scatter)
{
    __shared__ __align__(128) uint8_t sm[2][16384];
    const int tid = threadIdx.x, lid = tid & 31, wid = tid >> 5;
    const int wm = wid & 3, wn = wid >> 2;
    const int mbase = blockIdx.y * 128, nbase = blockIdx.x * 128;
    const uint32_t sbase = smem_u32(sm);

    const int lr = tid >> 1, lcb = (tid & 1) * 2;

    const uint32_t aoff = ((lid & 7) << 4) | (((lid >> 3) & 1) << 9) | ((lid >> 4) << 7);
    const uint32_t boff = ((lid & 7) << 4) | (((lid >> 3) & 1) << 7) | ((lid >> 4) << 9);

    float acc[2][8][4];
#pragma unroll
    for (int mt = 0; mt < 2; mt++)
#pragma unroll
        for (int nt = 0; nt < 8; nt++)
#pragma unroll
            for (int u = 0; u < 4; u++) acc[mt][nt][u] = 0.f;

    auto load_chunk = [&](int c, int stg) {
        const uint32_t sb = sbase + stg * 16384;
        const int kt = c * 32;
#pragma unroll
        for (int i = 0; i < 2; i++) {
            int ch = lcb + i;
            uint32_t d = sb + ((lr >> 3) << 9) + ((lr & 7) << 4) + (ch << 7);
            size_t ga  = (size_t)(mbase + lr) * KDIM + kt + ch * 8;
            size_t gbp = (size_t)(nbase + lr) * KDIM + kt + ch * 8;
            cp16(d,        Ah + ga);
            cp16(d + 8192, Bm + gbp);
        }
    };

    load_chunk(0, 0); CP_COMMIT();

    for (int c = 0; c < NC2; c++) {
        if (c + 1 < NC2) load_chunk(c + 1, (c + 1) & 1);
        CP_COMMIT();
        CP_WAIT1();
        __syncthreads();

        const uint32_t base = sbase + (c & 1) * 16384;
        const uint32_t aA = base + wm * 2048 + aoff;
        const uint32_t bB = base + 8192 + wn * 4096 + boff;

#pragma unroll
        for (int s = 0; s < 2; s++) {
            uint32_t ah[2][4], bf[4][4];
#pragma unroll
            for (int mt = 0; mt < 2; mt++) ldmx4(ah[mt], aA + s * 256 + mt * 1024);
#pragma unroll
            for (int g = 0; g < 4; g++) ldmx4(bf[g], bB + s * 256 + g * 1024);

#pragma unroll
            for (int mt = 0; mt < 2; mt++)
#pragma unroll
                for (int g = 0; g < 4; g++) {
                    mma16816h(acc[mt][2*g],   ah[mt], &bf[g][0]);
                    mma16816h(acc[mt][2*g+1], ah[mt], &bf[g][2]);
                }
        }
        __syncthreads();
    }

    const int rowb = mbase + wm * 32 + (lid >> 2);
    const int colb = nbase + wn * 64 + 2 * (lid & 3);
#pragma unroll
    for (int mt = 0; mt < 2; mt++)
#pragma unroll
        for (int nt = 0; nt < 8; nt++) {
            int col = colb + nt * 8;
#pragma unroll
            for (int h2 = 0; h2 < 2; h2++) {
                int row = rowb + mt * 16 + h2 * 8;
                float vx = acc[mt][nt][2*h2], vy = acc[mt][nt][2*h2+1];
                if (scatter) {
                    int which = col / CE, cc = col - which * CE;
                    int h = cc / HD, d = cc - h * HD;
                    int bb = row >> 10, tt = row & 1023;
                    size_t idx = (size_t)(((bb * NHEAD + h) * SEQ) + tt) * HD + d;
                    if (which == 0) {                 // q: split fp16 (exact store of accum)
                        uint32_t hi, lo;
                        split2h(vx, vy, hi, lo);
                        *(uint32_t*)(g_qh + idx) = hi;
                        *(uint32_t*)(g_ql + idx) = lo;
                    } else {                          // k/v: single fp16
                        size_t off = (which == 1) ? 0 : (size_t)BATCH*NHEAD*SEQ*HD;
                        *(uint32_t*)(g_kv + off + idx) = pack2h(vx, vy);
                    }
                } else {
                    *(float2*)(outp + (size_t)row * CE + col) = make_float2(vx, vy);
                }
            }
        }
}

// ------------------------------- flash attention (fp16) ---------------------
// QK: (Qh+Ql) x K (2-pass, Q exact).  PV: Ph x V (1-pass).
#define FBM    128
#define FBN    64
#define PITCHB 208
#define KVSTG  (2*FBN*PITCHB)               // K + V per stage
#define FSMEM  (2*FBM*PITCHB + 2*KVSTG)

__global__ __launch_bounds__(256, 1) void flash_mma()
{
    extern __shared__ uint8_t fs[];
    const int tid = threadIdx.x, lid = tid & 31, wid = tid >> 5;
    const int bh = blockIdx.y;
    const int qt = (int)gridDim.x - 1 - (int)blockIdx.x;   // heavy tiles first
    const int q0 = qt * FBM;
    const uint32_t sQh = smem_u32(fs);
    const uint32_t sKV = sQh + 2 * FBM * PITCHB;
    const size_t gb = (size_t)bh * SEQ * HD;
    const __half* Kg = g_kv;
    const __half* Vg = g_kv + (size_t)BATCH*NHEAD*SEQ*HD;
    const float scale = 0.10206207261596575f;

    const int rkv = tid >> 2, qq = tid & 3;

    {
        uint32_t sb = sKV + rkv * PITCHB + qq * 48;
        size_t go = gb + (size_t)rkv * HD + qq * 24;
#pragma unroll
        for (int k = 0; k < 3; k++) {
            cp16(sb + k*16,              Kg + go + k*8);
            cp16(sb + FBN*PITCHB + k*16, Vg + go + k*8);
        }
    }
    CP_COMMIT();
    {
        int r = tid >> 1, hf = tid & 1;
        uint32_t sq = sQh + r * PITCHB + hf * 96;
        size_t gq = gb + (size_t)(q0 + r) * HD + hf * 48;
#pragma unroll
        for (int k = 0; k < 6; k++) {
            cp16(sq + k*16,              g_qh + gq + k*8);
            cp16(sq + FBM*PITCHB + k*16, g_ql + gq + k*8);
        }
    }
    CP_COMMIT();

    const uint32_t aoff = (lid & 7) * PITCHB + ((lid >> 3) & 1) * (8 * PITCHB) + (lid >> 4) * 16;
    const uint32_t boff = (lid & 7) * PITCHB + ((lid >> 3) & 1) * 16 + (lid >> 4) * (8 * PITCHB);

    uint32_t qfh[6][4], qfl[6][4];
    float oacc[12][4];
#pragma unroll
    for (int n = 0; n < 12; n++)
#pragma unroll
        for (int u = 0; u < 4; u++) oacc[n][u] = 0.f;
    float m0 = -1e30f, m1 = -1e30f, lsum0 = 0.f, lsum1 = 0.f;
    const int row0 = q0 + wid * 16 + (lid >> 2);

    const int nkt = 2 * qt + 2;
    for (int kt = 0; kt < nkt; kt++) {
        if (kt + 1 < nkt) {
            uint32_t sb = sKV + ((kt + 1) & 1) * KVSTG + rkv * PITCHB + qq * 48;
            size_t go = gb + (size_t)((kt + 1) * FBN + rkv) * HD + qq * 24;
#pragma unroll
            for (int k = 0; k < 3; k++) {
                cp16(sb + k*16,              Kg + go + k*8);
                cp16(sb + FBN*PITCHB + k*16, Vg + go + k*8);
            }
        }
        CP_COMMIT();
        CP_WAIT1();
        __syncthreads();

        if (kt == 0) {
            uint32_t aQ = sQh + wid * 16 * PITCHB + aoff;
#pragma unroll
            for (int kc = 0; kc < 6; kc++) {
                ldmx4(qfh[kc], aQ + kc * 32);
                ldmx4(qfl[kc], aQ + FBM * PITCHB + kc * 32);
            }
        }

        const uint32_t stg = sKV + (kt & 1) * KVSTG;

        // ---- S = (Qh+Ql) K^T
        float sacc[8][4];
#pragma unroll
        for (int n = 0; n < 8; n++)
#pragma unroll
            for (int u = 0; u < 4; u++) sacc[n][u] = 0.f;
#pragma unroll
        for (int kc = 0; kc < 6; kc++) {
#pragma unroll
            for (int g = 0; g < 4; g++) {
                uint32_t k4[4];
                ldmx4(k4, stg + boff + g * (16 * PITCHB) + kc * 32);
                mma16816h(sacc[2*g],   qfh[kc], &k4[0]);
                mma16816h(sacc[2*g+1], qfh[kc], &k4[2]);
                mma16816h(sacc[2*g],   qfl[kc], &k4[0]);
                mma16816h(sacc[2*g+1], qfl[kc], &k4[2]);
            }
        }

        // ---- online softmax
        const int colb = kt * FBN + 2 * (lid & 3);
        float ml0 = -1e30f, ml1 = -1e30f;
#pragma unroll
        for (int n = 0; n < 8; n++)
#pragma unroll
            for (int e = 0; e < 2; e++) {
                int col = colb + 8 * n + e;
                float v0 = sacc[n][e] * scale;     if (col > row0)     v0 = -1e30f;
                float v1 = sacc[n][2 + e] * scale; if (col > row0 + 8) v1 = -1e30f;
                sacc[n][e] = v0; sacc[n][2 + e] = v1;
                ml0 = fmaxf(ml0, v0); ml1 = fmaxf(ml1, v1);
            }
        ml0 = fmaxf(ml0, __shfl_xor_sync(0xffffffffu, ml0, 1));
        ml0 = fmaxf(ml0, __shfl_xor_sync(0xffffffffu, ml0, 2));
        ml1 = fmaxf(ml1, __shfl_xor_sync(0xffffffffu, ml1, 1));
        ml1 = fmaxf(ml1, __shfl_xor_sync(0xffffffffu, ml1, 2));
        float mn0 = fmaxf(m0, ml0), mn1 = fmaxf(m1, ml1);
        float al0 = __expf(m0 - mn0), al1 = __expf(m1 - mn1);
        float ps0 = 0.f, ps1 = 0.f;
#pragma unroll
        for (int n = 0; n < 8; n++) {
            sacc[n][0] = __expf(sacc[n][0] - mn0); ps0 += sacc[n][0];
            sacc[n][1] = __expf(sacc[n][1] - mn0); ps0 += sacc[n][1];
            sacc[n][2] = __expf(sacc[n][2] - mn1); ps1 += sacc[n][2];
            sacc[n][3] = __expf(sacc[n][3] - mn1); ps1 += sacc[n][3];
        }
        ps0 += __shfl_xor_sync(0xffffffffu, ps0, 1);
        ps0 += __shfl_xor_sync(0xffffffffu, ps0, 2);
        ps1 += __shfl_xor_sync(0xffffffffu, ps1, 1);
        ps1 += __shfl_xor_sync(0xffffffffu, ps1, 2);
        lsum0 = lsum0 * al0 + ps0; m0 = mn0;
        lsum1 = lsum1 * al1 + ps1; m1 = mn1;
#pragma unroll
        for (int n = 0; n < 12; n++) {
            oacc[n][0] *= al0; oacc[n][1] *= al0;
            oacc[n][2] *= al1; oacc[n][3] *= al1;
        }

        // ---- O += Ph V  (single pass)
        const uint32_t vB = stg + FBN * PITCHB + aoff;
#pragma unroll
        for (int kc2 = 0; kc2 < 4; kc2++) {
            uint32_t pah[4];
            pah[0] = pack2h(sacc[2*kc2][0],   sacc[2*kc2][1]);
            pah[1] = pack2h(sacc[2*kc2][2],   sacc[2*kc2][3]);
            pah[2] = pack2h(sacc[2*kc2+1][0], sacc[2*kc2+1][1]);
            pah[3] = pack2h(sacc[2*kc2+1][2], sacc[2*kc2+1][3]);
            uint32_t vb = vB + kc2 * (16 * PITCHB);
#pragma unroll
            for (int dn = 0; dn < 6; dn++) {
                uint32_t v4[4];
                ldmx4t(v4, vb + dn * 32);
                mma16816h(oacc[2*dn],   pah, &v4[0]);
                mma16816h(oacc[2*dn+1], pah, &v4[2]);
            }
        }
        __syncthreads();
    }

    // epilogue: O/l -> fp16 [B,T,C] for the 1-pass projection GEMM
    const int b_ = bh >> 3, h_ = bh & 7;
    const float il0 = 1.f / lsum0, il1 = 1.f / lsum1;
    const size_t base0 = (size_t)(b_ * SEQ + row0) * CE + h_ * HD + 2 * (lid & 3);
    const size_t base1 = base0 + (size_t)8 * CE;
#pragma unroll
    for (int n = 0; n < 12; n++) {
        *(uint32_t*)(g_ah + base0 + 8 * n) = pack2h(oacc[n][0] * il0, oacc[n][1] * il0);
        *(uint32_t*)(g_ah + base1 + 8 * n) = pack2h(oacc[n][2] * il1, oacc[n][3] * il1);
    }
}

// ---------------------------------------------------------------------------
extern "C" void kernel_launch(void* const* d_in, const int* in_sizes, int n_in,
                              void* d_out, int out_size)
{
    const float* x  = (const float*)d_in[0];   // [8,1024,768]
    const float* Wa = (const float*)d_in[1];   // [768,2304]
    const float* Wp = (const float*)d_in[2];   // [768,768]
    float* out = (float*)d_out;

    void *xh, *wah, *wph, *ah;
    cudaGetSymbolAddress(&xh,  g_xh);
    cudaGetSymbolAddress(&wah, g_wah); cudaGetSymbolAddress(&wph, g_wph);
    cudaGetSymbolAddress(&ah,  g_ah);

    cudaFuncSetAttribute(flash_mma, cudaFuncAttributeMaxDynamicSharedMemorySize, FSMEM);

    // conversions
    conv_kernel_h<<<(MROWS * KDIM) / 1024, 256>>>(x, (__half*)xh, MROWS * KDIM);
    dim3 bt(32, 8);
    tconv_kernel<<<dim3(NQKV / 32, KDIM / 32), bt>>>(Wa, (__half*)wah, KDIM, NQKV);
    tconv_kernel<<<dim3(CE / 32, KDIM / 32), bt>>>(Wp, (__half*)wph, KDIM, CE);

    // 1) QKV GEMM (1-pass) -> q split fp16, k/v single fp16, [B,H,T,D]
    gemm_mma<<<dim3(NQKV / 128, MROWS / 128), 256>>>(
        (__half*)xh, (__half*)wah, nullptr, 1);

    // 2) flash attention (QK 2-pass, PV 1-pass) -> g_ah (fp16, [B,T,C])
    flash_mma<<<dim3(SEQ / FBM, BATCH * NHEAD), 256, FSMEM>>>();

    // 3) output projection (1-pass) -> d_out
    gemm_mma<<<dim3(CE / 128, MROWS / 128), 256>>>(
        (__half*)ah, (__half*)wph, out, 0);
}

// round 14
// speedup vs baseline: 2.3751x; 1.0522x over previous
#include <cuda_runtime.h>
#include <cuda_fp16.h>
#include <stdint.h>

#define CE     768
#define NHEAD  8
#define HD     96
#define BATCH  8
#define SEQ    1024
#define MROWS  (BATCH*SEQ)
#define KDIM   768
#define NQKV   (3*CE)
#define NC2    (KDIM/32)          // 24 chunks of K=32

// ------------------------------- scratch (allocation-free rule) -------------
__device__ __align__(16) __half g_xh[MROWS*KDIM];
__device__ __align__(16) __half g_wah[NQKV*KDIM];
__device__ __align__(16) __half g_wph[CE*KDIM];
__device__ __align__(16) __half g_ah[MROWS*KDIM];
__device__ __align__(16) __half g_qh[BATCH*NHEAD*SEQ*HD];
__device__ __align__(16) __half g_ql[BATCH*NHEAD*SEQ*HD];
__device__ __align__(16) __half g_kv[2*BATCH*NHEAD*SEQ*HD];   // k then v

// ------------------------------- helpers ------------------------------------
__device__ __forceinline__ uint32_t smem_u32(const void* p) {
    uint32_t a;
    asm("{ .reg .u64 t; cvta.to.shared.u64 t, %1; cvt.u32.u64 %0, t; }" : "=r"(a) : "l"(p));
    return a;
}
__device__ __forceinline__ void ldmx4(uint32_t* r, uint32_t addr) {
    asm volatile("ldmatrix.sync.aligned.m8n8.x4.shared.b16 {%0,%1,%2,%3}, [%4];"
                 : "=r"(r[0]), "=r"(r[1]), "=r"(r[2]), "=r"(r[3]) : "r"(addr));
}
__device__ __forceinline__ void ldmx4t(uint32_t* r, uint32_t addr) {
    asm volatile("ldmatrix.sync.aligned.m8n8.x4.trans.shared.b16 {%0,%1,%2,%3}, [%4];"
                 : "=r"(r[0]), "=r"(r[1]), "=r"(r[2]), "=r"(r[3]) : "r"(addr));
}
__device__ __forceinline__ void mma16816h(float* c, const uint32_t* a, const uint32_t* b) {
    asm volatile(
        "mma.sync.aligned.m16n8k16.row.col.f32.f16.f16.f32 "
        "{%0,%1,%2,%3}, {%4,%5,%6,%7}, {%8,%9}, {%0,%1,%2,%3};"
        : "+f"(c[0]), "+f"(c[1]), "+f"(c[2]), "+f"(c[3])
        : "r"(a[0]), "r"(a[1]), "r"(a[2]), "r"(a[3]), "r"(b[0]), "r"(b[1]));
}
__device__ __forceinline__ void cp16(uint32_t saddr, const void* gptr) {
    asm volatile("cp.async.ca.shared.global [%0], [%1], 16;"
                 :: "r"(saddr), "l"(__cvta_generic_to_global(gptr)) : "memory");
}
#define CP_COMMIT() asm volatile("cp.async.commit_group;" ::: "memory")
#define CP_WAIT1()  asm volatile("cp.async.wait_group 1;" ::: "memory")

__device__ __forceinline__ void split2h(float x, float y, uint32_t& hi, uint32_t& lo) {
    __half2 h, l;
    h.x = __float2half(x);  h.y = __float2half(y);
    l.x = __float2half(x - __half2float(h.x));
    l.y = __float2half(y - __half2float(h.y));
    hi = *(uint32_t*)&h;  lo = *(uint32_t*)&l;
}
__device__ __forceinline__ uint32_t pack2h(float x, float y) {
    __half2 h; h.x = __float2half(x); h.y = __float2half(y);
    return *(uint32_t*)&h;
}

// ------------------------------- conversion kernels -------------------------
__global__ void conv_kernel_h(const float* __restrict__ in,
                              __half* __restrict__ outh, int n)
{
    int i = (blockIdx.x * 256 + threadIdx.x) * 4;
    if (i >= n) return;
    float4 v = *(const float4*)(in + i);
    uint2 o;
    o.x = pack2h(v.x, v.y);
    o.y = pack2h(v.z, v.w);
    *(uint2*)(outh + i) = o;
}

// in: [K,N] fp32 row-major -> out: [N,K] fp16 (transposed)
__global__ void tconv_kernel(const float* __restrict__ in,
                             __half* __restrict__ outw, int K, int N)
{
    __shared__ float t[32][33];
    const int n0 = blockIdx.x * 32, k0 = blockIdx.y * 32;
#pragma unroll
    for (int i = 0; i < 4; i++) {
        int k = k0 + threadIdx.y + i * 8;
        t[threadIdx.y + i * 8][threadIdx.x] = in[(size_t)k * N + n0 + threadIdx.x];
    }
    __syncthreads();
#pragma unroll
    for (int i = 0; i < 4; i++) {
        int n = n0 + threadIdx.y + i * 8;
        float v = t[threadIdx.x][threadIdx.y + i * 8];
        outw[(size_t)n * K + k0 + threadIdx.x] = __float2half(v);
    }
}

// ------------------------------- HMMA GEMM (fp16, warp tile 64x64) ----------
// C[M,N] = A[M,768] * B[N,768]^T, fp16 operands, fp32 accum.
// Block 128x128, FOUR warps (2Mx2N, warp tile 64x64): 128B LDSM per MMA
// (vs 192 at 32x64) -> smem crossbar no longer binds. 128 threads,
// launch_bounds(128,2) keeps 2 CTAs/SM for sync/latency overlap.
// Stage 16KB: A@0(8K) B@8192(8K). addr(r,ch16) = (r>>3)<<9 | (r&7)<<4 | ch<<7.
__global__ __launch_bounds__(128, 2) void gemm_mma(
    const __half* __restrict__ Ah, const __half* __restrict__ Bm,
    float* __restrict__ outp, int scatter)
{
    __shared__ __align__(128) uint8_t sm[2][16384];
    const int tid = threadIdx.x, lid = tid & 31, wid = tid >> 5;
    const int wm = wid & 1, wn = wid >> 1;
    const int mbase = blockIdx.y * 128, nbase = blockIdx.x * 128;
    const uint32_t sbase = smem_u32(sm);

    const uint32_t aoff = ((lid & 7) << 4) | (((lid >> 3) & 1) << 9) | ((lid >> 4) << 7);
    const uint32_t boff = ((lid & 7) << 4) | (((lid >> 3) & 1) << 7) | ((lid >> 4) << 9);

    float acc[4][8][4];
#pragma unroll
    for (int mt = 0; mt < 4; mt++)
#pragma unroll
        for (int nt = 0; nt < 8; nt++)
#pragma unroll
            for (int u = 0; u < 4; u++) acc[mt][nt][u] = 0.f;

    auto load_chunk = [&](int c, int stg) {
        const uint32_t sb = sbase + stg * 16384;
        const int kt = c * 32;
#pragma unroll
        for (int i = 0; i < 2; i++) {
            int r = (tid >> 1) + i * 64;
#pragma unroll
            for (int j = 0; j < 2; j++) {
                int ch = (tid & 1) * 2 + j;
                uint32_t d = sb + ((r >> 3) << 9) + ((r & 7) << 4) + (ch << 7);
                size_t ga  = (size_t)(mbase + r) * KDIM + kt + ch * 8;
                size_t gbp = (size_t)(nbase + r) * KDIM + kt + ch * 8;
                cp16(d,        Ah + ga);
                cp16(d + 8192, Bm + gbp);
            }
        }
    };

    load_chunk(0, 0); CP_COMMIT();

    for (int c = 0; c < NC2; c++) {
        if (c + 1 < NC2) load_chunk(c + 1, (c + 1) & 1);
        CP_COMMIT();
        CP_WAIT1();
        __syncthreads();

        const uint32_t base = sbase + (c & 1) * 16384;
        const uint32_t aA = base + wm * 4096 + aoff;
        const uint32_t bB = base + 8192 + wn * 4096 + boff;

#pragma unroll
        for (int s = 0; s < 2; s++) {
            uint32_t af[4][4], bf[4][4];
#pragma unroll
            for (int mt = 0; mt < 4; mt++) ldmx4(af[mt], aA + s * 256 + mt * 1024);
#pragma unroll
            for (int g = 0; g < 4; g++)    ldmx4(bf[g], bB + s * 256 + g * 1024);

#pragma unroll
            for (int mt = 0; mt < 4; mt++)
#pragma unroll
                for (int g = 0; g < 4; g++) {
                    mma16816h(acc[mt][2*g],   af[mt], &bf[g][0]);
                    mma16816h(acc[mt][2*g+1], af[mt], &bf[g][2]);
                }
        }
        __syncthreads();
    }

    const int rowb = mbase + wm * 64 + (lid >> 2);
    const int colb = nbase + wn * 64 + 2 * (lid & 3);
#pragma unroll
    for (int mt = 0; mt < 4; mt++)
#pragma unroll
        for (int nt = 0; nt < 8; nt++) {
            int col = colb + nt * 8;
#pragma unroll
            for (int h2 = 0; h2 < 2; h2++) {
                int row = rowb + mt * 16 + h2 * 8;
                float vx = acc[mt][nt][2*h2], vy = acc[mt][nt][2*h2+1];
                if (scatter) {
                    int which = col / CE, cc = col - which * CE;
                    int h = cc / HD, d = cc - h * HD;
                    int bb = row >> 10, tt = row & 1023;
                    size_t idx = (size_t)(((bb * NHEAD + h) * SEQ) + tt) * HD + d;
                    if (which == 0) {                 // q: split fp16 (exact store of accum)
                        uint32_t hi, lo;
                        split2h(vx, vy, hi, lo);
                        *(uint32_t*)(g_qh + idx) = hi;
                        *(uint32_t*)(g_ql + idx) = lo;
                    } else {                          // k/v: single fp16
                        size_t off = (which == 1) ? 0 : (size_t)BATCH*NHEAD*SEQ*HD;
                        *(uint32_t*)(g_kv + off + idx) = pack2h(vx, vy);
                    }
                } else {
                    *(float2*)(outp + (size_t)row * CE + col) = make_float2(vx, vy);
                }
            }
        }
}

// ------------------------------- flash attention (fp16) ---------------------
// QK: (Qh+Ql) x K (2-pass, Q exact).  PV: Ph x V (1-pass).
#define FBM    128
#define FBN    64
#define PITCHB 208
#define KVSTG  (2*FBN*PITCHB)               // K + V per stage
#define FSMEM  (2*FBM*PITCHB + 2*KVSTG)

__global__ __launch_bounds__(256, 1) void flash_mma()
{
    extern __shared__ uint8_t fs[];
    const int tid = threadIdx.x, lid = tid & 31, wid = tid >> 5;
    const int bh = blockIdx.y;
    const int qt = (int)gridDim.x - 1 - (int)blockIdx.x;   // heavy tiles first
    const int q0 = qt * FBM;
    const uint32_t sQh = smem_u32(fs);
    const uint32_t sKV = sQh + 2 * FBM * PITCHB;
    const size_t gb = (size_t)bh * SEQ * HD;
    const __half* Kg = g_kv;
    const __half* Vg = g_kv + (size_t)BATCH*NHEAD*SEQ*HD;
    const float scale = 0.10206207261596575f;

    const int rkv = tid >> 2, qq = tid & 3;

    {
        uint32_t sb = sKV + rkv * PITCHB + qq * 48;
        size_t go = gb + (size_t)rkv * HD + qq * 24;
#pragma unroll
        for (int k = 0; k < 3; k++) {
            cp16(sb + k*16,              Kg + go + k*8);
            cp16(sb + FBN*PITCHB + k*16, Vg + go + k*8);
        }
    }
    CP_COMMIT();
    {
        int r = tid >> 1, hf = tid & 1;
        uint32_t sq = sQh + r * PITCHB + hf * 96;
        size_t gq = gb + (size_t)(q0 + r) * HD + hf * 48;
#pragma unroll
        for (int k = 0; k < 6; k++) {
            cp16(sq + k*16,              g_qh + gq + k*8);
            cp16(sq + FBM*PITCHB + k*16, g_ql + gq + k*8);
        }
    }
    CP_COMMIT();

    const uint32_t aoff = (lid & 7) * PITCHB + ((lid >> 3) & 1) * (8 * PITCHB) + (lid >> 4) * 16;
    const uint32_t boff = (lid & 7) * PITCHB + ((lid >> 3) & 1) * 16 + (lid >> 4) * (8 * PITCHB);

    uint32_t qfh[6][4], qfl[6][4];
    float oacc[12][4];
#pragma unroll
    for (int n = 0; n < 12; n++)
#pragma unroll
        for (int u = 0; u < 4; u++) oacc[n][u] = 0.f;
    float m0 = -1e30f, m1 = -1e30f, lsum0 = 0.f, lsum1 = 0.f;
    const int row0 = q0 + wid * 16 + (lid >> 2);

    const int nkt = 2 * qt + 2;
    for (int kt = 0; kt < nkt; kt++) {
        if (kt + 1 < nkt) {
            uint32_t sb = sKV + ((kt + 1) & 1) * KVSTG + rkv * PITCHB + qq * 48;
            size_t go = gb + (size_t)((kt + 1) * FBN + rkv) * HD + qq * 24;
#pragma unroll
            for (int k = 0; k < 3; k++) {
                cp16(sb + k*16,              Kg + go + k*8);
                cp16(sb + FBN*PITCHB + k*16, Vg + go + k*8);
            }
        }
        CP_COMMIT();
        CP_WAIT1();
        __syncthreads();

        if (kt == 0) {
            uint32_t aQ = sQh + wid * 16 * PITCHB + aoff;
#pragma unroll
            for (int kc = 0; kc < 6; kc++) {
                ldmx4(qfh[kc], aQ + kc * 32);
                ldmx4(qfl[kc], aQ + FBM * PITCHB + kc * 32);
            }
        }

        const uint32_t stg = sKV + (kt & 1) * KVSTG;

        // ---- S = (Qh+Ql) K^T
        float sacc[8][4];
#pragma unroll
        for (int n = 0; n < 8; n++)
#pragma unroll
            for (int u = 0; u < 4; u++) sacc[n][u] = 0.f;
#pragma unroll
        for (int kc = 0; kc < 6; kc++) {
#pragma unroll
            for (int g = 0; g < 4; g++) {
                uint32_t k4[4];
                ldmx4(k4, stg + boff + g * (16 * PITCHB) + kc * 32);
                mma16816h(sacc[2*g],   qfh[kc], &k4[0]);
                mma16816h(sacc[2*g+1], qfh[kc], &k4[2]);
                mma16816h(sacc[2*g],   qfl[kc], &k4[0]);
                mma16816h(sacc[2*g+1], qfl[kc], &k4[2]);
            }
        }

        // ---- online softmax
        const int colb = kt * FBN + 2 * (lid & 3);
        float ml0 = -1e30f, ml1 = -1e30f;
#pragma unroll
        for (int n = 0; n < 8; n++)
#pragma unroll
            for (int e = 0; e < 2; e++) {
                int col = colb + 8 * n + e;
                float v0 = sacc[n][e] * scale;     if (col > row0)     v0 = -1e30f;
                float v1 = sacc[n][2 + e] * scale; if (col > row0 + 8) v1 = -1e30f;
                sacc[n][e] = v0; sacc[n][2 + e] = v1;
                ml0 = fmaxf(ml0, v0); ml1 = fmaxf(ml1, v1);
            }
        ml0 = fmaxf(ml0, __shfl_xor_sync(0xffffffffu, ml0, 1));
        ml0 = fmaxf(ml0, __shfl_xor_sync(0xffffffffu, ml0, 2));
        ml1 = fmaxf(ml1, __shfl_xor_sync(0xffffffffu, ml1, 1));
        ml1 = fmaxf(ml1, __shfl_xor_sync(0xffffffffu, ml1, 2));
        float mn0 = fmaxf(m0, ml0), mn1 = fmaxf(m1, ml1);
        float al0 = __expf(m0 - mn0), al1 = __expf(m1 - mn1);
        float ps0 = 0.f, ps1 = 0.f;
#pragma unroll
        for (int n = 0; n < 8; n++) {
            sacc[n][0] = __expf(sacc[n][0] - mn0); ps0 += sacc[n][0];
            sacc[n][1] = __expf(sacc[n][1] - mn0); ps0 += sacc[n][1];
            sacc[n][2] = __expf(sacc[n][2] - mn1); ps1 += sacc[n][2];
            sacc[n][3] = __expf(sacc[n][3] - mn1); ps1 += sacc[n][3];
        }
        ps0 += __shfl_xor_sync(0xffffffffu, ps0, 1);
        ps0 += __shfl_xor_sync(0xffffffffu, ps0, 2);
        ps1 += __shfl_xor_sync(0xffffffffu, ps1, 1);
        ps1 += __shfl_xor_sync(0xffffffffu, ps1, 2);
        lsum0 = lsum0 * al0 + ps0; m0 = mn0;
        lsum1 = lsum1 * al1 + ps1; m1 = mn1;
#pragma unroll
        for (int n = 0; n < 12; n++) {
            oacc[n][0] *= al0; oacc[n][1] *= al0;
            oacc[n][2] *= al1; oacc[n][3] *= al1;
        }

        // ---- O += Ph V  (single pass)
        const uint32_t vB = stg + FBN * PITCHB + aoff;
#pragma unroll
        for (int kc2 = 0; kc2 < 4; kc2++) {
            uint32_t pah[4];
            pah[0] = pack2h(sacc[2*kc2][0],   sacc[2*kc2][1]);
            pah[1] = pack2h(sacc[2*kc2][2],   sacc[2*kc2][3]);
            pah[2] = pack2h(sacc[2*kc2+1][0], sacc[2*kc2+1][1]);
            pah[3] = pack2h(sacc[2*kc2+1][2], sacc[2*kc2+1][3]);
            uint32_t vb = vB + kc2 * (16 * PITCHB);
#pragma unroll
            for (int dn = 0; dn < 6; dn++) {
                uint32_t v4[4];
                ldmx4t(v4, vb + dn * 32);
                mma16816h(oacc[2*dn],   pah, &v4[0]);
                mma16816h(oacc[2*dn+1], pah, &v4[2]);
            }
        }
        __syncthreads();
    }

    // epilogue: O/l -> fp16 [B,T,C] for the 1-pass projection GEMM
    const int b_ = bh >> 3, h_ = bh & 7;
    const float il0 = 1.f / lsum0, il1 = 1.f / lsum1;
    const size_t base0 = (size_t)(b_ * SEQ + row0) * CE + h_ * HD + 2 * (lid & 3);
    const size_t base1 = base0 + (size_t)8 * CE;
#pragma unroll
    for (int n = 0; n < 12; n++) {
        *(uint32_t*)(g_ah + base0 + 8 * n) = pack2h(oacc[n][0] * il0, oacc[n][1] * il0);
        *(uint32_t*)(g_ah + base1 + 8 * n) = pack2h(oacc[n][2] * il1, oacc[n][3] * il1);
    }
}

// ---------------------------------------------------------------------------
extern "C" void kernel_launch(void* const* d_in, const int* in_sizes, int n_in,
                              void* d_out, int out_size)
{
    const float* x  = (const float*)d_in[0];   // [8,1024,768]
    const float* Wa = (const float*)d_in[1];   // [768,2304]
    const float* Wp = (const float*)d_in[2];   // [768,768]
    float* out = (float*)d_out;

    void *xh, *wah, *wph, *ah;
    cudaGetSymbolAddress(&xh,  g_xh);
    cudaGetSymbolAddress(&wah, g_wah); cudaGetSymbolAddress(&wph, g_wph);
    cudaGetSymbolAddress(&ah,  g_ah);

    cudaFuncSetAttribute(flash_mma, cudaFuncAttributeMaxDynamicSharedMemorySize, FSMEM);

    // conversions
    conv_kernel_h<<<(MROWS * KDIM) / 1024, 256>>>(x, (__half*)xh, MROWS * KDIM);
    dim3 bt(32, 8);
    tconv_kernel<<<dim3(NQKV / 32, KDIM / 32), bt>>>(Wa, (__half*)wah, KDIM, NQKV);
    tconv_kernel<<<dim3(CE / 32, KDIM / 32), bt>>>(Wp, (__half*)wph, KDIM, CE);

    // 1) QKV GEMM (1-pass, warp tile 64x64) -> q split fp16, k/v fp16
    gemm_mma<<<dim3(NQKV / 128, MROWS / 128), 128>>>(
        (__half*)xh, (__half*)wah, nullptr, 1);

    // 2) flash attention (QK 2-pass, PV 1-pass) -> g_ah (fp16, [B,T,C])
    flash_mma<<<dim3(SEQ / FBM, BATCH * NHEAD), 256, FSMEM>>>();

    // 3) output projection (1-pass, warp tile 64x64) -> d_out
    gemm_mma<<<dim3(CE / 128, MROWS / 128), 128>>>(
        (__half*)ah, (__half*)wph, out, 0);
}

// round 15
// speedup vs baseline: 2.4442x; 1.0291x over previous
#include <cuda_runtime.h>
#include <cuda_fp16.h>
#include <stdint.h>

#define CE     768
#define NHEAD  8
#define HD     96
#define BATCH  8
#define SEQ    1024
#define MROWS  (BATCH*SEQ)
#define KDIM   768
#define NQKV   (3*CE)
#define NC64   (KDIM/64)          // 12 chunks of K=64

// ------------------------------- scratch (allocation-free rule) -------------
__device__ __align__(16) __half g_xh[MROWS*KDIM];
__device__ __align__(16) __half g_wah[NQKV*KDIM];
__device__ __align__(16) __half g_wph[CE*KDIM];
__device__ __align__(16) __half g_ah[MROWS*KDIM];
__device__ __align__(16) __half g_qh[BATCH*NHEAD*SEQ*HD];
__device__ __align__(16) __half g_ql[BATCH*NHEAD*SEQ*HD];
__device__ __align__(16) __half g_kv[2*BATCH*NHEAD*SEQ*HD];   // k then v

// ------------------------------- helpers ------------------------------------
__device__ __forceinline__ uint32_t smem_u32(const void* p) {
    uint32_t a;
    asm("{ .reg .u64 t; cvta.to.shared.u64 t, %1; cvt.u32.u64 %0, t; }" : "=r"(a) : "l"(p));
    return a;
}
__device__ __forceinline__ void ldmx4(uint32_t* r, uint32_t addr) {
    asm volatile("ldmatrix.sync.aligned.m8n8.x4.shared.b16 {%0,%1,%2,%3}, [%4];"
                 : "=r"(r[0]), "=r"(r[1]), "=r"(r[2]), "=r"(r[3]) : "r"(addr));
}
__device__ __forceinline__ void ldmx4t(uint32_t* r, uint32_t addr) {
    asm volatile("ldmatrix.sync.aligned.m8n8.x4.trans.shared.b16 {%0,%1,%2,%3}, [%4];"
                 : "=r"(r[0]), "=r"(r[1]), "=r"(r[2]), "=r"(r[3]) : "r"(addr));
}
__device__ __forceinline__ void mma16816h(float* c, const uint32_t* a, const uint32_t* b) {
    asm volatile(
        "mma.sync.aligned.m16n8k16.row.col.f32.f16.f16.f32 "
        "{%0,%1,%2,%3}, {%4,%5,%6,%7}, {%8,%9}, {%0,%1,%2,%3};"
        : "+f"(c[0]), "+f"(c[1]), "+f"(c[2]), "+f"(c[3])
        : "r"(a[0]), "r"(a[1]), "r"(a[2]), "r"(a[3]), "r"(b[0]), "r"(b[1]));
}
__device__ __forceinline__ void cp16(uint32_t saddr, const void* gptr) {
    asm volatile("cp.async.ca.shared.global [%0], [%1], 16;"
                 :: "r"(saddr), "l"(__cvta_generic_to_global(gptr)) : "memory");
}
#define CP_COMMIT() asm volatile("cp.async.commit_group;" ::: "memory")
#define CP_WAIT1()  asm volatile("cp.async.wait_group 1;" ::: "memory")

__device__ __forceinline__ void split2h(float x, float y, uint32_t& hi, uint32_t& lo) {
    __half2 h, l;
    h.x = __float2half(x);  h.y = __float2half(y);
    l.x = __float2half(x - __half2float(h.x));
    l.y = __float2half(y - __half2float(h.y));
    hi = *(uint32_t*)&h;  lo = *(uint32_t*)&l;
}
__device__ __forceinline__ uint32_t pack2h(float x, float y) {
    __half2 h; h.x = __float2half(x); h.y = __float2half(y);
    return *(uint32_t*)&h;
}

// ------------------------------- conversion kernels -------------------------
__global__ void conv_kernel_h(const float* __restrict__ in,
                              __half* __restrict__ outh, int n)
{
    int i = (blockIdx.x * 256 + threadIdx.x) * 4;
    if (i >= n) return;
    float4 v = *(const float4*)(in + i);
    uint2 o;
    o.x = pack2h(v.x, v.y);
    o.y = pack2h(v.z, v.w);
    *(uint2*)(outh + i) = o;
}

// in: [K,N] fp32 row-major -> out: [N,K] fp16 (transposed)
__global__ void tconv_kernel(const float* __restrict__ in,
                             __half* __restrict__ outw, int K, int N)
{
    __shared__ float t[32][33];
    const int n0 = blockIdx.x * 32, k0 = blockIdx.y * 32;
#pragma unroll
    for (int i = 0; i < 4; i++) {
        int k = k0 + threadIdx.y + i * 8;
        t[threadIdx.y + i * 8][threadIdx.x] = in[(size_t)k * N + n0 + threadIdx.x];
    }
    __syncthreads();
#pragma unroll
    for (int i = 0; i < 4; i++) {
        int n = n0 + threadIdx.y + i * 8;
        float v = t[threadIdx.x][threadIdx.y + i * 8];
        outw[(size_t)n * K + k0 + threadIdx.x] = __float2half(v);
    }
}

// ------------------------------- HMMA GEMM (fp16, warp 64x64, K-chunk 64) ---
// C[M,N] = A[M,768] * B[N,768]^T, fp16 operands, fp32 accum.
// Block 128x128, 4 warps (2Mx2N, warp tile 64x64), K-chunk 64 (4 k16 substeps)
// -> only 12 chunks: per-chunk sync/wait overhead amortized over 128 MMAs/warp.
// Stage 32KB (A 16K @0, B 16K @16384), double-buffered dynamic smem (64KB),
// launch_bounds(128,2) keeps 2 CTAs/SM.
// Row layout: 8-row groups of 1024B; addr(r,ch16) = (r>>3)<<10 | (r&7)<<4 | ch<<7.
__global__ __launch_bounds__(128, 2) void gemm_mma(
    const __half* __restrict__ Ah, const __half* __restrict__ Bm,
    float* __restrict__ outp, int scatter)
{
    extern __shared__ __align__(128) uint8_t sm[];     // 2 x 32768
    const int tid = threadIdx.x, lid = tid & 31, wid = tid >> 5;
    const int wm = wid & 1, wn = wid >> 1;
    const int mbase = blockIdx.y * 128, nbase = blockIdx.x * 128;
    const uint32_t sbase = smem_u32(sm);

    const uint32_t aoff = ((lid & 7) << 4) | (((lid >> 3) & 1) << 10) | ((lid >> 4) << 7);
    const uint32_t boff = ((lid & 7) << 4) | (((lid >> 3) & 1) << 7) | ((lid >> 4) << 10);

    float acc[4][8][4];
#pragma unroll
    for (int mt = 0; mt < 4; mt++)
#pragma unroll
        for (int nt = 0; nt < 8; nt++)
#pragma unroll
            for (int u = 0; u < 4; u++) acc[mt][nt][u] = 0.f;

    auto load_chunk = [&](int c, int stg) {
        const uint32_t sb = sbase + stg * 32768;
        const int kt = c * 64;
#pragma unroll
        for (int i = 0; i < 2; i++) {
            int r = (tid >> 1) + i * 64;
#pragma unroll
            for (int j = 0; j < 4; j++) {
                int ch = (tid & 1) * 4 + j;
                uint32_t d = sb + ((r >> 3) << 10) + ((r & 7) << 4) + (ch << 7);
                size_t ga  = (size_t)(mbase + r) * KDIM + kt + ch * 8;
                size_t gbp = (size_t)(nbase + r) * KDIM + kt + ch * 8;
                cp16(d,         Ah + ga);
                cp16(d + 16384, Bm + gbp);
            }
        }
    };

    load_chunk(0, 0); CP_COMMIT();

    for (int c = 0; c < NC64; c++) {
        if (c + 1 < NC64) load_chunk(c + 1, (c + 1) & 1);
        CP_COMMIT();
        CP_WAIT1();
        __syncthreads();

        const uint32_t base = sbase + (c & 1) * 32768;
        const uint32_t aA = base + wm * 8192 + aoff;           // 64 rows = 8 groups
        const uint32_t bB = base + 16384 + wn * 8192 + boff;

#pragma unroll
        for (int s = 0; s < 4; s++) {                           // 4 k16 substeps
            uint32_t af[4][4], bf[4][4];
#pragma unroll
            for (int mt = 0; mt < 4; mt++) ldmx4(af[mt], aA + s * 256 + mt * 2048);
#pragma unroll
            for (int g = 0; g < 4; g++)    ldmx4(bf[g], bB + s * 256 + g * 2048);

#pragma unroll
            for (int mt = 0; mt < 4; mt++)
#pragma unroll
                for (int g = 0; g < 4; g++) {
                    mma16816h(acc[mt][2*g],   af[mt], &bf[g][0]);
                    mma16816h(acc[mt][2*g+1], af[mt], &bf[g][2]);
                }
        }
        __syncthreads();
    }

    const int rowb = mbase + wm * 64 + (lid >> 2);
    const int colb = nbase + wn * 64 + 2 * (lid & 3);
#pragma unroll
    for (int mt = 0; mt < 4; mt++)
#pragma unroll
        for (int nt = 0; nt < 8; nt++) {
            int col = colb + nt * 8;
#pragma unroll
            for (int h2 = 0; h2 < 2; h2++) {
                int row = rowb + mt * 16 + h2 * 8;
                float vx = acc[mt][nt][2*h2], vy = acc[mt][nt][2*h2+1];
                if (scatter) {
                    int which = col / CE, cc = col - which * CE;
                    int h = cc / HD, d = cc - h * HD;
                    int bb = row >> 10, tt = row & 1023;
                    size_t idx = (size_t)(((bb * NHEAD + h) * SEQ) + tt) * HD + d;
                    if (which == 0) {                 // q: split fp16 (exact store of accum)
                        uint32_t hi, lo;
                        split2h(vx, vy, hi, lo);
                        *(uint32_t*)(g_qh + idx) = hi;
                        *(uint32_t*)(g_ql + idx) = lo;
                    } else {                          // k/v: single fp16
                        size_t off = (which == 1) ? 0 : (size_t)BATCH*NHEAD*SEQ*HD;
                        *(uint32_t*)(g_kv + off + idx) = pack2h(vx, vy);
                    }
                } else {
                    *(float2*)(outp + (size_t)row * CE + col) = make_float2(vx, vy);
                }
            }
        }
}

// ------------------------------- flash attention (fp16) ---------------------
// QK: (Qh+Ql) x K (2-pass, Q exact).  PV: Ph x V (1-pass).
#define FBM    128
#define FBN    64
#define PITCHB 208
#define KVSTG  (2*FBN*PITCHB)               // K + V per stage
#define FSMEM  (2*FBM*PITCHB + 2*KVSTG)

__global__ __launch_bounds__(256, 1) void flash_mma()
{
    extern __shared__ uint8_t fs[];
    const int tid = threadIdx.x, lid = tid & 31, wid = tid >> 5;
    const int bh = blockIdx.y;
    const int qt = (int)gridDim.x - 1 - (int)blockIdx.x;   // heavy tiles first
    const int q0 = qt * FBM;
    const uint32_t sQh = smem_u32(fs);
    const uint32_t sKV = sQh + 2 * FBM * PITCHB;
    const size_t gb = (size_t)bh * SEQ * HD;
    const __half* Kg = g_kv;
    const __half* Vg = g_kv + (size_t)BATCH*NHEAD*SEQ*HD;
    const float scale = 0.10206207261596575f;

    const int rkv = tid >> 2, qq = tid & 3;

    {
        uint32_t sb = sKV + rkv * PITCHB + qq * 48;
        size_t go = gb + (size_t)rkv * HD + qq * 24;
#pragma unroll
        for (int k = 0; k < 3; k++) {
            cp16(sb + k*16,              Kg + go + k*8);
            cp16(sb + FBN*PITCHB + k*16, Vg + go + k*8);
        }
    }
    CP_COMMIT();
    {
        int r = tid >> 1, hf = tid & 1;
        uint32_t sq = sQh + r * PITCHB + hf * 96;
        size_t gq = gb + (size_t)(q0 + r) * HD + hf * 48;
#pragma unroll
        for (int k = 0; k < 6; k++) {
            cp16(sq + k*16,              g_qh + gq + k*8);
            cp16(sq + FBM*PITCHB + k*16, g_ql + gq + k*8);
        }
    }
    CP_COMMIT();

    const uint32_t aoff = (lid & 7) * PITCHB + ((lid >> 3) & 1) * (8 * PITCHB) + (lid >> 4) * 16;
    const uint32_t boff = (lid & 7) * PITCHB + ((lid >> 3) & 1) * 16 + (lid >> 4) * (8 * PITCHB);

    uint32_t qfh[6][4], qfl[6][4];
    float oacc[12][4];
#pragma unroll
    for (int n = 0; n < 12; n++)
#pragma unroll
        for (int u = 0; u < 4; u++) oacc[n][u] = 0.f;
    float m0 = -1e30f, m1 = -1e30f, lsum0 = 0.f, lsum1 = 0.f;
    const int row0 = q0 + wid * 16 + (lid >> 2);

    const int nkt = 2 * qt + 2;
    for (int kt = 0; kt < nkt; kt++) {
        if (kt + 1 < nkt) {
            uint32_t sb = sKV + ((kt + 1) & 1) * KVSTG + rkv * PITCHB + qq * 48;
            size_t go = gb + (size_t)((kt + 1) * FBN + rkv) * HD + qq * 24;
#pragma unroll
            for (int k = 0; k < 3; k++) {
                cp16(sb + k*16,              Kg + go + k*8);
                cp16(sb + FBN*PITCHB + k*16, Vg + go + k*8);
            }
        }
        CP_COMMIT();
        CP_WAIT1();
        __syncthreads();

        if (kt == 0) {
            uint32_t aQ = sQh + wid * 16 * PITCHB + aoff;
#pragma unroll
            for (int kc = 0; kc < 6; kc++) {
                ldmx4(qfh[kc], aQ + kc * 32);
                ldmx4(qfl[kc], aQ + FBM * PITCHB + kc * 32);
            }
        }

        const uint32_t stg = sKV + (kt & 1) * KVSTG;

        // ---- S = (Qh+Ql) K^T
        float sacc[8][4];
#pragma unroll
        for (int n = 0; n < 8; n++)
#pragma unroll
            for (int u = 0; u < 4; u++) sacc[n][u] = 0.f;
#pragma unroll
        for (int kc = 0; kc < 6; kc++) {
#pragma unroll
            for (int g = 0; g < 4; g++) {
                uint32_t k4[4];
                ldmx4(k4, stg + boff + g * (16 * PITCHB) + kc * 32);
                mma16816h(sacc[2*g],   qfh[kc], &k4[0]);
                mma16816h(sacc[2*g+1], qfh[kc], &k4[2]);
                mma16816h(sacc[2*g],   qfl[kc], &k4[0]);
                mma16816h(sacc[2*g+1], qfl[kc], &k4[2]);
            }
        }

        // ---- online softmax
        const int colb = kt * FBN + 2 * (lid & 3);
        float ml0 = -1e30f, ml1 = -1e30f;
#pragma unroll
        for (int n = 0; n < 8; n++)
#pragma unroll
            for (int e = 0; e < 2; e++) {
                int col = colb + 8 * n + e;
                float v0 = sacc[n][e] * scale;     if (col > row0)     v0 = -1e30f;
                float v1 = sacc[n][2 + e] * scale; if (col > row0 + 8) v1 = -1e30f;
                sacc[n][e] = v0; sacc[n][2 + e] = v1;
                ml0 = fmaxf(ml0, v0); ml1 = fmaxf(ml1, v1);
            }
        ml0 = fmaxf(ml0, __shfl_xor_sync(0xffffffffu, ml0, 1));
        ml0 = fmaxf(ml0, __shfl_xor_sync(0xffffffffu, ml0, 2));
        ml1 = fmaxf(ml1, __shfl_xor_sync(0xffffffffu, ml1, 1));
        ml1 = fmaxf(ml1, __shfl_xor_sync(0xffffffffu, ml1, 2));
        float mn0 = fmaxf(m0, ml0), mn1 = fmaxf(m1, ml1);
        float al0 = __expf(m0 - mn0), al1 = __expf(m1 - mn1);
        float ps0 = 0.f, ps1 = 0.f;
#pragma unroll
        for (int n = 0; n < 8; n++) {
            sacc[n][0] = __expf(sacc[n][0] - mn0); ps0 += sacc[n][0];
            sacc[n][1] = __expf(sacc[n][1] - mn0); ps0 += sacc[n][1];
            sacc[n][2] = __expf(sacc[n][2] - mn1); ps1 += sacc[n][2];
            sacc[n][3] = __expf(sacc[n][3] - mn1); ps1 += sacc[n][3];
        }
        ps0 += __shfl_xor_sync(0xffffffffu, ps0, 1);
        ps0 += __shfl_xor_sync(0xffffffffu, ps0, 2);
        ps1 += __shfl_xor_sync(0xffffffffu, ps1, 1);
        ps1 += __shfl_xor_sync(0xffffffffu, ps1, 2);
        lsum0 = lsum0 * al0 + ps0; m0 = mn0;
        lsum1 = lsum1 * al1 + ps1; m1 = mn1;
#pragma unroll
        for (int n = 0; n < 12; n++) {
            oacc[n][0] *= al0; oacc[n][1] *= al0;
            oacc[n][2] *= al1; oacc[n][3] *= al1;
        }

        // ---- O += Ph V  (single pass)
        const uint32_t vB = stg + FBN * PITCHB + aoff;
#pragma unroll
        for (int kc2 = 0; kc2 < 4; kc2++) {
            uint32_t pah[4];
            pah[0] = pack2h(sacc[2*kc2][0],   sacc[2*kc2][1]);
            pah[1] = pack2h(sacc[2*kc2][2],   sacc[2*kc2][3]);
            pah[2] = pack2h(sacc[2*kc2+1][0], sacc[2*kc2+1][1]);
            pah[3] = pack2h(sacc[2*kc2+1][2], sacc[2*kc2+1][3]);
            uint32_t vb = vB + kc2 * (16 * PITCHB);
#pragma unroll
            for (int dn = 0; dn < 6; dn++) {
                uint32_t v4[4];
                ldmx4t(v4, vb + dn * 32);
                mma16816h(oacc[2*dn],   pah, &v4[0]);
                mma16816h(oacc[2*dn+1], pah, &v4[2]);
            }
        }
        __syncthreads();
    }

    // epilogue: O/l -> fp16 [B,T,C] for the 1-pass projection GEMM
    const int b_ = bh >> 3, h_ = bh & 7;
    const float il0 = 1.f / lsum0, il1 = 1.f / lsum1;
    const size_t base0 = (size_t)(b_ * SEQ + row0) * CE + h_ * HD + 2 * (lid & 3);
    const size_t base1 = base0 + (size_t)8 * CE;
#pragma unroll
    for (int n = 0; n < 12; n++) {
        *(uint32_t*)(g_ah + base0 + 8 * n) = pack2h(oacc[n][0] * il0, oacc[n][1] * il0);
        *(uint32_t*)(g_ah + base1 + 8 * n) = pack2h(oacc[n][2] * il1, oacc[n][3] * il1);
    }
}

// ---------------------------------------------------------------------------
extern "C" void kernel_launch(void* const* d_in, const int* in_sizes, int n_in,
                              void* d_out, int out_size)
{
    const float* x  = (const float*)d_in[0];   // [8,1024,768]
    const float* Wa = (const float*)d_in[1];   // [768,2304]
    const float* Wp = (const float*)d_in[2];   // [768,768]
    float* out = (float*)d_out;

    void *xh, *wah, *wph, *ah;
    cudaGetSymbolAddress(&xh,  g_xh);
    cudaGetSymbolAddress(&wah, g_wah); cudaGetSymbolAddress(&wph, g_wph);
    cudaGetSymbolAddress(&ah,  g_ah);

    cudaFuncSetAttribute(flash_mma, cudaFuncAttributeMaxDynamicSharedMemorySize, FSMEM);
    cudaFuncSetAttribute(gemm_mma,  cudaFuncAttributeMaxDynamicSharedMemorySize, 65536);

    // conversions
    conv_kernel_h<<<(MROWS * KDIM) / 1024, 256>>>(x, (__half*)xh, MROWS * KDIM);
    dim3 bt(32, 8);
    tconv_kernel<<<dim3(NQKV / 32, KDIM / 32), bt>>>(Wa, (__half*)wah, KDIM, NQKV);
    tconv_kernel<<<dim3(CE / 32, KDIM / 32), bt>>>(Wp, (__half*)wph, KDIM, CE);

    // 1) QKV GEMM (1-pass, warp 64x64, K-chunk 64) -> q split fp16, k/v fp16
    gemm_mma<<<dim3(NQKV / 128, MROWS / 128), 128, 65536>>>(
        (__half*)xh, (__half*)wah, nullptr, 1);

    // 2) flash attention (QK 2-pass, PV 1-pass) -> g_ah (fp16, [B,T,C])
    flash_mma<<<dim3(SEQ / FBM, BATCH * NHEAD), 256, FSMEM>>>();

    // 3) output projection (1-pass, warp 64x64, K-chunk 64) -> d_out
    gemm_mma<<<dim3(CE / 128, MROWS / 128), 128, 65536>>>(
        (__half*)ah, (__half*)wph, out, 0);
}

// round 16
// speedup vs baseline: 2.4769x; 1.0134x over previous
#include <cuda_runtime.h>
#include <cuda_fp16.h>
#include <stdint.h>

#define CE     768
#define NHEAD  8
#define HD     96
#define BATCH  8
#define SEQ    1024
#define MROWS  (BATCH*SEQ)
#define KDIM   768
#define NQKV   (3*CE)
#define NC64   (KDIM/64)          // 12 chunks of K=64

// ------------------------------- scratch (allocation-free rule) -------------
__device__ __align__(16) __half g_xh[MROWS*KDIM];
__device__ __align__(16) __half g_wah[NQKV*KDIM];
__device__ __align__(16) __half g_wph[CE*KDIM];
__device__ __align__(16) __half g_ah[MROWS*KDIM];
__device__ __align__(16) __half g_qh[BATCH*NHEAD*SEQ*HD];
__device__ __align__(16) __half g_kv[2*BATCH*NHEAD*SEQ*HD];   // k then v

// ------------------------------- helpers ------------------------------------
__device__ __forceinline__ uint32_t smem_u32(const void* p) {
    uint32_t a;
    asm("{ .reg .u64 t; cvta.to.shared.u64 t, %1; cvt.u32.u64 %0, t; }" : "=r"(a) : "l"(p));
    return a;
}
__device__ __forceinline__ void ldmx4(uint32_t* r, uint32_t addr) {
    asm volatile("ldmatrix.sync.aligned.m8n8.x4.shared.b16 {%0,%1,%2,%3}, [%4];"
                 : "=r"(r[0]), "=r"(r[1]), "=r"(r[2]), "=r"(r[3]) : "r"(addr));
}
__device__ __forceinline__ void ldmx4t(uint32_t* r, uint32_t addr) {
    asm volatile("ldmatrix.sync.aligned.m8n8.x4.trans.shared.b16 {%0,%1,%2,%3}, [%4];"
                 : "=r"(r[0]), "=r"(r[1]), "=r"(r[2]), "=r"(r[3]) : "r"(addr));
}
__device__ __forceinline__ void mma16816h(float* c, const uint32_t* a, const uint32_t* b) {
    asm volatile(
        "mma.sync.aligned.m16n8k16.row.col.f32.f16.f16.f32 "
        "{%0,%1,%2,%3}, {%4,%5,%6,%7}, {%8,%9}, {%0,%1,%2,%3};"
        : "+f"(c[0]), "+f"(c[1]), "+f"(c[2]), "+f"(c[3])
        : "r"(a[0]), "r"(a[1]), "r"(a[2]), "r"(a[3]), "r"(b[0]), "r"(b[1]));
}
__device__ __forceinline__ void cp16(uint32_t saddr, const void* gptr) {
    asm volatile("cp.async.ca.shared.global [%0], [%1], 16;"
                 :: "r"(saddr), "l"(__cvta_generic_to_global(gptr)) : "memory");
}
#define CP_COMMIT() asm volatile("cp.async.commit_group;" ::: "memory")
#define CP_WAIT1()  asm volatile("cp.async.wait_group 1;" ::: "memory")

__device__ __forceinline__ uint32_t pack2h(float x, float y) {
    __half2 h; h.x = __float2half(x); h.y = __float2half(y);
    return *(uint32_t*)&h;
}

// ------------------------------- conversion kernels -------------------------
__global__ void conv_kernel_h(const float* __restrict__ in,
                              __half* __restrict__ outh, int n)
{
    int i = (blockIdx.x * 256 + threadIdx.x) * 4;
    if (i >= n) return;
    float4 v = *(const float4*)(in + i);
    uint2 o;
    o.x = pack2h(v.x, v.y);
    o.y = pack2h(v.z, v.w);
    *(uint2*)(outh + i) = o;
}

// in: [K,N] fp32 row-major -> out: [N,K] fp16 (transposed)
__global__ void tconv_kernel(const float* __restrict__ in,
                             __half* __restrict__ outw, int K, int N)
{
    __shared__ float t[32][33];
    const int n0 = blockIdx.x * 32, k0 = blockIdx.y * 32;
#pragma unroll
    for (int i = 0; i < 4; i++) {
        int k = k0 + threadIdx.y + i * 8;
        t[threadIdx.y + i * 8][threadIdx.x] = in[(size_t)k * N + n0 + threadIdx.x];
    }
    __syncthreads();
#pragma unroll
    for (int i = 0; i < 4; i++) {
        int n = n0 + threadIdx.y + i * 8;
        float v = t[threadIdx.x][threadIdx.y + i * 8];
        outw[(size_t)n * K + k0 + threadIdx.x] = __float2half(v);
    }
}

// ------------------------------- HMMA GEMM (fp16, warp 64x64, K-chunk 64) ---
// C[M,N] = A[M,768] * B[N,768]^T, fp16 operands, fp32 accum.
// Block 128x128, 4 warps (2Mx2N, warp tile 64x64), K-chunk 64, double-buffered
// dynamic smem (2x32KB), launch_bounds(128,2) -> 2 CTAs/SM.
// Row layout: 8-row groups of 1024B; addr(r,ch16) = (r>>3)<<10 | (r&7)<<4 | ch<<7.
__global__ __launch_bounds__(128, 2) void gemm_mma(
    const __half* __restrict__ Ah, const __half* __restrict__ Bm,
    float* __restrict__ outp, int scatter)
{
    extern __shared__ __align__(128) uint8_t sm[];     // 2 x 32768
    const int tid = threadIdx.x, lid = tid & 31, wid = tid >> 5;
    const int wm = wid & 1, wn = wid >> 1;
    const int mbase = blockIdx.y * 128, nbase = blockIdx.x * 128;
    const uint32_t sbase = smem_u32(sm);

    const uint32_t aoff = ((lid & 7) << 4) | (((lid >> 3) & 1) << 10) | ((lid >> 4) << 7);
    const uint32_t boff = ((lid & 7) << 4) | (((lid >> 3) & 1) << 7) | ((lid >> 4) << 10);

    float acc[4][8][4];
#pragma unroll
    for (int mt = 0; mt < 4; mt++)
#pragma unroll
        for (int nt = 0; nt < 8; nt++)
#pragma unroll
            for (int u = 0; u < 4; u++) acc[mt][nt][u] = 0.f;

    auto load_chunk = [&](int c, int stg) {
        const uint32_t sb = sbase + stg * 32768;
        const int kt = c * 64;
#pragma unroll
        for (int i = 0; i < 2; i++) {
            int r = (tid >> 1) + i * 64;
#pragma unroll
            for (int j = 0; j < 4; j++) {
                int ch = (tid & 1) * 4 + j;
                uint32_t d = sb + ((r >> 3) << 10) + ((r & 7) << 4) + (ch << 7);
                size_t ga  = (size_t)(mbase + r) * KDIM + kt + ch * 8;
                size_t gbp = (size_t)(nbase + r) * KDIM + kt + ch * 8;
                cp16(d,         Ah + ga);
                cp16(d + 16384, Bm + gbp);
            }
        }
    };

    load_chunk(0, 0); CP_COMMIT();

    for (int c = 0; c < NC64; c++) {
        if (c + 1 < NC64) load_chunk(c + 1, (c + 1) & 1);
        CP_COMMIT();
        CP_WAIT1();
        __syncthreads();

        const uint32_t base = sbase + (c & 1) * 32768;
        const uint32_t aA = base + wm * 8192 + aoff;
        const uint32_t bB = base + 16384 + wn * 8192 + boff;

#pragma unroll
        for (int s = 0; s < 4; s++) {
            uint32_t af[4][4], bf[4][4];
#pragma unroll
            for (int mt = 0; mt < 4; mt++) ldmx4(af[mt], aA + s * 256 + mt * 2048);
#pragma unroll
            for (int g = 0; g < 4; g++)    ldmx4(bf[g], bB + s * 256 + g * 2048);

#pragma unroll
            for (int mt = 0; mt < 4; mt++)
#pragma unroll
                for (int g = 0; g < 4; g++) {
                    mma16816h(acc[mt][2*g],   af[mt], &bf[g][0]);
                    mma16816h(acc[mt][2*g+1], af[mt], &bf[g][2]);
                }
        }
        __syncthreads();
    }

    const int rowb = mbase + wm * 64 + (lid >> 2);
    const int colb = nbase + wn * 64 + 2 * (lid & 3);
#pragma unroll
    for (int mt = 0; mt < 4; mt++)
#pragma unroll
        for (int nt = 0; nt < 8; nt++) {
            int col = colb + nt * 8;
#pragma unroll
            for (int h2 = 0; h2 < 2; h2++) {
                int row = rowb + mt * 16 + h2 * 8;
                float vx = acc[mt][nt][2*h2], vy = acc[mt][nt][2*h2+1];
                if (scatter) {
                    int which = col / CE, cc = col - which * CE;
                    int h = cc / HD, d = cc - h * HD;
                    int bb = row >> 10, tt = row & 1023;
                    size_t idx = (size_t)(((bb * NHEAD + h) * SEQ) + tt) * HD + d;
                    if (which == 0) {
                        *(uint32_t*)(g_qh + idx) = pack2h(vx, vy);
                    } else {
                        size_t off = (which == 1) ? 0 : (size_t)BATCH*NHEAD*SEQ*HD;
                        *(uint32_t*)(g_kv + off + idx) = pack2h(vx, vy);
                    }
                } else {
                    *(float2*)(outp + (size_t)row * CE + col) = make_float2(vx, vy);
                }
            }
        }
}

// ------------------------------- flash attention (fp16, 1-pass QK + PV) -----
#define FBM    128
#define FBN    64
#define PITCHB 208
#define KVSTG  (2*FBN*PITCHB)               // K + V per stage
#define FSMEM  (FBM*PITCHB + 2*KVSTG)       // 26624 + 53248

__global__ __launch_bounds__(256, 1) void flash_mma()
{
    extern __shared__ uint8_t fs[];
    const int tid = threadIdx.x, lid = tid & 31, wid = tid >> 5;
    const int bh = blockIdx.y;
    const int qt = (int)gridDim.x - 1 - (int)blockIdx.x;   // heavy tiles first
    const int q0 = qt * FBM;
    const uint32_t sQh = smem_u32(fs);
    const uint32_t sKV = sQh + FBM * PITCHB;
    const size_t gb = (size_t)bh * SEQ * HD;
    const __half* Kg = g_kv;
    const __half* Vg = g_kv + (size_t)BATCH*NHEAD*SEQ*HD;
    const float scale = 0.10206207261596575f;

    const int rkv = tid >> 2, qq = tid & 3;

    {
        uint32_t sb = sKV + rkv * PITCHB + qq * 48;
        size_t go = gb + (size_t)rkv * HD + qq * 24;
#pragma unroll
        for (int k = 0; k < 3; k++) {
            cp16(sb + k*16,              Kg + go + k*8);
            cp16(sb + FBN*PITCHB + k*16, Vg + go + k*8);
        }
    }
    CP_COMMIT();
    {
        int r = tid >> 1, hf = tid & 1;
        uint32_t sq = sQh + r * PITCHB + hf * 96;
        size_t gq = gb + (size_t)(q0 + r) * HD + hf * 48;
#pragma unroll
        for (int k = 0; k < 6; k++)
            cp16(sq + k*16, g_qh + gq + k*8);
    }
    CP_COMMIT();

    const uint32_t aoff = (lid & 7) * PITCHB + ((lid >> 3) & 1) * (8 * PITCHB) + (lid >> 4) * 16;
    const uint32_t boff = (lid & 7) * PITCHB + ((lid >> 3) & 1) * 16 + (lid >> 4) * (8 * PITCHB);

    uint32_t qfh[6][4];
    float oacc[12][4];
#pragma unroll
    for (int n = 0; n < 12; n++)
#pragma unroll
        for (int u = 0; u < 4; u++) oacc[n][u] = 0.f;
    float m0 = -1e30f, m1 = -1e30f, lsum0 = 0.f, lsum1 = 0.f;
    const int row0 = q0 + wid * 16 + (lid >> 2);

    const int nkt = 2 * qt + 2;
    for (int kt = 0; kt < nkt; kt++) {
        if (kt + 1 < nkt) {
            uint32_t sb = sKV + ((kt + 1) & 1) * KVSTG + rkv * PITCHB + qq * 48;
            size_t go = gb + (size_t)((kt + 1) * FBN + rkv) * HD + qq * 24;
#pragma unroll
            for (int k = 0; k < 3; k++) {
                cp16(sb + k*16,              Kg + go + k*8);
                cp16(sb + FBN*PITCHB + k*16, Vg + go + k*8);
            }
        }
        CP_COMMIT();
        CP_WAIT1();
        __syncthreads();

        if (kt == 0) {
            uint32_t aQ = sQh + wid * 16 * PITCHB + aoff;
#pragma unroll
            for (int kc = 0; kc < 6; kc++)
                ldmx4(qfh[kc], aQ + kc * 32);
        }

        const uint32_t stg = sKV + (kt & 1) * KVSTG;

        // ---- S = Q K^T (1-pass)
        float sacc[8][4];
#pragma unroll
        for (int n = 0; n < 8; n++)
#pragma unroll
            for (int u = 0; u < 4; u++) sacc[n][u] = 0.f;
#pragma unroll
        for (int kc = 0; kc < 6; kc++) {
#pragma unroll
            for (int g = 0; g < 4; g++) {
                uint32_t k4[4];
                ldmx4(k4, stg + boff + g * (16 * PITCHB) + kc * 32);
                mma16816h(sacc[2*g],   qfh[kc], &k4[0]);
                mma16816h(sacc[2*g+1], qfh[kc], &k4[2]);
            }
        }

        // ---- online softmax
        const int colb = kt * FBN + 2 * (lid & 3);
        float ml0 = -1e30f, ml1 = -1e30f;
#pragma unroll
        for (int n = 0; n < 8; n++)
#pragma unroll
            for (int e = 0; e < 2; e++) {
                int col = colb + 8 * n + e;
                float v0 = sacc[n][e] * scale;     if (col > row0)     v0 = -1e30f;
                float v1 = sacc[n][2 + e] * scale; if (col > row0 + 8) v1 = -1e30f;
                sacc[n][e] = v0; sacc[n][2 + e] = v1;
                ml0 = fmaxf(ml0, v0); ml1 = fmaxf(ml1, v1);
            }
        ml0 = fmaxf(ml0, __shfl_xor_sync(0xffffffffu, ml0, 1));
        ml0 = fmaxf(ml0, __shfl_xor_sync(0xffffffffu, ml0, 2));
        ml1 = fmaxf(ml1, __shfl_xor_sync(0xffffffffu, ml1, 1));
        ml1 = fmaxf(ml1, __shfl_xor_sync(0xffffffffu, ml1, 2));
        float mn0 = fmaxf(m0, ml0), mn1 = fmaxf(m1, ml1);
        float al0 = __expf(m0 - mn0), al1 = __expf(m1 - mn1);
        float ps0 = 0.f, ps1 = 0.f;
#pragma unroll
        for (int n = 0; n < 8; n++) {
            sacc[n][0] = __expf(sacc[n][0] - mn0); ps0 += sacc[n][0];
            sacc[n][1] = __expf(sacc[n][1] - mn0); ps0 += sacc[n][1];
            sacc[n][2] = __expf(sacc[n][2] - mn1); ps1 += sacc[n][2];
            sacc[n][3] = __expf(sacc[n][3] - mn1); ps1 += sacc[n][3];
        }
        ps0 += __shfl_xor_sync(0xffffffffu, ps0, 1);
        ps0 += __shfl_xor_sync(0xffffffffu, ps0, 2);
        ps1 += __shfl_xor_sync(0xffffffffu, ps1, 1);
        ps1 += __shfl_xor_sync(0xffffffffu, ps1, 2);
        lsum0 = lsum0 * al0 + ps0; m0 = mn0;
        lsum1 = lsum1 * al1 + ps1; m1 = mn1;
#pragma unroll
        for (int n = 0; n < 12; n++) {
            oacc[n][0] *= al0; oacc[n][1] *= al0;
            oacc[n][2] *= al1; oacc[n][3] *= al1;
        }

        // ---- O += Ph V  (single pass)
        const uint32_t vB = stg + FBN * PITCHB + aoff;
#pragma unroll
        for (int kc2 = 0; kc2 < 4; kc2++) {
            uint32_t pah[4];
            pah[0] = pack2h(sacc[2*kc2][0],   sacc[2*kc2][1]);
            pah[1] = pack2h(sacc[2*kc2][2],   sacc[2*kc2][3]);
            pah[2] = pack2h(sacc[2*kc2+1][0], sacc[2*kc2+1][1]);
            pah[3] = pack2h(sacc[2*kc2+1][2], sacc[2*kc2+1][3]);
            uint32_t vb = vB + kc2 * (16 * PITCHB);
#pragma unroll
            for (int dn = 0; dn < 6; dn++) {
                uint32_t v4[4];
                ldmx4t(v4, vb + dn * 32);
                mma16816h(oacc[2*dn],   pah, &v4[0]);
                mma16816h(oacc[2*dn+1], pah, &v4[2]);
            }
        }
        __syncthreads();
    }

    // epilogue: O/l -> fp16 [B,T,C] for the 1-pass projection GEMM
    const int b_ = bh >> 3, h_ = bh & 7;
    const float il0 = 1.f / lsum0, il1 = 1.f / lsum1;
    const size_t base0 = (size_t)(b_ * SEQ + row0) * CE + h_ * HD + 2 * (lid & 3);
    const size_t base1 = base0 + (size_t)8 * CE;
#pragma unroll
    for (int n = 0; n < 12; n++) {
        *(uint32_t*)(g_ah + base0 + 8 * n) = pack2h(oacc[n][0] * il0, oacc[n][1] * il0);
        *(uint32_t*)(g_ah + base1 + 8 * n) = pack2h(oacc[n][2] * il1, oacc[n][3] * il1);
    }
}

// ---------------------------------------------------------------------------
extern "C" void kernel_launch(void* const* d_in, const int* in_sizes, int n_in,
                              void* d_out, int out_size)
{
    const float* x  = (const float*)d_in[0];   // [8,1024,768]
    const float* Wa = (const float*)d_in[1];   // [768,2304]
    const float* Wp = (const float*)d_in[2];   // [768,768]
    float* out = (float*)d_out;

    void *xh, *wah, *wph, *ah;
    cudaGetSymbolAddress(&xh,  g_xh);
    cudaGetSymbolAddress(&wah, g_wah); cudaGetSymbolAddress(&wph, g_wph);
    cudaGetSymbolAddress(&ah,  g_ah);

    cudaFuncSetAttribute(flash_mma, cudaFuncAttributeMaxDynamicSharedMemorySize, FSMEM);
    cudaFuncSetAttribute(gemm_mma,  cudaFuncAttributeMaxDynamicSharedMemorySize, 65536);

    // conversions
    conv_kernel_h<<<(MROWS * KDIM) / 1024, 256>>>(x, (__half*)xh, MROWS * KDIM);
    dim3 bt(32, 8);
    tconv_kernel<<<dim3(NQKV / 32, KDIM / 32), bt>>>(Wa, (__half*)wah, KDIM, NQKV);
    tconv_kernel<<<dim3(CE / 32, KDIM / 32), bt>>>(Wp, (__half*)wph, KDIM, CE);

    // 1) QKV GEMM (1-pass) -> q/k/v single fp16, [B,H,T,D]
    gemm_mma<<<dim3(NQKV / 128, MROWS / 128), 128, 65536>>>(
        (__half*)xh, (__half*)wah, nullptr, 1);

    // 2) flash attention (QK 1-pass, PV 1-pass) -> g_ah (fp16, [B,T,C])
    flash_mma<<<dim3(SEQ / FBM, BATCH * NHEAD), 256, FSMEM>>>();

    // 3) output projection (1-pass) -> d_out
    gemm_mma<<<dim3(CE / 128, MROWS / 128), 128, 65536>>>(
        (__half*)ah, (__half*)wph, out, 0);
}

// round 17
// speedup vs baseline: 2.5304x; 1.0216x over previous
#include <cuda_runtime.h>
#include <cuda_fp16.h>
#include <stdint.h>

#define CE     768
#define NHEAD  8
#define HD     96
#define BATCH  8
#define SEQ    1024
#define MROWS  (BATCH*SEQ)
#define KDIM   768
#define NQKV   (3*CE)
#define NC64   (KDIM/64)          // 12 chunks of K=64

// ------------------------------- scratch (allocation-free rule) -------------
__device__ __align__(16) __half g_xh[MROWS*KDIM];
__device__ __align__(16) __half g_wah[NQKV*KDIM];
__device__ __align__(16) __half g_wph[CE*KDIM];
__device__ __align__(16) __half g_ah[MROWS*KDIM];
__device__ __align__(16) __half g_qh[BATCH*NHEAD*SEQ*HD];
__device__ __align__(16) __half g_kv[2*BATCH*NHEAD*SEQ*HD];   // k then v

// ------------------------------- helpers ------------------------------------
__device__ __forceinline__ uint32_t smem_u32(const void* p) {
    uint32_t a;
    asm("{ .reg .u64 t; cvta.to.shared.u64 t, %1; cvt.u32.u64 %0, t; }" : "=r"(a) : "l"(p));
    return a;
}
__device__ __forceinline__ void ldmx4(uint32_t* r, uint32_t addr) {
    asm volatile("ldmatrix.sync.aligned.m8n8.x4.shared.b16 {%0,%1,%2,%3}, [%4];"
                 : "=r"(r[0]), "=r"(r[1]), "=r"(r[2]), "=r"(r[3]) : "r"(addr));
}
__device__ __forceinline__ void ldmx4t(uint32_t* r, uint32_t addr) {
    asm volatile("ldmatrix.sync.aligned.m8n8.x4.trans.shared.b16 {%0,%1,%2,%3}, [%4];"
                 : "=r"(r[0]), "=r"(r[1]), "=r"(r[2]), "=r"(r[3]) : "r"(addr));
}
__device__ __forceinline__ void mma16816h(float* c, const uint32_t* a, const uint32_t* b) {
    asm volatile(
        "mma.sync.aligned.m16n8k16.row.col.f32.f16.f16.f32 "
        "{%0,%1,%2,%3}, {%4,%5,%6,%7}, {%8,%9}, {%0,%1,%2,%3};"
        : "+f"(c[0]), "+f"(c[1]), "+f"(c[2]), "+f"(c[3])
        : "r"(a[0]), "r"(a[1]), "r"(a[2]), "r"(a[3]), "r"(b[0]), "r"(b[1]));
}
__device__ __forceinline__ void cp16(uint32_t saddr, const void* gptr) {
    asm volatile("cp.async.ca.shared.global [%0], [%1], 16;"
                 :: "r"(saddr), "l"(__cvta_generic_to_global(gptr)) : "memory");
}
#define CP_COMMIT() asm volatile("cp.async.commit_group;" ::: "memory")
#define CP_WAIT1()  asm volatile("cp.async.wait_group 1;" ::: "memory")

__device__ __forceinline__ uint32_t pack2h(float x, float y) {
    __half2 h; h.x = __float2half(x); h.y = __float2half(y);
    return *(uint32_t*)&h;
}

// ------------------------------- conversion kernels -------------------------
__global__ void conv_kernel_h(const float* __restrict__ in,
                              __half* __restrict__ outh, int n)
{
    int i = (blockIdx.x * 256 + threadIdx.x) * 4;
    if (i >= n) return;
    float4 v = *(const float4*)(in + i);
    uint2 o;
    o.x = pack2h(v.x, v.y);
    o.y = pack2h(v.z, v.w);
    *(uint2*)(outh + i) = o;
}

// in: [K,N] fp32 row-major -> out: [N,K] fp16 (transposed)
__global__ void tconv_kernel(const float* __restrict__ in,
                             __half* __restrict__ outw, int K, int N)
{
    __shared__ float t[32][33];
    const int n0 = blockIdx.x * 32, k0 = blockIdx.y * 32;
#pragma unroll
    for (int i = 0; i < 4; i++) {
        int k = k0 + threadIdx.y + i * 8;
        t[threadIdx.y + i * 8][threadIdx.x] = in[(size_t)k * N + n0 + threadIdx.x];
    }
    __syncthreads();
#pragma unroll
    for (int i = 0; i < 4; i++) {
        int n = n0 + threadIdx.y + i * 8;
        float v = t[threadIdx.x][threadIdx.y + i * 8];
        outw[(size_t)n * K + k0 + threadIdx.x] = __float2half(v);
    }
}

// ------------------------------- HMMA GEMM (fp16, warp 64x64, K-chunk 64) ---
// C[M,N] = A[M,768] * B[N,768]^T, fp16 operands, fp32 accum.
// Block 128x128, 4 warps (2Mx2N, warp tile 64x64), K-chunk 64, double-buffered
// dynamic smem (2x32KB), launch_bounds(128,2) -> 2 CTAs/SM.
__global__ __launch_bounds__(128, 2) void gemm_mma(
    const __half* __restrict__ Ah, const __half* __restrict__ Bm,
    float* __restrict__ outp, int scatter)
{
    extern __shared__ __align__(128) uint8_t sm[];     // 2 x 32768
    const int tid = threadIdx.x, lid = tid & 31, wid = tid >> 5;
    const int wm = wid & 1, wn = wid >> 1;
    const int mbase = blockIdx.y * 128, nbase = blockIdx.x * 128;
    const uint32_t sbase = smem_u32(sm);

    const uint32_t aoff = ((lid & 7) << 4) | (((lid >> 3) & 1) << 10) | ((lid >> 4) << 7);
    const uint32_t boff = ((lid & 7) << 4) | (((lid >> 3) & 1) << 7) | ((lid >> 4) << 10);

    float acc[4][8][4];
#pragma unroll
    for (int mt = 0; mt < 4; mt++)
#pragma unroll
        for (int nt = 0; nt < 8; nt++)
#pragma unroll
            for (int u = 0; u < 4; u++) acc[mt][nt][u] = 0.f;

    auto load_chunk = [&](int c, int stg) {
        const uint32_t sb = sbase + stg * 32768;
        const int kt = c * 64;
#pragma unroll
        for (int i = 0; i < 2; i++) {
            int r = (tid >> 1) + i * 64;
#pragma unroll
            for (int j = 0; j < 4; j++) {
                int ch = (tid & 1) * 4 + j;
                uint32_t d = sb + ((r >> 3) << 10) + ((r & 7) << 4) + (ch << 7);
                size_t ga  = (size_t)(mbase + r) * KDIM + kt + ch * 8;
                size_t gbp = (size_t)(nbase + r) * KDIM + kt + ch * 8;
                cp16(d,         Ah + ga);
                cp16(d + 16384, Bm + gbp);
            }
        }
    };

    load_chunk(0, 0); CP_COMMIT();

    for (int c = 0; c < NC64; c++) {
        if (c + 1 < NC64) load_chunk(c + 1, (c + 1) & 1);
        CP_COMMIT();
        CP_WAIT1();
        __syncthreads();

        const uint32_t base = sbase + (c & 1) * 32768;
        const uint32_t aA = base + wm * 8192 + aoff;
        const uint32_t bB = base + 16384 + wn * 8192 + boff;

#pragma unroll
        for (int s = 0; s < 4; s++) {
            uint32_t af[4][4], bf[4][4];
#pragma unroll
            for (int mt = 0; mt < 4; mt++) ldmx4(af[mt], aA + s * 256 + mt * 2048);
#pragma unroll
            for (int g = 0; g < 4; g++)    ldmx4(bf[g], bB + s * 256 + g * 2048);

#pragma unroll
            for (int mt = 0; mt < 4; mt++)
#pragma unroll
                for (int g = 0; g < 4; g++) {
                    mma16816h(acc[mt][2*g],   af[mt], &bf[g][0]);
                    mma16816h(acc[mt][2*g+1], af[mt], &bf[g][2]);
                }
        }
        __syncthreads();
    }

    const int rowb = mbase + wm * 64 + (lid >> 2);
    const int colb = nbase + wn * 64 + 2 * (lid & 3);
#pragma unroll
    for (int mt = 0; mt < 4; mt++)
#pragma unroll
        for (int nt = 0; nt < 8; nt++) {
            int col = colb + nt * 8;
#pragma unroll
            for (int h2 = 0; h2 < 2; h2++) {
                int row = rowb + mt * 16 + h2 * 8;
                float vx = acc[mt][nt][2*h2], vy = acc[mt][nt][2*h2+1];
                if (scatter) {
                    int which = col / CE, cc = col - which * CE;
                    int h = cc / HD, d = cc - h * HD;
                    int bb = row >> 10, tt = row & 1023;
                    size_t idx = (size_t)(((bb * NHEAD + h) * SEQ) + tt) * HD + d;
                    if (which == 0) {
                        *(uint32_t*)(g_qh + idx) = pack2h(vx, vy);
                    } else {
                        size_t off = (which == 1) ? 0 : (size_t)BATCH*NHEAD*SEQ*HD;
                        *(uint32_t*)(g_kv + off + idx) = pack2h(vx, vy);
                    }
                } else {
                    *(float2*)(outp + (size_t)row * CE + col) = make_float2(vx, vy);
                }
            }
        }
}

// ------------------------------- flash attention (fp16, FBN=128) ------------
// QK 1-pass, PV 1-pass. One 128-key tile per iteration: exactly one diagonal
// tile per CTA (kt==qt) -> masking only on the last iteration.
#define FBM    128
#define FBN    128
#define PITCHB 208
#define KVSTG  (2*FBN*PITCHB)               // K + V per stage = 53248
#define FSMEM  (FBM*PITCHB + 2*KVSTG)       // 26624 + 106496 = 133120

__global__ __launch_bounds__(256, 1) void flash_mma()
{
    extern __shared__ uint8_t fs[];
    const int tid = threadIdx.x, lid = tid & 31, wid = tid >> 5;
    const int bh = blockIdx.y;
    const int qt = (int)gridDim.x - 1 - (int)blockIdx.x;   // heavy tiles first
    const int q0 = qt * FBM;
    const uint32_t sQh = smem_u32(fs);
    const uint32_t sKV = sQh + FBM * PITCHB;
    const size_t gb = (size_t)bh * SEQ * HD;
    const __half* Kg = g_kv;
    const __half* Vg = g_kv + (size_t)BATCH*NHEAD*SEQ*HD;
    const float scale = 0.10206207261596575f;

    // KV loader: r = tid>>1 (128 rows), hf = tid&1, 6 chunks of 16B each
    const int rl = tid >> 1, hf = tid & 1;

    {   // stage-0 KV
        uint32_t sb = sKV + rl * PITCHB + hf * 96;
        size_t go = gb + (size_t)rl * HD + hf * 48;
#pragma unroll
        for (int k = 0; k < 6; k++) {
            cp16(sb + k*16,              Kg + go + k*8);
            cp16(sb + FBN*PITCHB + k*16, Vg + go + k*8);
        }
    }
    CP_COMMIT();
    {   // Q (resident)
        uint32_t sq = sQh + rl * PITCHB + hf * 96;
        size_t gq = gb + (size_t)(q0 + rl) * HD + hf * 48;
#pragma unroll
        for (int k = 0; k < 6; k++)
            cp16(sq + k*16, g_qh + gq + k*8);
    }
    CP_COMMIT();

    const uint32_t aoff = (lid & 7) * PITCHB + ((lid >> 3) & 1) * (8 * PITCHB) + (lid >> 4) * 16;
    const uint32_t boff = (lid & 7) * PITCHB + ((lid >> 3) & 1) * 16 + (lid >> 4) * (8 * PITCHB);

    uint32_t qfh[6][4];
    float oacc[12][4];
#pragma unroll
    for (int n = 0; n < 12; n++)
#pragma unroll
        for (int u = 0; u < 4; u++) oacc[n][u] = 0.f;
    float m0 = -1e30f, m1 = -1e30f, lsum0 = 0.f, lsum1 = 0.f;
    const int row0 = q0 + wid * 16 + (lid >> 2);

    const int nkt = qt + 1;
    for (int kt = 0; kt < nkt; kt++) {
        if (kt + 1 < nkt) {
            uint32_t sb = sKV + ((kt + 1) & 1) * KVSTG + rl * PITCHB + hf * 96;
            size_t go = gb + (size_t)((kt + 1) * FBN + rl) * HD + hf * 48;
#pragma unroll
            for (int k = 0; k < 6; k++) {
                cp16(sb + k*16,              Kg + go + k*8);
                cp16(sb + FBN*PITCHB + k*16, Vg + go + k*8);
            }
        }
        CP_COMMIT();
        CP_WAIT1();
        __syncthreads();

        if (kt == 0) {
            uint32_t aQ = sQh + wid * 16 * PITCHB + aoff;
#pragma unroll
            for (int kc = 0; kc < 6; kc++)
                ldmx4(qfh[kc], aQ + kc * 32);
        }

        const uint32_t stg = sKV + (kt & 1) * KVSTG;

        // ---- S = Q K^T (1-pass, 128 keys)
        float sacc[16][4];
#pragma unroll
        for (int n = 0; n < 16; n++)
#pragma unroll
            for (int u = 0; u < 4; u++) sacc[n][u] = 0.f;
#pragma unroll
        for (int kc = 0; kc < 6; kc++) {
#pragma unroll
            for (int g = 0; g < 8; g++) {
                uint32_t k4[4];
                ldmx4(k4, stg + boff + g * (16 * PITCHB) + kc * 32);
                mma16816h(sacc[2*g],   qfh[kc], &k4[0]);
                mma16816h(sacc[2*g+1], qfh[kc], &k4[2]);
            }
        }

        // ---- online softmax (mask only on the diagonal tile kt==qt)
        float ml0 = -1e30f, ml1 = -1e30f;
        if (kt == qt) {
            const int colb = kt * FBN + 2 * (lid & 3);
#pragma unroll
            for (int n = 0; n < 16; n++)
#pragma unroll
                for (int e = 0; e < 2; e++) {
                    int col = colb + 8 * n + e;
                    float v0 = sacc[n][e] * scale;     if (col > row0)     v0 = -1e30f;
                    float v1 = sacc[n][2 + e] * scale; if (col > row0 + 8) v1 = -1e30f;
                    sacc[n][e] = v0; sacc[n][2 + e] = v1;
                    ml0 = fmaxf(ml0, v0); ml1 = fmaxf(ml1, v1);
                }
        } else {
#pragma unroll
            for (int n = 0; n < 16; n++)
#pragma unroll
                for (int e = 0; e < 2; e++) {
                    float v0 = sacc[n][e] * scale;
                    float v1 = sacc[n][2 + e] * scale;
                    sacc[n][e] = v0; sacc[n][2 + e] = v1;
                    ml0 = fmaxf(ml0, v0); ml1 = fmaxf(ml1, v1);
                }
        }
        ml0 = fmaxf(ml0, __shfl_xor_sync(0xffffffffu, ml0, 1));
        ml0 = fmaxf(ml0, __shfl_xor_sync(0xffffffffu, ml0, 2));
        ml1 = fmaxf(ml1, __shfl_xor_sync(0xffffffffu, ml1, 1));
        ml1 = fmaxf(ml1, __shfl_xor_sync(0xffffffffu, ml1, 2));
        float mn0 = fmaxf(m0, ml0), mn1 = fmaxf(m1, ml1);
        float al0 = __expf(m0 - mn0), al1 = __expf(m1 - mn1);
        float ps0 = 0.f, ps1 = 0.f;
#pragma unroll
        for (int n = 0; n < 16; n++) {
            sacc[n][0] = __expf(sacc[n][0] - mn0); ps0 += sacc[n][0];
            sacc[n][1] = __expf(sacc[n][1] - mn0); ps0 += sacc[n][1];
            sacc[n][2] = __expf(sacc[n][2] - mn1); ps1 += sacc[n][2];
            sacc[n][3] = __expf(sacc[n][3] - mn1); ps1 += sacc[n][3];
        }
        ps0 += __shfl_xor_sync(0xffffffffu, ps0, 1);
        ps0 += __shfl_xor_sync(0xffffffffu, ps0, 2);
        ps1 += __shfl_xor_sync(0xffffffffu, ps1, 1);
        ps1 += __shfl_xor_sync(0xffffffffu, ps1, 2);
        lsum0 = lsum0 * al0 + ps0; m0 = mn0;
        lsum1 = lsum1 * al1 + ps1; m1 = mn1;
#pragma unroll
        for (int n = 0; n < 12; n++) {
            oacc[n][0] *= al0; oacc[n][1] *= al0;
            oacc[n][2] *= al1; oacc[n][3] *= al1;
        }

        // ---- O += Ph V  (single pass, 128 keys = 8 k16 substeps)
        const uint32_t vB = stg + FBN * PITCHB + aoff;
#pragma unroll
        for (int kc2 = 0; kc2 < 8; kc2++) {
            uint32_t pah[4];
            pah[0] = pack2h(sacc[2*kc2][0],   sacc[2*kc2][1]);
            pah[1] = pack2h(sacc[2*kc2][2],   sacc[2*kc2][3]);
            pah[2] = pack2h(sacc[2*kc2+1][0], sacc[2*kc2+1][1]);
            pah[3] = pack2h(sacc[2*kc2+1][2], sacc[2*kc2+1][3]);
            uint32_t vb = vB + kc2 * (16 * PITCHB);
#pragma unroll
            for (int dn = 0; dn < 6; dn++) {
                uint32_t v4[4];
                ldmx4t(v4, vb + dn * 32);
                mma16816h(oacc[2*dn],   pah, &v4[0]);
                mma16816h(oacc[2*dn+1], pah, &v4[2]);
            }
        }
        __syncthreads();
    }

    // epilogue: O/l -> fp16 [B,T,C] for the 1-pass projection GEMM
    const int b_ = bh >> 3, h_ = bh & 7;
    const float il0 = 1.f / lsum0, il1 = 1.f / lsum1;
    const size_t base0 = (size_t)(b_ * SEQ + row0) * CE + h_ * HD + 2 * (lid & 3);
    const size_t base1 = base0 + (size_t)8 * CE;
#pragma unroll
    for (int n = 0; n < 12; n++) {
        *(uint32_t*)(g_ah + base0 + 8 * n) = pack2h(oacc[n][0] * il0, oacc[n][1] * il0);
        *(uint32_t*)(g_ah + base1 + 8 * n) = pack2h(oacc[n][2] * il1, oacc[n][3] * il1);
    }
}

// ---------------------------------------------------------------------------
extern "C" void kernel_launch(void* const* d_in, const int* in_sizes, int n_in,
                              void* d_out, int out_size)
{
    const float* x  = (const float*)d_in[0];   // [8,1024,768]
    const float* Wa = (const float*)d_in[1];   // [768,2304]
    const float* Wp = (const float*)d_in[2];   // [768,768]
    float* out = (float*)d_out;

    void *xh, *wah, *wph, *ah;
    cudaGetSymbolAddress(&xh,  g_xh);
    cudaGetSymbolAddress(&wah, g_wah); cudaGetSymbolAddress(&wph, g_wph);
    cudaGetSymbolAddress(&ah,  g_ah);

    cudaFuncSetAttribute(flash_mma, cudaFuncAttributeMaxDynamicSharedMemorySize, FSMEM);
    cudaFuncSetAttribute(gemm_mma,  cudaFuncAttributeMaxDynamicSharedMemorySize, 65536);

    // conversions
    conv_kernel_h<<<(MROWS * KDIM) / 1024, 256>>>(x, (__half*)xh, MROWS * KDIM);
    dim3 bt(32, 8);
    tconv_kernel<<<dim3(NQKV / 32, KDIM / 32), bt>>>(Wa, (__half*)wah, KDIM, NQKV);
    tconv_kernel<<<dim3(CE / 32, KDIM / 32), bt>>>(Wp, (__half*)wph, KDIM, CE);

    // 1) QKV GEMM (1-pass) -> q/k/v single fp16, [B,H,T,D]
    gemm_mma<<<dim3(NQKV / 128, MROWS / 128), 128, 65536>>>(
        (__half*)xh, (__half*)wah, nullptr, 1);

    // 2) flash attention (FBN=128, QK/PV 1-pass) -> g_ah (fp16, [B,T,C])
    flash_mma<<<dim3(SEQ / FBM, BATCH * NHEAD), 256, FSMEM>>>();

    // 3) output projection (1-pass) -> d_out
    gemm_mma<<<dim3(CE / 128, MROWS / 128), 128, 65536>>>(
        (__half*)ah, (__half*)wph, out, 0);
}